// round 4
// baseline (speedup 1.0000x reference)
#include <cuda_runtime.h>
#include <cuda_fp16.h>
#include <math.h>

#define NB   4
#define SEQ  4096
#define EDIM 1024
#define ADIM 64
#define NS   4      // KV splits per q-tile

// Projected Q,K,V stored as split fp16 planes (hi + lo), [B*S, A] each.
__device__ __half g_Qh[NB * SEQ * ADIM];
__device__ __half g_Ql[NB * SEQ * ADIM];
__device__ __half g_Kh[NB * SEQ * ADIM];
__device__ __half g_Kl[NB * SEQ * ADIM];
__device__ __half g_Vh[NB * SEQ * ADIM];
__device__ __half g_Vl[NB * SEQ * ADIM];

// Pre-split weights: rows 0-63 = W_K, 64-127 = W_Q, 128-191 = W_V. [192][1024]
__device__ __half g_Wh[192 * EDIM];
__device__ __half g_Wl[192 * EDIM];

// Split-KV partial results: O (unnormalized), row max m, row sum l.
__device__ float g_Om[NB * NS * SEQ * ADIM];   // 16.8 MB
__device__ float g_m [NB * NS * SEQ];
__device__ float g_l [NB * NS * SEQ];

// m16n8k16 f16 MMA, f32 accumulate, in-place C.
__device__ __forceinline__ void mma16816(float d[4], const unsigned a[4], const unsigned b[2])
{
    asm volatile(
        "mma.sync.aligned.m16n8k16.row.col.f32.f16.f16.f32 "
        "{%0,%1,%2,%3}, {%4,%5,%6,%7}, {%8,%9}, {%0,%1,%2,%3};\n"
        : "+f"(d[0]), "+f"(d[1]), "+f"(d[2]), "+f"(d[3])
        : "r"(a[0]), "r"(a[1]), "r"(a[2]), "r"(a[3]), "r"(b[0]), "r"(b[1]));
}

__device__ __forceinline__ void split1(float v, __half& h, __half& l)
{
    h = __float2half_rn(v);
    l = __float2half_rn(v - __half2float(h));
}

// Split a float pair into packed hi/lo half2 words.
__device__ __forceinline__ void split2(float a, float b, unsigned& hi, unsigned& lo)
{
    __half2 h = __floats2half2_rn(a, b);
    float2 hf = __half22float2(h);
    __half2 l = __floats2half2_rn(a - hf.x, b - hf.y);
    hi = *(unsigned*)&h;
    lo = *(unsigned*)&l;
}

struct alignas(16) H8 { __half h[8]; };

// ---------------------------------------------------------------------------
// One-time weight split: fp32 W_{K,Q,V} -> fp16 hi/lo planes in global.
// ---------------------------------------------------------------------------
__global__ __launch_bounds__(256)
void wsplit(const float* __restrict__ wk,
            const float* __restrict__ wq,
            const float* __restrict__ wv)
{
    int idx  = blockIdx.x * 256 + threadIdx.x;   // one float4 per thread
    int base = idx * 4;
    int r = base >> 10;
    int c = base & 1023;
    const float* src = (r < 64)  ? wk + (size_t)r * EDIM
                     : (r < 128) ? wq + (size_t)(r - 64) * EDIM
                                 : wv + (size_t)(r - 128) * EDIM;
    float4 v = *(const float4*)(src + c);
    __half h[4], l[4];
    split1(v.x, h[0], l[0]); split1(v.y, h[1], l[1]);
    split1(v.z, h[2], l[2]); split1(v.w, h[3], l[3]);
    *(uint2*)(g_Wh + (size_t)r * EDIM + c) = *(uint2*)h;
    *(uint2*)(g_Wl + (size_t)r * EDIM + c) = *(uint2*)l;
}

// ---------------------------------------------------------------------------
// QKV projection on tensor cores (fp16x2 split); W pre-split in global.
// ---------------------------------------------------------------------------
__global__ __launch_bounds__(256, 2)
void qkv_proj(const float* __restrict__ x)
{
    __shared__ __align__(16) __half Xh[64 * 40];
    __shared__ __align__(16) __half Xl[64 * 40];
    __shared__ __align__(16) __half Wh[192 * 40];
    __shared__ __align__(16) __half Wl[192 * 40];

    const int tid  = threadIdx.x;
    const int warp = tid >> 5;
    const int lane = tid & 31;
    const int g    = lane >> 2;
    const int cq   = lane & 3;
    const int rg   = warp >> 1;
    const int cg   = warp & 1;
    const int rows0 = blockIdx.x * 64;

    float acc[12][4];
    #pragma unroll
    for (int j = 0; j < 12; j++)
        #pragma unroll
        for (int i = 0; i < 4; i++) acc[j][i] = 0.f;

    for (int e0 = 0; e0 < EDIM; e0 += 32) {
        // X chunk [64 x 32]: load fp32, split inline (each element read once)
        #pragma unroll
        for (int k = 0; k < 2; k++) {
            int f  = tid + k * 256;
            int r  = f >> 3;
            int c4 = f & 7;
            float4 v = *(const float4*)(x + (size_t)(rows0 + r) * EDIM + e0 + c4 * 4);
            __half h[4], l[4];
            split1(v.x, h[0], l[0]); split1(v.y, h[1], l[1]);
            split1(v.z, h[2], l[2]); split1(v.w, h[3], l[3]);
            *(uint2*)(Xh + r * 40 + c4 * 4) = *(uint2*)h;
            *(uint2*)(Xl + r * 40 + c4 * 4) = *(uint2*)l;
        }
        // W chunk [192 x 32]: straight uint4 copies of pre-split planes
        #pragma unroll
        for (int k = 0; k < 3; k++) {
            int f  = tid + k * 256;
            int r  = f >> 2;
            int c8 = f & 3;
            *(uint4*)(Wh + r * 40 + c8 * 8) = *(const uint4*)(g_Wh + (size_t)r * EDIM + e0 + c8 * 8);
            *(uint4*)(Wl + r * 40 + c8 * 8) = *(const uint4*)(g_Wl + (size_t)r * EDIM + e0 + c8 * 8);
        }
        __syncthreads();

        const unsigned* Xh32 = (const unsigned*)Xh;
        const unsigned* Xl32 = (const unsigned*)Xl;
        const unsigned* Wh32 = (const unsigned*)Wh;
        const unsigned* Wl32 = (const unsigned*)Wl;

        #pragma unroll
        for (int kc = 0; kc < 2; kc++) {
            int ab = (16 * rg + g) * 20 + 8 * kc + cq;
            unsigned ah[4] = { Xh32[ab], Xh32[ab + 160], Xh32[ab + 4], Xh32[ab + 164] };
            unsigned al[4] = { Xl32[ab], Xl32[ab + 160], Xl32[ab + 4], Xl32[ab + 164] };
            #pragma unroll
            for (int j = 0; j < 12; j++) {
                int n0 = cg * 96 + 8 * j;
                int bb = (n0 + g) * 20 + 8 * kc + cq;
                unsigned bh[2] = { Wh32[bb], Wh32[bb + 4] };
                unsigned bl[2] = { Wl32[bb], Wl32[bb + 4] };
                mma16816(acc[j], ah, bh);
                mma16816(acc[j], ah, bl);
                mma16816(acc[j], al, bh);
            }
        }
        __syncthreads();
    }

    const int row_lo = rows0 + 16 * rg + g;
    const int row_hi = row_lo + 8;
    #pragma unroll
    for (int j = 0; j < 12; j++) {
        int colg = cg * 96 + 8 * j + 2 * cq;
        __half *dh, *dl;
        float sc = 1.f;
        int cl;
        if (colg < 64)       { dh = g_Kh; dl = g_Kl; cl = colg; }
        else if (colg < 128) { dh = g_Qh; dl = g_Ql; cl = colg - 64; sc = 0.125f; }
        else                 { dh = g_Vh; dl = g_Vl; cl = colg - 128; }

        unsigned h2, l2;
        split2(acc[j][0] * sc, acc[j][1] * sc, h2, l2);
        *(unsigned*)(dh + (size_t)row_lo * ADIM + cl) = h2;
        *(unsigned*)(dl + (size_t)row_lo * ADIM + cl) = l2;
        split2(acc[j][2] * sc, acc[j][3] * sc, h2, l2);
        *(unsigned*)(dh + (size_t)row_hi * ADIM + cl) = h2;
        *(unsigned*)(dl + (size_t)row_hi * ADIM + cl) = l2;
    }
}

// ---------------------------------------------------------------------------
// Causal flash attention, split-KV. Block = (q-tile, split s, batch).
// P stays in registers (S C-fragments repacked as PV A-fragments).
// ---------------------------------------------------------------------------
#define ST 72
#define SW 36
#define OFF_KH 0
#define OFF_KL 4608
#define OFF_VH 9216
#define OFF_VL 13824
#define SMEM_HALVES 18432

__global__ __launch_bounds__(128, 4)
void attn_kernel()
{
    extern __shared__ __align__(16) __half sh[];

    const int tid  = threadIdx.x;
    const int w    = tid >> 5;
    const int lane = tid & 31;
    const int g    = lane >> 2;
    const int cq   = lane & 3;
    const int bx   = blockIdx.x;
    const int s    = bx & (NS - 1);
    const int qi   = (SEQ / 64 - 1) - (bx >> 2);   // heavy q-tiles first
    const int b    = blockIdx.y;
    const int q0   = qi * 64;

    if (qi < s) return;

    // Resident Q fragments (pre-scaled at projection)
    unsigned qh[4][4], ql[4][4];
    {
        size_t rl = (size_t)(b * SEQ + q0 + 16 * w + g) * ADIM;
        size_t rh = rl + 8 * ADIM;
        #pragma unroll
        for (int kc = 0; kc < 4; kc++) {
            int off = 16 * kc + 2 * cq;
            qh[kc][0] = *(const unsigned*)(g_Qh + rl + off);
            qh[kc][1] = *(const unsigned*)(g_Qh + rh + off);
            qh[kc][2] = *(const unsigned*)(g_Qh + rl + off + 8);
            qh[kc][3] = *(const unsigned*)(g_Qh + rh + off + 8);
            ql[kc][0] = *(const unsigned*)(g_Ql + rl + off);
            ql[kc][1] = *(const unsigned*)(g_Ql + rh + off);
            ql[kc][2] = *(const unsigned*)(g_Ql + rl + off + 8);
            ql[kc][3] = *(const unsigned*)(g_Ql + rh + off + 8);
        }
    }

    float o[8][4];
    #pragma unroll
    for (int j = 0; j < 8; j++)
        #pragma unroll
        for (int i = 0; i < 4; i++) o[j][i] = 0.f;
    float m_lo = -1e30f, m_hi = -1e30f, l_lo = 0.f, l_hi = 0.f;

    for (int kb = s; kb <= qi; kb += NS) {
        __syncthreads();
        {
            const __half* sKh = g_Kh + (size_t)(b * SEQ + kb * 64) * ADIM;
            const __half* sKl = g_Kl + (size_t)(b * SEQ + kb * 64) * ADIM;
            #pragma unroll
            for (int k = 0; k < 4; k++) {
                int f = tid + 128 * k;
                int r = f >> 3, c = f & 7;
                *(uint4*)(sh + OFF_KH + r * ST + 8 * c) = *(const uint4*)(sKh + r * ADIM + 8 * c);
                *(uint4*)(sh + OFF_KL + r * ST + 8 * c) = *(const uint4*)(sKl + r * ADIM + 8 * c);
            }
        }
        {
            int kp = tid & 31;
            int a0 = (tid >> 5) * 16;
            const __half* r0h = g_Vh + (size_t)(b * SEQ + kb * 64 + 2 * kp) * ADIM + a0;
            const __half* r0l = g_Vl + (size_t)(b * SEQ + kb * 64 + 2 * kp) * ADIM + a0;
            H8 xh0 = *(const H8*)(r0h),      xh1 = *(const H8*)(r0h + 8);
            H8 yh0 = *(const H8*)(r0h + 64), yh1 = *(const H8*)(r0h + 72);
            H8 xl0 = *(const H8*)(r0l),      xl1 = *(const H8*)(r0l + 8);
            H8 yl0 = *(const H8*)(r0l + 64), yl1 = *(const H8*)(r0l + 72);
            #pragma unroll
            for (int i = 0; i < 8; i++) {
                *(__half2*)(sh + OFF_VH + (a0 + i) * ST + 2 * kp)     = __halves2half2(xh0.h[i], yh0.h[i]);
                *(__half2*)(sh + OFF_VH + (a0 + 8 + i) * ST + 2 * kp) = __halves2half2(xh1.h[i], yh1.h[i]);
                *(__half2*)(sh + OFF_VL + (a0 + i) * ST + 2 * kp)     = __halves2half2(xl0.h[i], yl0.h[i]);
                *(__half2*)(sh + OFF_VL + (a0 + 8 + i) * ST + 2 * kp) = __halves2half2(xl1.h[i], yl1.h[i]);
            }
        }
        __syncthreads();

        // ---- S = Q K^T
        float sreg[8][4];
        #pragma unroll
        for (int j = 0; j < 8; j++)
            #pragma unroll
            for (int i = 0; i < 4; i++) sreg[j][i] = 0.f;

        const unsigned* Kh32 = (const unsigned*)(sh + OFF_KH);
        const unsigned* Kl32 = (const unsigned*)(sh + OFF_KL);
        #pragma unroll
        for (int kc = 0; kc < 4; kc++) {
            #pragma unroll
            for (int j = 0; j < 8; j++) {
                int bb = (8 * j + g) * SW + 8 * kc + cq;
                unsigned bh[2] = { Kh32[bb], Kh32[bb + 4] };
                unsigned bl[2] = { Kl32[bb], Kl32[bb + 4] };
                mma16816(sreg[j], qh[kc], bh);
                mma16816(sreg[j], qh[kc], bl);
                mma16816(sreg[j], ql[kc], bh);
            }
        }

        if (kb == qi) {
            int r_lo = 16 * w + g, r_hi = r_lo + 8;
            #pragma unroll
            for (int j = 0; j < 8; j++) {
                int c0 = 8 * j + 2 * cq;
                if (c0     > r_lo) sreg[j][0] = -1e30f;
                if (c0 + 1 > r_lo) sreg[j][1] = -1e30f;
                if (c0     > r_hi) sreg[j][2] = -1e30f;
                if (c0 + 1 > r_hi) sreg[j][3] = -1e30f;
            }
        }

        // ---- online softmax
        float mx0 = -1e30f, mx1 = -1e30f;
        #pragma unroll
        for (int j = 0; j < 8; j++) {
            mx0 = fmaxf(mx0, fmaxf(sreg[j][0], sreg[j][1]));
            mx1 = fmaxf(mx1, fmaxf(sreg[j][2], sreg[j][3]));
        }
        mx0 = fmaxf(mx0, __shfl_xor_sync(0xffffffffu, mx0, 1));
        mx0 = fmaxf(mx0, __shfl_xor_sync(0xffffffffu, mx0, 2));
        mx1 = fmaxf(mx1, __shfl_xor_sync(0xffffffffu, mx1, 1));
        mx1 = fmaxf(mx1, __shfl_xor_sync(0xffffffffu, mx1, 2));
        float mn0 = fmaxf(m_lo, mx0), mn1 = fmaxf(m_hi, mx1);
        float sc0 = __expf(m_lo - mn0), sc1 = __expf(m_hi - mn1);
        m_lo = mn0; m_hi = mn1;
        float su0 = 0.f, su1 = 0.f;
        #pragma unroll
        for (int j = 0; j < 8; j++) {
            sreg[j][0] = __expf(sreg[j][0] - mn0);
            sreg[j][1] = __expf(sreg[j][1] - mn0);
            sreg[j][2] = __expf(sreg[j][2] - mn1);
            sreg[j][3] = __expf(sreg[j][3] - mn1);
            su0 += sreg[j][0] + sreg[j][1];
            su1 += sreg[j][2] + sreg[j][3];
        }
        su0 += __shfl_xor_sync(0xffffffffu, su0, 1);
        su0 += __shfl_xor_sync(0xffffffffu, su0, 2);
        su1 += __shfl_xor_sync(0xffffffffu, su1, 1);
        su1 += __shfl_xor_sync(0xffffffffu, su1, 2);
        l_lo = l_lo * sc0 + su0;
        l_hi = l_hi * sc1 + su1;
        #pragma unroll
        for (int j = 0; j < 8; j++) {
            o[j][0] *= sc0; o[j][1] *= sc0;
            o[j][2] *= sc1; o[j][3] *= sc1;
        }

        // ---- pack P directly into PV A-fragments (no smem round-trip).
        // A-frag chunk kc (kv cols 16kc..16kc+15) comes from S tiles j=2kc, 2kc+1.
        unsigned ph[4][4], pl[4][4];
        #pragma unroll
        for (int kc = 0; kc < 4; kc++) {
            split2(sreg[2 * kc][0],     sreg[2 * kc][1],     ph[kc][0], pl[kc][0]);
            split2(sreg[2 * kc][2],     sreg[2 * kc][3],     ph[kc][1], pl[kc][1]);
            split2(sreg[2 * kc + 1][0], sreg[2 * kc + 1][1], ph[kc][2], pl[kc][2]);
            split2(sreg[2 * kc + 1][2], sreg[2 * kc + 1][3], ph[kc][3], pl[kc][3]);
        }

        // ---- O += P V
        const unsigned* Vh32 = (const unsigned*)(sh + OFF_VH);
        const unsigned* Vl32 = (const unsigned*)(sh + OFF_VL);
        #pragma unroll
        for (int kc = 0; kc < 4; kc++) {
            #pragma unroll
            for (int j = 0; j < 8; j++) {
                int bb = (8 * j + g) * SW + 8 * kc + cq;
                unsigned bh[2] = { Vh32[bb], Vh32[bb + 4] };
                unsigned bl[2] = { Vl32[bb], Vl32[bb + 4] };
                mma16816(o[j], ph[kc], bh);
                mma16816(o[j], ph[kc], bl);
                mma16816(o[j], pl[kc], bh);
            }
        }
    }

    // ---- epilogue: write unnormalized partial O + (m, l)
    const int row_lo = q0 + 16 * w + g;
    const int row_hi = row_lo + 8;
    const size_t sb  = (size_t)(b * NS + s) * SEQ;
    #pragma unroll
    for (int j = 0; j < 8; j++) {
        int col = 8 * j + 2 * cq;
        *(float2*)(g_Om + (sb + row_lo) * ADIM + col) = make_float2(o[j][0], o[j][1]);
        *(float2*)(g_Om + (sb + row_hi) * ADIM + col) = make_float2(o[j][2], o[j][3]);
    }
    if (cq == 0) {
        g_m[sb + row_lo] = m_lo;  g_l[sb + row_lo] = l_lo;
        g_m[sb + row_hi] = m_hi;  g_l[sb + row_hi] = l_hi;
    }
}

// ---------------------------------------------------------------------------
// Combine split-KV partials.
// ---------------------------------------------------------------------------
__global__ __launch_bounds__(128)
void combine_kernel(float* __restrict__ out)
{
    const int tid = threadIdx.x;
    const int row = blockIdx.x * 8 + (tid >> 4);
    const int b   = blockIdx.y;
    const int c0  = (tid & 15) * 4;
    const int qi  = row >> 6;
    const int ns  = (qi + 1 < NS) ? (qi + 1) : NS;

    float m = -1e30f;
    #pragma unroll
    for (int s = 0; s < NS; s++)
        if (s < ns) m = fmaxf(m, g_m[(size_t)(b * NS + s) * SEQ + row]);

    float l = 0.f;
    float4 acc = make_float4(0.f, 0.f, 0.f, 0.f);
    #pragma unroll
    for (int s = 0; s < NS; s++) {
        if (s >= ns) break;
        size_t sb = (size_t)(b * NS + s) * SEQ + row;
        float wgt = __expf(g_m[sb] - m);
        l += g_l[sb] * wgt;
        float4 v = *(const float4*)(g_Om + sb * ADIM + c0);
        acc.x += v.x * wgt; acc.y += v.y * wgt;
        acc.z += v.z * wgt; acc.w += v.w * wgt;
    }
    float inv = 1.f / l;
    float4 r;
    r.x = rintf(acc.x * inv * 1e4f) * 1e-4f;
    r.y = rintf(acc.y * inv * 1e4f) * 1e-4f;
    r.z = rintf(acc.z * inv * 1e4f) * 1e-4f;
    r.w = rintf(acc.w * inv * 1e4f) * 1e-4f;
    *(float4*)(out + ((size_t)b * SEQ + row) * ADIM + c0) = r;
}

extern "C" void kernel_launch(void* const* d_in, const int* in_sizes, int n_in,
                              void* d_out, int out_size)
{
    const float* x  = (const float*)d_in[0];
    const float* wk = (const float*)d_in[1];
    const float* wq = (const float*)d_in[2];
    const float* wv = (const float*)d_in[3];
    float* out = (float*)d_out;

    wsplit<<<192, 256>>>(wk, wq, wv);
    qkv_proj<<<(NB * SEQ) / 64, 256>>>(x);

    int smem = SMEM_HALVES * (int)sizeof(__half);  // 36864 B
    cudaFuncSetAttribute(attn_kernel, cudaFuncAttributeMaxDynamicSharedMemorySize, smem);
    attn_kernel<<<dim3((SEQ / 64) * NS, NB), 128, smem>>>();

    combine_kernel<<<dim3(SEQ / 8, NB), 128>>>(out);
}

// round 5
// speedup vs baseline: 1.0075x; 1.0075x over previous
#include <cuda_runtime.h>
#include <cuda_fp16.h>
#include <math.h>

#define NB   4
#define SEQ  4096
#define EDIM 1024
#define ADIM 64
#define NS   4      // KV splits per q-tile

// Projected Q,K,V stored as split fp16 planes (hi + lo), [B*S, A] each.
__device__ __half g_Qh[NB * SEQ * ADIM];
__device__ __half g_Ql[NB * SEQ * ADIM];
__device__ __half g_Kh[NB * SEQ * ADIM];
__device__ __half g_Kl[NB * SEQ * ADIM];
__device__ __half g_Vh[NB * SEQ * ADIM];
__device__ __half g_Vl[NB * SEQ * ADIM];

// Pre-split weights: rows 0-63 = W_K, 64-127 = W_Q, 128-191 = W_V. [192][1024]
__device__ __half g_Wh[192 * EDIM];
__device__ __half g_Wl[192 * EDIM];

// Split-KV partial results: O (unnormalized), row max m, row sum l.
__device__ float g_Om[NB * NS * SEQ * ADIM];   // 16.8 MB
__device__ float g_m [NB * NS * SEQ];
__device__ float g_l [NB * NS * SEQ];

// m16n8k16 f16 MMA, f32 accumulate, in-place C.
__device__ __forceinline__ void mma16816(float d[4], const unsigned a[4], const unsigned b[2])
{
    asm volatile(
        "mma.sync.aligned.m16n8k16.row.col.f32.f16.f16.f32 "
        "{%0,%1,%2,%3}, {%4,%5,%6,%7}, {%8,%9}, {%0,%1,%2,%3};\n"
        : "+f"(d[0]), "+f"(d[1]), "+f"(d[2]), "+f"(d[3])
        : "r"(a[0]), "r"(a[1]), "r"(a[2]), "r"(a[3]), "r"(b[0]), "r"(b[1]));
}

__device__ __forceinline__ void split1(float v, __half& h, __half& l)
{
    h = __float2half_rn(v);
    l = __float2half_rn(v - __half2float(h));
}

// Split a float pair into packed hi/lo half2 words.
__device__ __forceinline__ void split2(float a, float b, unsigned& hi, unsigned& lo)
{
    __half2 h = __floats2half2_rn(a, b);
    float2 hf = __half22float2(h);
    __half2 l = __floats2half2_rn(a - hf.x, b - hf.y);
    hi = *(unsigned*)&h;
    lo = *(unsigned*)&l;
}

struct alignas(16) H8 { __half h[8]; };

// ---------------------------------------------------------------------------
// One-time weight split: fp32 W_{K,Q,V} -> fp16 hi/lo planes in global.
// ---------------------------------------------------------------------------
__global__ __launch_bounds__(256)
void wsplit(const float* __restrict__ wk,
            const float* __restrict__ wq,
            const float* __restrict__ wv)
{
    int idx  = blockIdx.x * 256 + threadIdx.x;   // one float4 per thread
    int base = idx * 4;
    int r = base >> 10;
    int c = base & 1023;
    const float* src = (r < 64)  ? wk + (size_t)r * EDIM
                     : (r < 128) ? wq + (size_t)(r - 64) * EDIM
                                 : wv + (size_t)(r - 128) * EDIM;
    float4 v = *(const float4*)(src + c);
    __half h[4], l[4];
    split1(v.x, h[0], l[0]); split1(v.y, h[1], l[1]);
    split1(v.z, h[2], l[2]); split1(v.w, h[3], l[3]);
    *(uint2*)(g_Wh + (size_t)r * EDIM + c) = *(uint2*)h;
    *(uint2*)(g_Wl + (size_t)r * EDIM + c) = *(uint2*)l;
}

// ---------------------------------------------------------------------------
// QKV projection on tensor cores (fp16x2 split); W pre-split in global.
// ---------------------------------------------------------------------------
__global__ __launch_bounds__(256, 2)
void qkv_proj(const float* __restrict__ x)
{
    __shared__ __align__(16) __half Xh[64 * 40];
    __shared__ __align__(16) __half Xl[64 * 40];
    __shared__ __align__(16) __half Wh[192 * 40];
    __shared__ __align__(16) __half Wl[192 * 40];

    const int tid  = threadIdx.x;
    const int warp = tid >> 5;
    const int lane = tid & 31;
    const int g    = lane >> 2;
    const int cq   = lane & 3;
    const int rg   = warp >> 1;
    const int cg   = warp & 1;
    const int rows0 = blockIdx.x * 64;

    float acc[12][4];
    #pragma unroll
    for (int j = 0; j < 12; j++)
        #pragma unroll
        for (int i = 0; i < 4; i++) acc[j][i] = 0.f;

    for (int e0 = 0; e0 < EDIM; e0 += 32) {
        // X chunk [64 x 32]: load fp32, split inline
        #pragma unroll
        for (int k = 0; k < 2; k++) {
            int f  = tid + k * 256;
            int r  = f >> 3;
            int c4 = f & 7;
            float4 v = *(const float4*)(x + (size_t)(rows0 + r) * EDIM + e0 + c4 * 4);
            __half h[4], l[4];
            split1(v.x, h[0], l[0]); split1(v.y, h[1], l[1]);
            split1(v.z, h[2], l[2]); split1(v.w, h[3], l[3]);
            *(uint2*)(Xh + r * 40 + c4 * 4) = *(uint2*)h;
            *(uint2*)(Xl + r * 40 + c4 * 4) = *(uint2*)l;
        }
        // W chunk [192 x 32]: straight uint4 copies of pre-split planes
        #pragma unroll
        for (int k = 0; k < 3; k++) {
            int f  = tid + k * 256;
            int r  = f >> 2;
            int c8 = f & 3;
            *(uint4*)(Wh + r * 40 + c8 * 8) = *(const uint4*)(g_Wh + (size_t)r * EDIM + e0 + c8 * 8);
            *(uint4*)(Wl + r * 40 + c8 * 8) = *(const uint4*)(g_Wl + (size_t)r * EDIM + e0 + c8 * 8);
        }
        __syncthreads();

        const unsigned* Xh32 = (const unsigned*)Xh;
        const unsigned* Xl32 = (const unsigned*)Xl;
        const unsigned* Wh32 = (const unsigned*)Wh;
        const unsigned* Wl32 = (const unsigned*)Wl;

        #pragma unroll
        for (int kc = 0; kc < 2; kc++) {
            int ab = (16 * rg + g) * 20 + 8 * kc + cq;
            unsigned ah[4] = { Xh32[ab], Xh32[ab + 160], Xh32[ab + 4], Xh32[ab + 164] };
            unsigned al[4] = { Xl32[ab], Xl32[ab + 160], Xl32[ab + 4], Xl32[ab + 164] };
            #pragma unroll
            for (int j = 0; j < 12; j++) {
                int n0 = cg * 96 + 8 * j;
                int bb = (n0 + g) * 20 + 8 * kc + cq;
                unsigned bh[2] = { Wh32[bb], Wh32[bb + 4] };
                unsigned bl[2] = { Wl32[bb], Wl32[bb + 4] };
                mma16816(acc[j], ah, bh);
                mma16816(acc[j], ah, bl);
                mma16816(acc[j], al, bh);
            }
        }
        __syncthreads();
    }

    const int row_lo = rows0 + 16 * rg + g;
    const int row_hi = row_lo + 8;
    #pragma unroll
    for (int j = 0; j < 12; j++) {
        int colg = cg * 96 + 8 * j + 2 * cq;
        __half *dh, *dl;
        float sc = 1.f;
        int cl;
        if (colg < 64)       { dh = g_Kh; dl = g_Kl; cl = colg; }
        else if (colg < 128) { dh = g_Qh; dl = g_Ql; cl = colg - 64; sc = 0.125f; }
        else                 { dh = g_Vh; dl = g_Vl; cl = colg - 128; }

        unsigned h2, l2;
        split2(acc[j][0] * sc, acc[j][1] * sc, h2, l2);
        *(unsigned*)(dh + (size_t)row_lo * ADIM + cl) = h2;
        *(unsigned*)(dl + (size_t)row_lo * ADIM + cl) = l2;
        split2(acc[j][2] * sc, acc[j][3] * sc, h2, l2);
        *(unsigned*)(dh + (size_t)row_hi * ADIM + cl) = h2;
        *(unsigned*)(dl + (size_t)row_hi * ADIM + cl) = l2;
    }
}

// ---------------------------------------------------------------------------
// Causal flash attention, split-KV. P packed to A-fragments per k-chunk,
// fused with the PV MMA so the extra live-register window is only 8 regs.
// ---------------------------------------------------------------------------
#define ST 72
#define SW 36
#define OFF_KH 0
#define OFF_KL 4608
#define OFF_VH 9216
#define OFF_VL 13824
#define SMEM_HALVES 18432

__global__ __launch_bounds__(128, 3)
void attn_kernel()
{
    extern __shared__ __align__(16) __half sh[];

    const int tid  = threadIdx.x;
    const int w    = tid >> 5;
    const int lane = tid & 31;
    const int g    = lane >> 2;
    const int cq   = lane & 3;
    const int bx   = blockIdx.x;
    const int s    = bx & (NS - 1);
    const int qi   = (SEQ / 64 - 1) - (bx >> 2);   // heavy q-tiles first
    const int b    = blockIdx.y;
    const int q0   = qi * 64;

    if (qi < s) return;

    // Resident Q fragments (pre-scaled at projection)
    unsigned qh[4][4], ql[4][4];
    {
        size_t rl = (size_t)(b * SEQ + q0 + 16 * w + g) * ADIM;
        size_t rh = rl + 8 * ADIM;
        #pragma unroll
        for (int kc = 0; kc < 4; kc++) {
            int off = 16 * kc + 2 * cq;
            qh[kc][0] = *(const unsigned*)(g_Qh + rl + off);
            qh[kc][1] = *(const unsigned*)(g_Qh + rh + off);
            qh[kc][2] = *(const unsigned*)(g_Qh + rl + off + 8);
            qh[kc][3] = *(const unsigned*)(g_Qh + rh + off + 8);
            ql[kc][0] = *(const unsigned*)(g_Ql + rl + off);
            ql[kc][1] = *(const unsigned*)(g_Ql + rh + off);
            ql[kc][2] = *(const unsigned*)(g_Ql + rl + off + 8);
            ql[kc][3] = *(const unsigned*)(g_Ql + rh + off + 8);
        }
    }

    float o[8][4];
    #pragma unroll
    for (int j = 0; j < 8; j++)
        #pragma unroll
        for (int i = 0; i < 4; i++) o[j][i] = 0.f;
    float m_lo = -1e30f, m_hi = -1e30f, l_lo = 0.f, l_hi = 0.f;

    for (int kb = s; kb <= qi; kb += NS) {
        __syncthreads();
        {
            const __half* sKh = g_Kh + (size_t)(b * SEQ + kb * 64) * ADIM;
            const __half* sKl = g_Kl + (size_t)(b * SEQ + kb * 64) * ADIM;
            #pragma unroll
            for (int k = 0; k < 4; k++) {
                int f = tid + 128 * k;
                int r = f >> 3, c = f & 7;
                *(uint4*)(sh + OFF_KH + r * ST + 8 * c) = *(const uint4*)(sKh + r * ADIM + 8 * c);
                *(uint4*)(sh + OFF_KL + r * ST + 8 * c) = *(const uint4*)(sKl + r * ADIM + 8 * c);
            }
        }
        {
            int kp = tid & 31;
            int a0 = (tid >> 5) * 16;
            const __half* r0h = g_Vh + (size_t)(b * SEQ + kb * 64 + 2 * kp) * ADIM + a0;
            const __half* r0l = g_Vl + (size_t)(b * SEQ + kb * 64 + 2 * kp) * ADIM + a0;
            H8 xh0 = *(const H8*)(r0h),      xh1 = *(const H8*)(r0h + 8);
            H8 yh0 = *(const H8*)(r0h + 64), yh1 = *(const H8*)(r0h + 72);
            H8 xl0 = *(const H8*)(r0l),      xl1 = *(const H8*)(r0l + 8);
            H8 yl0 = *(const H8*)(r0l + 64), yl1 = *(const H8*)(r0l + 72);
            #pragma unroll
            for (int i = 0; i < 8; i++) {
                *(__half2*)(sh + OFF_VH + (a0 + i) * ST + 2 * kp)     = __halves2half2(xh0.h[i], yh0.h[i]);
                *(__half2*)(sh + OFF_VH + (a0 + 8 + i) * ST + 2 * kp) = __halves2half2(xh1.h[i], yh1.h[i]);
                *(__half2*)(sh + OFF_VL + (a0 + i) * ST + 2 * kp)     = __halves2half2(xl0.h[i], yl0.h[i]);
                *(__half2*)(sh + OFF_VL + (a0 + 8 + i) * ST + 2 * kp) = __halves2half2(xl1.h[i], yl1.h[i]);
            }
        }
        __syncthreads();

        // ---- S = Q K^T
        float sreg[8][4];
        #pragma unroll
        for (int j = 0; j < 8; j++)
            #pragma unroll
            for (int i = 0; i < 4; i++) sreg[j][i] = 0.f;

        const unsigned* Kh32 = (const unsigned*)(sh + OFF_KH);
        const unsigned* Kl32 = (const unsigned*)(sh + OFF_KL);
        #pragma unroll
        for (int kc = 0; kc < 4; kc++) {
            #pragma unroll
            for (int j = 0; j < 8; j++) {
                int bb = (8 * j + g) * SW + 8 * kc + cq;
                unsigned bh[2] = { Kh32[bb], Kh32[bb + 4] };
                unsigned bl[2] = { Kl32[bb], Kl32[bb + 4] };
                mma16816(sreg[j], qh[kc], bh);
                mma16816(sreg[j], qh[kc], bl);
                mma16816(sreg[j], ql[kc], bh);
            }
        }

        if (kb == qi) {
            int r_lo = 16 * w + g, r_hi = r_lo + 8;
            #pragma unroll
            for (int j = 0; j < 8; j++) {
                int c0 = 8 * j + 2 * cq;
                if (c0     > r_lo) sreg[j][0] = -1e30f;
                if (c0 + 1 > r_lo) sreg[j][1] = -1e30f;
                if (c0     > r_hi) sreg[j][2] = -1e30f;
                if (c0 + 1 > r_hi) sreg[j][3] = -1e30f;
            }
        }

        // ---- online softmax
        float mx0 = -1e30f, mx1 = -1e30f;
        #pragma unroll
        for (int j = 0; j < 8; j++) {
            mx0 = fmaxf(mx0, fmaxf(sreg[j][0], sreg[j][1]));
            mx1 = fmaxf(mx1, fmaxf(sreg[j][2], sreg[j][3]));
        }
        mx0 = fmaxf(mx0, __shfl_xor_sync(0xffffffffu, mx0, 1));
        mx0 = fmaxf(mx0, __shfl_xor_sync(0xffffffffu, mx0, 2));
        mx1 = fmaxf(mx1, __shfl_xor_sync(0xffffffffu, mx1, 1));
        mx1 = fmaxf(mx1, __shfl_xor_sync(0xffffffffu, mx1, 2));
        float mn0 = fmaxf(m_lo, mx0), mn1 = fmaxf(m_hi, mx1);
        float sc0 = __expf(m_lo - mn0), sc1 = __expf(m_hi - mn1);
        m_lo = mn0; m_hi = mn1;
        float su0 = 0.f, su1 = 0.f;
        #pragma unroll
        for (int j = 0; j < 8; j++) {
            sreg[j][0] = __expf(sreg[j][0] - mn0);
            sreg[j][1] = __expf(sreg[j][1] - mn0);
            sreg[j][2] = __expf(sreg[j][2] - mn1);
            sreg[j][3] = __expf(sreg[j][3] - mn1);
            su0 += sreg[j][0] + sreg[j][1];
            su1 += sreg[j][2] + sreg[j][3];
        }
        su0 += __shfl_xor_sync(0xffffffffu, su0, 1);
        su0 += __shfl_xor_sync(0xffffffffu, su0, 2);
        su1 += __shfl_xor_sync(0xffffffffu, su1, 1);
        su1 += __shfl_xor_sync(0xffffffffu, su1, 2);
        l_lo = l_lo * sc0 + su0;
        l_hi = l_hi * sc1 + su1;
        #pragma unroll
        for (int j = 0; j < 8; j++) {
            o[j][0] *= sc0; o[j][1] *= sc0;
            o[j][2] *= sc1; o[j][3] *= sc1;
        }

        // ---- O += P V, packing P per k-chunk (only 8 extra regs live)
        const unsigned* Vh32 = (const unsigned*)(sh + OFF_VH);
        const unsigned* Vl32 = (const unsigned*)(sh + OFF_VL);
        #pragma unroll
        for (int kc = 0; kc < 4; kc++) {
            unsigned ph[4], pl[4];
            split2(sreg[2 * kc][0],     sreg[2 * kc][1],     ph[0], pl[0]);
            split2(sreg[2 * kc][2],     sreg[2 * kc][3],     ph[1], pl[1]);
            split2(sreg[2 * kc + 1][0], sreg[2 * kc + 1][1], ph[2], pl[2]);
            split2(sreg[2 * kc + 1][2], sreg[2 * kc + 1][3], ph[3], pl[3]);
            #pragma unroll
            for (int j = 0; j < 8; j++) {
                int bb = (8 * j + g) * SW + 8 * kc + cq;
                unsigned bh[2] = { Vh32[bb], Vh32[bb + 4] };
                unsigned bl[2] = { Vl32[bb], Vl32[bb + 4] };
                mma16816(o[j], ph, bh);
                mma16816(o[j], ph, bl);
                mma16816(o[j], pl, bh);
            }
        }
    }

    // ---- epilogue: write unnormalized partial O + (m, l)
    const int row_lo = q0 + 16 * w + g;
    const int row_hi = row_lo + 8;
    const size_t sb  = (size_t)(b * NS + s) * SEQ;
    #pragma unroll
    for (int j = 0; j < 8; j++) {
        int col = 8 * j + 2 * cq;
        *(float2*)(g_Om + (sb + row_lo) * ADIM + col) = make_float2(o[j][0], o[j][1]);
        *(float2*)(g_Om + (sb + row_hi) * ADIM + col) = make_float2(o[j][2], o[j][3]);
    }
    if (cq == 0) {
        g_m[sb + row_lo] = m_lo;  g_l[sb + row_lo] = l_lo;
        g_m[sb + row_hi] = m_hi;  g_l[sb + row_hi] = l_hi;
    }
}

// ---------------------------------------------------------------------------
// Combine split-KV partials.
// ---------------------------------------------------------------------------
__global__ __launch_bounds__(128)
void combine_kernel(float* __restrict__ out)
{
    const int tid = threadIdx.x;
    const int row = blockIdx.x * 8 + (tid >> 4);
    const int b   = blockIdx.y;
    const int c0  = (tid & 15) * 4;
    const int qi  = row >> 6;
    const int ns  = (qi + 1 < NS) ? (qi + 1) : NS;

    float m = -1e30f;
    #pragma unroll
    for (int s = 0; s < NS; s++)
        if (s < ns) m = fmaxf(m, g_m[(size_t)(b * NS + s) * SEQ + row]);

    float l = 0.f;
    float4 acc = make_float4(0.f, 0.f, 0.f, 0.f);
    #pragma unroll
    for (int s = 0; s < NS; s++) {
        if (s >= ns) break;
        size_t sb = (size_t)(b * NS + s) * SEQ + row;
        float wgt = __expf(g_m[sb] - m);
        l += g_l[sb] * wgt;
        float4 v = *(const float4*)(g_Om + sb * ADIM + c0);
        acc.x += v.x * wgt; acc.y += v.y * wgt;
        acc.z += v.z * wgt; acc.w += v.w * wgt;
    }
    float inv = 1.f / l;
    float4 r;
    r.x = rintf(acc.x * inv * 1e4f) * 1e-4f;
    r.y = rintf(acc.y * inv * 1e4f) * 1e-4f;
    r.z = rintf(acc.z * inv * 1e4f) * 1e-4f;
    r.w = rintf(acc.w * inv * 1e4f) * 1e-4f;
    *(float4*)(out + ((size_t)b * SEQ + row) * ADIM + c0) = r;
}

extern "C" void kernel_launch(void* const* d_in, const int* in_sizes, int n_in,
                              void* d_out, int out_size)
{
    const float* x  = (const float*)d_in[0];
    const float* wk = (const float*)d_in[1];
    const float* wq = (const float*)d_in[2];
    const float* wv = (const float*)d_in[3];
    float* out = (float*)d_out;

    wsplit<<<192, 256>>>(wk, wq, wv);
    qkv_proj<<<(NB * SEQ) / 64, 256>>>(x);

    int smem = SMEM_HALVES * (int)sizeof(__half);  // 36864 B
    cudaFuncSetAttribute(attn_kernel, cudaFuncAttributeMaxDynamicSharedMemorySize, smem);
    attn_kernel<<<dim3((SEQ / 64) * NS, NB), 128, smem>>>();

    combine_kernel<<<dim3(SEQ / 8, NB), 128>>>(out);
}

// round 6
// speedup vs baseline: 1.7250x; 1.7120x over previous
#include <cuda_runtime.h>
#include <cuda_fp16.h>
#include <math.h>

#define NB   4
#define SEQ  4096
#define EDIM 1024
#define ADIM 64
#define NS   8      // KV splits per q-tile

// Projected Q,K,V stored as split fp16 planes (hi + lo), [B*S, A] each.
__device__ __half g_Qh[NB * SEQ * ADIM];
__device__ __half g_Ql[NB * SEQ * ADIM];
__device__ __half g_Kh[NB * SEQ * ADIM];
__device__ __half g_Kl[NB * SEQ * ADIM];
__device__ __half g_Vh[NB * SEQ * ADIM];
__device__ __half g_Vl[NB * SEQ * ADIM];

// Split-KV partial results: O (unnormalized), row max m, row sum l.
__device__ float g_Om[NB * NS * SEQ * ADIM];   // 33.6 MB
__device__ float g_m [NB * NS * SEQ];
__device__ float g_l [NB * NS * SEQ];

// m16n8k16 f16 MMA, f32 accumulate, in-place C.
__device__ __forceinline__ void mma16816(float d[4], const unsigned a[4], const unsigned b[2])
{
    asm volatile(
        "mma.sync.aligned.m16n8k16.row.col.f32.f16.f16.f32 "
        "{%0,%1,%2,%3}, {%4,%5,%6,%7}, {%8,%9}, {%0,%1,%2,%3};\n"
        : "+f"(d[0]), "+f"(d[1]), "+f"(d[2]), "+f"(d[3])
        : "r"(a[0]), "r"(a[1]), "r"(a[2]), "r"(a[3]), "r"(b[0]), "r"(b[1]));
}

__device__ __forceinline__ void split1(float v, __half& h, __half& l)
{
    h = __float2half_rn(v);
    l = __float2half_rn(v - __half2float(h));
}

// Split a float pair into packed hi/lo half2 words.
__device__ __forceinline__ void split2(float a, float b, unsigned& hi, unsigned& lo)
{
    __half2 h = __floats2half2_rn(a, b);
    float2 hf = __half22float2(h);
    __half2 l = __floats2half2_rn(a - hf.x, b - hf.y);
    hi = *(unsigned*)&h;
    lo = *(unsigned*)&l;
}

struct alignas(16) H8 { __half h[8]; };

// ---------------------------------------------------------------------------
// QKV projection on tensor cores (fp16x2 split). EXACT R2 version (88us).
// ---------------------------------------------------------------------------
__global__ __launch_bounds__(256, 2)
void qkv_proj(const float* __restrict__ x,
              const float* __restrict__ wk,
              const float* __restrict__ wq,
              const float* __restrict__ wv)
{
    __shared__ __align__(16) __half Xh[64 * 40];
    __shared__ __align__(16) __half Xl[64 * 40];
    __shared__ __align__(16) __half Wh[192 * 40];
    __shared__ __align__(16) __half Wl[192 * 40];

    const int tid  = threadIdx.x;
    const int warp = tid >> 5;
    const int lane = tid & 31;
    const int g    = lane >> 2;
    const int cq   = lane & 3;
    const int rg   = warp >> 1;
    const int cg   = warp & 1;
    const int rows0 = blockIdx.x * 64;

    float acc[12][4];
    #pragma unroll
    for (int j = 0; j < 12; j++)
        #pragma unroll
        for (int i = 0; i < 4; i++) acc[j][i] = 0.f;

    for (int e0 = 0; e0 < EDIM; e0 += 32) {
        #pragma unroll
        for (int k = 0; k < 2; k++) {
            int f  = tid + k * 256;
            int r  = f >> 3;
            int c4 = f & 7;
            float4 v = *(const float4*)(x + (size_t)(rows0 + r) * EDIM + e0 + c4 * 4);
            float vv[4] = { v.x, v.y, v.z, v.w };
            #pragma unroll
            for (int i = 0; i < 4; i++) {
                __half h, l; split1(vv[i], h, l);
                Xh[r * 40 + c4 * 4 + i] = h;
                Xl[r * 40 + c4 * 4 + i] = l;
            }
        }
        #pragma unroll
        for (int k = 0; k < 6; k++) {
            int f  = tid + k * 256;
            int r  = f >> 3;
            int c4 = f & 7;
            const float* src = (r < 64)  ? wk + (size_t)r * EDIM
                             : (r < 128) ? wq + (size_t)(r - 64) * EDIM
                                         : wv + (size_t)(r - 128) * EDIM;
            float4 v = *(const float4*)(src + e0 + c4 * 4);
            float vv[4] = { v.x, v.y, v.z, v.w };
            #pragma unroll
            for (int i = 0; i < 4; i++) {
                __half h, l; split1(vv[i], h, l);
                Wh[r * 40 + c4 * 4 + i] = h;
                Wl[r * 40 + c4 * 4 + i] = l;
            }
        }
        __syncthreads();

        const unsigned* Xh32 = (const unsigned*)Xh;
        const unsigned* Xl32 = (const unsigned*)Xl;
        const unsigned* Wh32 = (const unsigned*)Wh;
        const unsigned* Wl32 = (const unsigned*)Wl;

        #pragma unroll
        for (int kc = 0; kc < 2; kc++) {
            int ab = (16 * rg + g) * 20 + 8 * kc + cq;
            unsigned ah[4] = { Xh32[ab], Xh32[ab + 160], Xh32[ab + 4], Xh32[ab + 164] };
            unsigned al[4] = { Xl32[ab], Xl32[ab + 160], Xl32[ab + 4], Xl32[ab + 164] };
            #pragma unroll
            for (int j = 0; j < 12; j++) {
                int n0 = cg * 96 + 8 * j;
                int bb = (n0 + g) * 20 + 8 * kc + cq;
                unsigned bh[2] = { Wh32[bb], Wh32[bb + 4] };
                unsigned bl[2] = { Wl32[bb], Wl32[bb + 4] };
                mma16816(acc[j], ah, bh);
                mma16816(acc[j], ah, bl);
                mma16816(acc[j], al, bh);
            }
        }
        __syncthreads();
    }

    const int row_lo = rows0 + 16 * rg + g;
    const int row_hi = row_lo + 8;
    #pragma unroll
    for (int j = 0; j < 12; j++) {
        int colg = cg * 96 + 8 * j + 2 * cq;
        __half *dh, *dl;
        float sc = 1.f;
        int cl;
        if (colg < 64)       { dh = g_Kh; dl = g_Kl; cl = colg; }
        else if (colg < 128) { dh = g_Qh; dl = g_Ql; cl = colg - 64; sc = 0.125f; }
        else                 { dh = g_Vh; dl = g_Vl; cl = colg - 128; }

        unsigned h2, l2;
        split2(acc[j][0] * sc, acc[j][1] * sc, h2, l2);
        *(unsigned*)(dh + (size_t)row_lo * ADIM + cl) = h2;
        *(unsigned*)(dl + (size_t)row_lo * ADIM + cl) = l2;
        split2(acc[j][2] * sc, acc[j][3] * sc, h2, l2);
        *(unsigned*)(dh + (size_t)row_hi * ADIM + cl) = h2;
        *(unsigned*)(dl + (size_t)row_hi * ADIM + cl) = l2;
    }
}

// ---------------------------------------------------------------------------
// Causal flash attention, split-KV (NS=8). P packed to A-fragments per
// k-chunk, fused with the PV MMA (8 extra live regs).
// ---------------------------------------------------------------------------
#define ST 72
#define SW 36
#define OFF_KH 0
#define OFF_KL 4608
#define OFF_VH 9216
#define OFF_VL 13824
#define SMEM_HALVES 18432

__global__ __launch_bounds__(128, 3)
void attn_kernel()
{
    extern __shared__ __align__(16) __half sh[];

    const int tid  = threadIdx.x;
    const int w    = tid >> 5;
    const int lane = tid & 31;
    const int g    = lane >> 2;
    const int cq   = lane & 3;
    const int bx   = blockIdx.x;
    const int s    = bx & (NS - 1);
    const int qi   = (SEQ / 64 - 1) - (bx >> 3);   // heavy q-tiles first
    const int b    = blockIdx.y;
    const int q0   = qi * 64;

    if (qi < s) return;

    // Resident Q fragments (pre-scaled at projection)
    unsigned qh[4][4], ql[4][4];
    {
        size_t rl = (size_t)(b * SEQ + q0 + 16 * w + g) * ADIM;
        size_t rh = rl + 8 * ADIM;
        #pragma unroll
        for (int kc = 0; kc < 4; kc++) {
            int off = 16 * kc + 2 * cq;
            qh[kc][0] = *(const unsigned*)(g_Qh + rl + off);
            qh[kc][1] = *(const unsigned*)(g_Qh + rh + off);
            qh[kc][2] = *(const unsigned*)(g_Qh + rl + off + 8);
            qh[kc][3] = *(const unsigned*)(g_Qh + rh + off + 8);
            ql[kc][0] = *(const unsigned*)(g_Ql + rl + off);
            ql[kc][1] = *(const unsigned*)(g_Ql + rh + off);
            ql[kc][2] = *(const unsigned*)(g_Ql + rl + off + 8);
            ql[kc][3] = *(const unsigned*)(g_Ql + rh + off + 8);
        }
    }

    float o[8][4];
    #pragma unroll
    for (int j = 0; j < 8; j++)
        #pragma unroll
        for (int i = 0; i < 4; i++) o[j][i] = 0.f;
    float m_lo = -1e30f, m_hi = -1e30f, l_lo = 0.f, l_hi = 0.f;

    for (int kb = s; kb <= qi; kb += NS) {
        __syncthreads();
        {
            const __half* sKh = g_Kh + (size_t)(b * SEQ + kb * 64) * ADIM;
            const __half* sKl = g_Kl + (size_t)(b * SEQ + kb * 64) * ADIM;
            #pragma unroll
            for (int k = 0; k < 4; k++) {
                int f = tid + 128 * k;
                int r = f >> 3, c = f & 7;
                *(uint4*)(sh + OFF_KH + r * ST + 8 * c) = *(const uint4*)(sKh + r * ADIM + 8 * c);
                *(uint4*)(sh + OFF_KL + r * ST + 8 * c) = *(const uint4*)(sKl + r * ADIM + 8 * c);
            }
        }
        {
            int kp = tid & 31;
            int a0 = (tid >> 5) * 16;
            const __half* r0h = g_Vh + (size_t)(b * SEQ + kb * 64 + 2 * kp) * ADIM + a0;
            const __half* r0l = g_Vl + (size_t)(b * SEQ + kb * 64 + 2 * kp) * ADIM + a0;
            H8 xh0 = *(const H8*)(r0h),      xh1 = *(const H8*)(r0h + 8);
            H8 yh0 = *(const H8*)(r0h + 64), yh1 = *(const H8*)(r0h + 72);
            H8 xl0 = *(const H8*)(r0l),      xl1 = *(const H8*)(r0l + 8);
            H8 yl0 = *(const H8*)(r0l + 64), yl1 = *(const H8*)(r0l + 72);
            #pragma unroll
            for (int i = 0; i < 8; i++) {
                *(__half2*)(sh + OFF_VH + (a0 + i) * ST + 2 * kp)     = __halves2half2(xh0.h[i], yh0.h[i]);
                *(__half2*)(sh + OFF_VH + (a0 + 8 + i) * ST + 2 * kp) = __halves2half2(xh1.h[i], yh1.h[i]);
                *(__half2*)(sh + OFF_VL + (a0 + i) * ST + 2 * kp)     = __halves2half2(xl0.h[i], yl0.h[i]);
                *(__half2*)(sh + OFF_VL + (a0 + 8 + i) * ST + 2 * kp) = __halves2half2(xl1.h[i], yl1.h[i]);
            }
        }
        __syncthreads();

        // ---- S = Q K^T
        float sreg[8][4];
        #pragma unroll
        for (int j = 0; j < 8; j++)
            #pragma unroll
            for (int i = 0; i < 4; i++) sreg[j][i] = 0.f;

        const unsigned* Kh32 = (const unsigned*)(sh + OFF_KH);
        const unsigned* Kl32 = (const unsigned*)(sh + OFF_KL);
        #pragma unroll
        for (int kc = 0; kc < 4; kc++) {
            #pragma unroll
            for (int j = 0; j < 8; j++) {
                int bb = (8 * j + g) * SW + 8 * kc + cq;
                unsigned bh[2] = { Kh32[bb], Kh32[bb + 4] };
                unsigned bl[2] = { Kl32[bb], Kl32[bb + 4] };
                mma16816(sreg[j], qh[kc], bh);
                mma16816(sreg[j], qh[kc], bl);
                mma16816(sreg[j], ql[kc], bh);
            }
        }

        if (kb == qi) {
            int r_lo = 16 * w + g, r_hi = r_lo + 8;
            #pragma unroll
            for (int j = 0; j < 8; j++) {
                int c0 = 8 * j + 2 * cq;
                if (c0     > r_lo) sreg[j][0] = -1e30f;
                if (c0 + 1 > r_lo) sreg[j][1] = -1e30f;
                if (c0     > r_hi) sreg[j][2] = -1e30f;
                if (c0 + 1 > r_hi) sreg[j][3] = -1e30f;
            }
        }

        // ---- online softmax
        float mx0 = -1e30f, mx1 = -1e30f;
        #pragma unroll
        for (int j = 0; j < 8; j++) {
            mx0 = fmaxf(mx0, fmaxf(sreg[j][0], sreg[j][1]));
            mx1 = fmaxf(mx1, fmaxf(sreg[j][2], sreg[j][3]));
        }
        mx0 = fmaxf(mx0, __shfl_xor_sync(0xffffffffu, mx0, 1));
        mx0 = fmaxf(mx0, __shfl_xor_sync(0xffffffffu, mx0, 2));
        mx1 = fmaxf(mx1, __shfl_xor_sync(0xffffffffu, mx1, 1));
        mx1 = fmaxf(mx1, __shfl_xor_sync(0xffffffffu, mx1, 2));
        float mn0 = fmaxf(m_lo, mx0), mn1 = fmaxf(m_hi, mx1);
        float sc0 = __expf(m_lo - mn0), sc1 = __expf(m_hi - mn1);
        m_lo = mn0; m_hi = mn1;
        float su0 = 0.f, su1 = 0.f;
        #pragma unroll
        for (int j = 0; j < 8; j++) {
            sreg[j][0] = __expf(sreg[j][0] - mn0);
            sreg[j][1] = __expf(sreg[j][1] - mn0);
            sreg[j][2] = __expf(sreg[j][2] - mn1);
            sreg[j][3] = __expf(sreg[j][3] - mn1);
            su0 += sreg[j][0] + sreg[j][1];
            su1 += sreg[j][2] + sreg[j][3];
        }
        su0 += __shfl_xor_sync(0xffffffffu, su0, 1);
        su0 += __shfl_xor_sync(0xffffffffu, su0, 2);
        su1 += __shfl_xor_sync(0xffffffffu, su1, 1);
        su1 += __shfl_xor_sync(0xffffffffu, su1, 2);
        l_lo = l_lo * sc0 + su0;
        l_hi = l_hi * sc1 + su1;
        #pragma unroll
        for (int j = 0; j < 8; j++) {
            o[j][0] *= sc0; o[j][1] *= sc0;
            o[j][2] *= sc1; o[j][3] *= sc1;
        }

        // ---- O += P V, packing P per k-chunk (only 8 extra regs live)
        const unsigned* Vh32 = (const unsigned*)(sh + OFF_VH);
        const unsigned* Vl32 = (const unsigned*)(sh + OFF_VL);
        #pragma unroll
        for (int kc = 0; kc < 4; kc++) {
            unsigned ph[4], pl[4];
            split2(sreg[2 * kc][0],     sreg[2 * kc][1],     ph[0], pl[0]);
            split2(sreg[2 * kc][2],     sreg[2 * kc][3],     ph[1], pl[1]);
            split2(sreg[2 * kc + 1][0], sreg[2 * kc + 1][1], ph[2], pl[2]);
            split2(sreg[2 * kc + 1][2], sreg[2 * kc + 1][3], ph[3], pl[3]);
            #pragma unroll
            for (int j = 0; j < 8; j++) {
                int bb = (8 * j + g) * SW + 8 * kc + cq;
                unsigned bh[2] = { Vh32[bb], Vh32[bb + 4] };
                unsigned bl[2] = { Vl32[bb], Vl32[bb + 4] };
                mma16816(o[j], ph, bh);
                mma16816(o[j], ph, bl);
                mma16816(o[j], pl, bh);
            }
        }
    }

    // ---- epilogue: write unnormalized partial O + (m, l)
    const int row_lo = q0 + 16 * w + g;
    const int row_hi = row_lo + 8;
    const size_t sb  = (size_t)(b * NS + s) * SEQ;
    #pragma unroll
    for (int j = 0; j < 8; j++) {
        int col = 8 * j + 2 * cq;
        *(float2*)(g_Om + (sb + row_lo) * ADIM + col) = make_float2(o[j][0], o[j][1]);
        *(float2*)(g_Om + (sb + row_hi) * ADIM + col) = make_float2(o[j][2], o[j][3]);
    }
    if (cq == 0) {
        g_m[sb + row_lo] = m_lo;  g_l[sb + row_lo] = l_lo;
        g_m[sb + row_hi] = m_hi;  g_l[sb + row_hi] = l_hi;
    }
}

// ---------------------------------------------------------------------------
// Combine split-KV partials.
// ---------------------------------------------------------------------------
__global__ __launch_bounds__(128)
void combine_kernel(float* __restrict__ out)
{
    const int tid = threadIdx.x;
    const int row = blockIdx.x * 8 + (tid >> 4);
    const int b   = blockIdx.y;
    const int c0  = (tid & 15) * 4;
    const int qi  = row >> 6;
    const int ns  = (qi + 1 < NS) ? (qi + 1) : NS;

    float m = -1e30f;
    #pragma unroll
    for (int s = 0; s < NS; s++)
        if (s < ns) m = fmaxf(m, g_m[(size_t)(b * NS + s) * SEQ + row]);

    float l = 0.f;
    float4 acc = make_float4(0.f, 0.f, 0.f, 0.f);
    #pragma unroll
    for (int s = 0; s < NS; s++) {
        if (s >= ns) break;
        size_t sb = (size_t)(b * NS + s) * SEQ + row;
        float wgt = __expf(g_m[sb] - m);
        l += g_l[sb] * wgt;
        float4 v = *(const float4*)(g_Om + sb * ADIM + c0);
        acc.x += v.x * wgt; acc.y += v.y * wgt;
        acc.z += v.z * wgt; acc.w += v.w * wgt;
    }
    float inv = 1.f / l;
    float4 r;
    r.x = rintf(acc.x * inv * 1e4f) * 1e-4f;
    r.y = rintf(acc.y * inv * 1e4f) * 1e-4f;
    r.z = rintf(acc.z * inv * 1e4f) * 1e-4f;
    r.w = rintf(acc.w * inv * 1e4f) * 1e-4f;
    *(float4*)(out + ((size_t)b * SEQ + row) * ADIM + c0) = r;
}

extern "C" void kernel_launch(void* const* d_in, const int* in_sizes, int n_in,
                              void* d_out, int out_size)
{
    const float* x  = (const float*)d_in[0];
    const float* wk = (const float*)d_in[1];
    const float* wq = (const float*)d_in[2];
    const float* wv = (const float*)d_in[3];
    float* out = (float*)d_out;

    qkv_proj<<<(NB * SEQ) / 64, 256>>>(x, wk, wq, wv);

    int smem = SMEM_HALVES * (int)sizeof(__half);  // 36864 B
    cudaFuncSetAttribute(attn_kernel, cudaFuncAttributeMaxDynamicSharedMemorySize, smem);
    attn_kernel<<<dim3((SEQ / 64) * NS, NB), 128, smem>>>();

    combine_kernel<<<dim3(SEQ / 8, NB), 128>>>(out);
}

// round 7
// speedup vs baseline: 1.7715x; 1.0270x over previous
#include <cuda_runtime.h>
#include <cuda_fp16.h>
#include <math.h>

#define NB   4
#define SEQ  4096
#define EDIM 1024
#define ADIM 64
#define NS   8      // KV splits per q-tile

// Projected Q,K,V stored as split fp16 planes (hi + lo), [B*S, A] each.
__device__ __half g_Qh[NB * SEQ * ADIM];
__device__ __half g_Ql[NB * SEQ * ADIM];
__device__ __half g_Kh[NB * SEQ * ADIM];
__device__ __half g_Kl[NB * SEQ * ADIM];
__device__ __half g_Vh[NB * SEQ * ADIM];
__device__ __half g_Vl[NB * SEQ * ADIM];

// Split-KV partial results: O (unnormalized), row max m, row sum l.
__device__ float g_Om[NB * NS * SEQ * ADIM];   // 33.6 MB
__device__ float g_m [NB * NS * SEQ];
__device__ float g_l [NB * NS * SEQ];

// m16n8k16 f16 MMA, f32 accumulate, in-place C.
__device__ __forceinline__ void mma16816(float d[4], const unsigned a[4], const unsigned b[2])
{
    asm volatile(
        "mma.sync.aligned.m16n8k16.row.col.f32.f16.f16.f32 "
        "{%0,%1,%2,%3}, {%4,%5,%6,%7}, {%8,%9}, {%0,%1,%2,%3};\n"
        : "+f"(d[0]), "+f"(d[1]), "+f"(d[2]), "+f"(d[3])
        : "r"(a[0]), "r"(a[1]), "r"(a[2]), "r"(a[3]), "r"(b[0]), "r"(b[1]));
}

__device__ __forceinline__ void split1(float v, __half& h, __half& l)
{
    h = __float2half_rn(v);
    l = __float2half_rn(v - __half2float(h));
}

// Split a float pair into packed hi/lo half2 words.
__device__ __forceinline__ void split2(float a, float b, unsigned& hi, unsigned& lo)
{
    __half2 h = __floats2half2_rn(a, b);
    float2 hf = __half22float2(h);
    __half2 l = __floats2half2_rn(a - hf.x, b - hf.y);
    hi = *(unsigned*)&h;
    lo = *(unsigned*)&l;
}

// 16-byte async copy global -> shared (cp.async.cg).
__device__ __forceinline__ void cp16(void* smem_dst, const void* gsrc)
{
    unsigned sa = (unsigned)__cvta_generic_to_shared(smem_dst);
    asm volatile("cp.async.cg.shared.global [%0], [%1], 16;\n" :: "r"(sa), "l"(gsrc));
}

struct alignas(16) H8 { __half h[8]; };

// ---------------------------------------------------------------------------
// QKV projection, cp.async software-pipelined.
// Raw fp32 chunks stream into double-buffered smem; split + MMA on buffer i
// overlaps the async fill of buffer i+1.
// Dynamic smem layout (bytes):
//   Xraw[2][64*32]  f32 : 0      .. 16384
//   Wraw[2][192*32] f32 : 16384  .. 65536
//   Xh [64*40]  h16     : 65536  .. 70656
//   Xl [64*40]  h16     : 70656  .. 75776
//   Wh [192*40] h16     : 75776  .. 91136
//   Wl [192*40] h16     : 91136  .. 106496
// ---------------------------------------------------------------------------
#define QP_SMEM 106496

__global__ __launch_bounds__(256, 2)
void qkv_proj(const float* __restrict__ x,
              const float* __restrict__ wk,
              const float* __restrict__ wq,
              const float* __restrict__ wv)
{
    extern __shared__ __align__(16) char qsm[];
    float*  Xraw = (float*)qsm;                    // [2][2048]
    float*  Wraw = (float*)(qsm + 16384);          // [2][6144]
    __half* Xh   = (__half*)(qsm + 65536);
    __half* Xl   = (__half*)(qsm + 70656);
    __half* Wh   = (__half*)(qsm + 75776);
    __half* Wl   = (__half*)(qsm + 91136);

    const int tid  = threadIdx.x;
    const int warp = tid >> 5;
    const int lane = tid & 31;
    const int g    = lane >> 2;
    const int cq   = lane & 3;
    const int rg   = warp >> 1;
    const int cg   = warp & 1;
    const int rows0 = blockIdx.x * 64;

    // Per-thread copy indices (same for every chunk)
    const int xr  = tid >> 3;          // 0..31  (two rows: xr, xr+32)
    const int xc  = (tid & 7) * 4;     // float offset within 32-wide chunk
    const int wr0 = tid >> 3;          // W rows wr0 + 32*k, k=0..5

    float acc[12][4];
    #pragma unroll
    for (int j = 0; j < 12; j++)
        #pragma unroll
        for (int i = 0; i < 4; i++) acc[j][i] = 0.f;

    // ---- issue chunk 0
    {
        const int e0 = 0;
        cp16(Xraw + xr * 32 + xc,        x + (size_t)(rows0 + xr) * EDIM + e0 + xc);
        cp16(Xraw + (xr + 32) * 32 + xc, x + (size_t)(rows0 + xr + 32) * EDIM + e0 + xc);
        #pragma unroll
        for (int k = 0; k < 6; k++) {
            int r = wr0 + 32 * k;
            const float* src = (r < 64)  ? wk + (size_t)r * EDIM
                             : (r < 128) ? wq + (size_t)(r - 64) * EDIM
                                         : wv + (size_t)(r - 128) * EDIM;
            cp16(Wraw + r * 32 + xc, src + e0 + xc);
        }
        asm volatile("cp.async.commit_group;\n" ::: "memory");
    }

    for (int it = 0; it < 32; it++) {
        const int buf  = it & 1;
        float* Xb = Xraw + buf * 2048;
        float* Wb = Wraw + buf * 6144;

        if (it + 1 < 32) {
            const int nbuf = (it + 1) & 1;
            const int e0   = (it + 1) * 32;
            float* Xn = Xraw + nbuf * 2048;
            float* Wn = Wraw + nbuf * 6144;
            cp16(Xn + xr * 32 + xc,        x + (size_t)(rows0 + xr) * EDIM + e0 + xc);
            cp16(Xn + (xr + 32) * 32 + xc, x + (size_t)(rows0 + xr + 32) * EDIM + e0 + xc);
            #pragma unroll
            for (int k = 0; k < 6; k++) {
                int r = wr0 + 32 * k;
                const float* src = (r < 64)  ? wk + (size_t)r * EDIM
                                 : (r < 128) ? wq + (size_t)(r - 64) * EDIM
                                             : wv + (size_t)(r - 128) * EDIM;
                cp16(Wn + r * 32 + xc, src + e0 + xc);
            }
            asm volatile("cp.async.commit_group;\n" ::: "memory");
            asm volatile("cp.async.wait_group 1;\n" ::: "memory");
        } else {
            asm volatile("cp.async.wait_group 0;\n" ::: "memory");
        }
        __syncthreads();   // chunk `it` resident; also orders prev MMA vs split below

        // ---- split raw fp32 -> fp16 hi/lo planes
        #pragma unroll
        for (int k = 0; k < 2; k++) {
            int r = xr + 32 * k;
            float4 v = *(const float4*)(Xb + r * 32 + xc);
            __half h[4], l[4];
            split1(v.x, h[0], l[0]); split1(v.y, h[1], l[1]);
            split1(v.z, h[2], l[2]); split1(v.w, h[3], l[3]);
            *(uint2*)(Xh + r * 40 + xc) = *(uint2*)h;
            *(uint2*)(Xl + r * 40 + xc) = *(uint2*)l;
        }
        #pragma unroll
        for (int k = 0; k < 6; k++) {
            int r = wr0 + 32 * k;
            float4 v = *(const float4*)(Wb + r * 32 + xc);
            __half h[4], l[4];
            split1(v.x, h[0], l[0]); split1(v.y, h[1], l[1]);
            split1(v.z, h[2], l[2]); split1(v.w, h[3], l[3]);
            *(uint2*)(Wh + r * 40 + xc) = *(uint2*)h;
            *(uint2*)(Wl + r * 40 + xc) = *(uint2*)l;
        }
        __syncthreads();

        // ---- MMAs on split planes
        const unsigned* Xh32 = (const unsigned*)Xh;
        const unsigned* Xl32 = (const unsigned*)Xl;
        const unsigned* Wh32 = (const unsigned*)Wh;
        const unsigned* Wl32 = (const unsigned*)Wl;

        #pragma unroll
        for (int kc = 0; kc < 2; kc++) {
            int ab = (16 * rg + g) * 20 + 8 * kc + cq;
            unsigned ah[4] = { Xh32[ab], Xh32[ab + 160], Xh32[ab + 4], Xh32[ab + 164] };
            unsigned al[4] = { Xl32[ab], Xl32[ab + 160], Xl32[ab + 4], Xl32[ab + 164] };
            #pragma unroll
            for (int j = 0; j < 12; j++) {
                int n0 = cg * 96 + 8 * j;
                int bb = (n0 + g) * 20 + 8 * kc + cq;
                unsigned bh[2] = { Wh32[bb], Wh32[bb + 4] };
                unsigned bl[2] = { Wl32[bb], Wl32[bb + 4] };
                mma16816(acc[j], ah, bh);
                mma16816(acc[j], ah, bl);
                mma16816(acc[j], al, bh);
            }
        }
    }

    const int row_lo = rows0 + 16 * rg + g;
    const int row_hi = row_lo + 8;
    #pragma unroll
    for (int j = 0; j < 12; j++) {
        int colg = cg * 96 + 8 * j + 2 * cq;
        __half *dh, *dl;
        float sc = 1.f;
        int cl;
        if (colg < 64)       { dh = g_Kh; dl = g_Kl; cl = colg; }
        else if (colg < 128) { dh = g_Qh; dl = g_Ql; cl = colg - 64; sc = 0.125f; }
        else                 { dh = g_Vh; dl = g_Vl; cl = colg - 128; }

        unsigned h2, l2;
        split2(acc[j][0] * sc, acc[j][1] * sc, h2, l2);
        *(unsigned*)(dh + (size_t)row_lo * ADIM + cl) = h2;
        *(unsigned*)(dl + (size_t)row_lo * ADIM + cl) = l2;
        split2(acc[j][2] * sc, acc[j][3] * sc, h2, l2);
        *(unsigned*)(dh + (size_t)row_hi * ADIM + cl) = h2;
        *(unsigned*)(dl + (size_t)row_hi * ADIM + cl) = l2;
    }
}

// ---------------------------------------------------------------------------
// Causal flash attention, split-KV (NS=8). Unchanged from R5.
// ---------------------------------------------------------------------------
#define ST 72
#define SW 36
#define OFF_KH 0
#define OFF_KL 4608
#define OFF_VH 9216
#define OFF_VL 13824
#define SMEM_HALVES 18432

__global__ __launch_bounds__(128, 3)
void attn_kernel()
{
    extern __shared__ __align__(16) __half sh[];

    const int tid  = threadIdx.x;
    const int w    = tid >> 5;
    const int lane = tid & 31;
    const int g    = lane >> 2;
    const int cq   = lane & 3;
    const int bx   = blockIdx.x;
    const int s    = bx & (NS - 1);
    const int qi   = (SEQ / 64 - 1) - (bx >> 3);   // heavy q-tiles first
    const int b    = blockIdx.y;
    const int q0   = qi * 64;

    if (qi < s) return;

    unsigned qh[4][4], ql[4][4];
    {
        size_t rl = (size_t)(b * SEQ + q0 + 16 * w + g) * ADIM;
        size_t rh = rl + 8 * ADIM;
        #pragma unroll
        for (int kc = 0; kc < 4; kc++) {
            int off = 16 * kc + 2 * cq;
            qh[kc][0] = *(const unsigned*)(g_Qh + rl + off);
            qh[kc][1] = *(const unsigned*)(g_Qh + rh + off);
            qh[kc][2] = *(const unsigned*)(g_Qh + rl + off + 8);
            qh[kc][3] = *(const unsigned*)(g_Qh + rh + off + 8);
            ql[kc][0] = *(const unsigned*)(g_Ql + rl + off);
            ql[kc][1] = *(const unsigned*)(g_Ql + rh + off);
            ql[kc][2] = *(const unsigned*)(g_Ql + rl + off + 8);
            ql[kc][3] = *(const unsigned*)(g_Ql + rh + off + 8);
        }
    }

    float o[8][4];
    #pragma unroll
    for (int j = 0; j < 8; j++)
        #pragma unroll
        for (int i = 0; i < 4; i++) o[j][i] = 0.f;
    float m_lo = -1e30f, m_hi = -1e30f, l_lo = 0.f, l_hi = 0.f;

    for (int kb = s; kb <= qi; kb += NS) {
        __syncthreads();
        {
            const __half* sKh = g_Kh + (size_t)(b * SEQ + kb * 64) * ADIM;
            const __half* sKl = g_Kl + (size_t)(b * SEQ + kb * 64) * ADIM;
            #pragma unroll
            for (int k = 0; k < 4; k++) {
                int f = tid + 128 * k;
                int r = f >> 3, c = f & 7;
                *(uint4*)(sh + OFF_KH + r * ST + 8 * c) = *(const uint4*)(sKh + r * ADIM + 8 * c);
                *(uint4*)(sh + OFF_KL + r * ST + 8 * c) = *(const uint4*)(sKl + r * ADIM + 8 * c);
            }
        }
        {
            int kp = tid & 31;
            int a0 = (tid >> 5) * 16;
            const __half* r0h = g_Vh + (size_t)(b * SEQ + kb * 64 + 2 * kp) * ADIM + a0;
            const __half* r0l = g_Vl + (size_t)(b * SEQ + kb * 64 + 2 * kp) * ADIM + a0;
            H8 xh0 = *(const H8*)(r0h),      xh1 = *(const H8*)(r0h + 8);
            H8 yh0 = *(const H8*)(r0h + 64), yh1 = *(const H8*)(r0h + 72);
            H8 xl0 = *(const H8*)(r0l),      xl1 = *(const H8*)(r0l + 8);
            H8 yl0 = *(const H8*)(r0l + 64), yl1 = *(const H8*)(r0l + 72);
            #pragma unroll
            for (int i = 0; i < 8; i++) {
                *(__half2*)(sh + OFF_VH + (a0 + i) * ST + 2 * kp)     = __halves2half2(xh0.h[i], yh0.h[i]);
                *(__half2*)(sh + OFF_VH + (a0 + 8 + i) * ST + 2 * kp) = __halves2half2(xh1.h[i], yh1.h[i]);
                *(__half2*)(sh + OFF_VL + (a0 + i) * ST + 2 * kp)     = __halves2half2(xl0.h[i], yl0.h[i]);
                *(__half2*)(sh + OFF_VL + (a0 + 8 + i) * ST + 2 * kp) = __halves2half2(xl1.h[i], yl1.h[i]);
            }
        }
        __syncthreads();

        float sreg[8][4];
        #pragma unroll
        for (int j = 0; j < 8; j++)
            #pragma unroll
            for (int i = 0; i < 4; i++) sreg[j][i] = 0.f;

        const unsigned* Kh32 = (const unsigned*)(sh + OFF_KH);
        const unsigned* Kl32 = (const unsigned*)(sh + OFF_KL);
        #pragma unroll
        for (int kc = 0; kc < 4; kc++) {
            #pragma unroll
            for (int j = 0; j < 8; j++) {
                int bb = (8 * j + g) * SW + 8 * kc + cq;
                unsigned bh[2] = { Kh32[bb], Kh32[bb + 4] };
                unsigned bl[2] = { Kl32[bb], Kl32[bb + 4] };
                mma16816(sreg[j], qh[kc], bh);
                mma16816(sreg[j], qh[kc], bl);
                mma16816(sreg[j], ql[kc], bh);
            }
        }

        if (kb == qi) {
            int r_lo = 16 * w + g, r_hi = r_lo + 8;
            #pragma unroll
            for (int j = 0; j < 8; j++) {
                int c0 = 8 * j + 2 * cq;
                if (c0     > r_lo) sreg[j][0] = -1e30f;
                if (c0 + 1 > r_lo) sreg[j][1] = -1e30f;
                if (c0     > r_hi) sreg[j][2] = -1e30f;
                if (c0 + 1 > r_hi) sreg[j][3] = -1e30f;
            }
        }

        float mx0 = -1e30f, mx1 = -1e30f;
        #pragma unroll
        for (int j = 0; j < 8; j++) {
            mx0 = fmaxf(mx0, fmaxf(sreg[j][0], sreg[j][1]));
            mx1 = fmaxf(mx1, fmaxf(sreg[j][2], sreg[j][3]));
        }
        mx0 = fmaxf(mx0, __shfl_xor_sync(0xffffffffu, mx0, 1));
        mx0 = fmaxf(mx0, __shfl_xor_sync(0xffffffffu, mx0, 2));
        mx1 = fmaxf(mx1, __shfl_xor_sync(0xffffffffu, mx1, 1));
        mx1 = fmaxf(mx1, __shfl_xor_sync(0xffffffffu, mx1, 2));
        float mn0 = fmaxf(m_lo, mx0), mn1 = fmaxf(m_hi, mx1);
        float sc0 = __expf(m_lo - mn0), sc1 = __expf(m_hi - mn1);
        m_lo = mn0; m_hi = mn1;
        float su0 = 0.f, su1 = 0.f;
        #pragma unroll
        for (int j = 0; j < 8; j++) {
            sreg[j][0] = __expf(sreg[j][0] - mn0);
            sreg[j][1] = __expf(sreg[j][1] - mn0);
            sreg[j][2] = __expf(sreg[j][2] - mn1);
            sreg[j][3] = __expf(sreg[j][3] - mn1);
            su0 += sreg[j][0] + sreg[j][1];
            su1 += sreg[j][2] + sreg[j][3];
        }
        su0 += __shfl_xor_sync(0xffffffffu, su0, 1);
        su0 += __shfl_xor_sync(0xffffffffu, su0, 2);
        su1 += __shfl_xor_sync(0xffffffffu, su1, 1);
        su1 += __shfl_xor_sync(0xffffffffu, su1, 2);
        l_lo = l_lo * sc0 + su0;
        l_hi = l_hi * sc1 + su1;
        #pragma unroll
        for (int j = 0; j < 8; j++) {
            o[j][0] *= sc0; o[j][1] *= sc0;
            o[j][2] *= sc1; o[j][3] *= sc1;
        }

        const unsigned* Vh32 = (const unsigned*)(sh + OFF_VH);
        const unsigned* Vl32 = (const unsigned*)(sh + OFF_VL);
        #pragma unroll
        for (int kc = 0; kc < 4; kc++) {
            unsigned ph[4], pl[4];
            split2(sreg[2 * kc][0],     sreg[2 * kc][1],     ph[0], pl[0]);
            split2(sreg[2 * kc][2],     sreg[2 * kc][3],     ph[1], pl[1]);
            split2(sreg[2 * kc + 1][0], sreg[2 * kc + 1][1], ph[2], pl[2]);
            split2(sreg[2 * kc + 1][2], sreg[2 * kc + 1][3], ph[3], pl[3]);
            #pragma unroll
            for (int j = 0; j < 8; j++) {
                int bb = (8 * j + g) * SW + 8 * kc + cq;
                unsigned bh[2] = { Vh32[bb], Vh32[bb + 4] };
                unsigned bl[2] = { Vl32[bb], Vl32[bb + 4] };
                mma16816(o[j], ph, bh);
                mma16816(o[j], ph, bl);
                mma16816(o[j], pl, bh);
            }
        }
    }

    const int row_lo = q0 + 16 * w + g;
    const int row_hi = row_lo + 8;
    const size_t sb  = (size_t)(b * NS + s) * SEQ;
    #pragma unroll
    for (int j = 0; j < 8; j++) {
        int col = 8 * j + 2 * cq;
        *(float2*)(g_Om + (sb + row_lo) * ADIM + col) = make_float2(o[j][0], o[j][1]);
        *(float2*)(g_Om + (sb + row_hi) * ADIM + col) = make_float2(o[j][2], o[j][3]);
    }
    if (cq == 0) {
        g_m[sb + row_lo] = m_lo;  g_l[sb + row_lo] = l_lo;
        g_m[sb + row_hi] = m_hi;  g_l[sb + row_hi] = l_hi;
    }
}

// ---------------------------------------------------------------------------
// Combine split-KV partials.
// ---------------------------------------------------------------------------
__global__ __launch_bounds__(128)
void combine_kernel(float* __restrict__ out)
{
    const int tid = threadIdx.x;
    const int row = blockIdx.x * 8 + (tid >> 4);
    const int b   = blockIdx.y;
    const int c0  = (tid & 15) * 4;
    const int qi  = row >> 6;
    const int ns  = (qi + 1 < NS) ? (qi + 1) : NS;

    float m = -1e30f;
    #pragma unroll
    for (int s = 0; s < NS; s++)
        if (s < ns) m = fmaxf(m, g_m[(size_t)(b * NS + s) * SEQ + row]);

    float l = 0.f;
    float4 acc = make_float4(0.f, 0.f, 0.f, 0.f);
    #pragma unroll
    for (int s = 0; s < NS; s++) {
        if (s >= ns) break;
        size_t sb = (size_t)(b * NS + s) * SEQ + row;
        float wgt = __expf(g_m[sb] - m);
        l += g_l[sb] * wgt;
        float4 v = *(const float4*)(g_Om + sb * ADIM + c0);
        acc.x += v.x * wgt; acc.y += v.y * wgt;
        acc.z += v.z * wgt; acc.w += v.w * wgt;
    }
    float inv = 1.f / l;
    float4 r;
    r.x = rintf(acc.x * inv * 1e4f) * 1e-4f;
    r.y = rintf(acc.y * inv * 1e4f) * 1e-4f;
    r.z = rintf(acc.z * inv * 1e4f) * 1e-4f;
    r.w = rintf(acc.w * inv * 1e4f) * 1e-4f;
    *(float4*)(out + ((size_t)b * SEQ + row) * ADIM + c0) = r;
}

extern "C" void kernel_launch(void* const* d_in, const int* in_sizes, int n_in,
                              void* d_out, int out_size)
{
    const float* x  = (const float*)d_in[0];
    const float* wk = (const float*)d_in[1];
    const float* wq = (const float*)d_in[2];
    const float* wv = (const float*)d_in[3];
    float* out = (float*)d_out;

    cudaFuncSetAttribute(qkv_proj, cudaFuncAttributeMaxDynamicSharedMemorySize, QP_SMEM);
    qkv_proj<<<(NB * SEQ) / 64, 256, QP_SMEM>>>(x, wk, wq, wv);

    int smem = SMEM_HALVES * (int)sizeof(__half);  // 36864 B
    cudaFuncSetAttribute(attn_kernel, cudaFuncAttributeMaxDynamicSharedMemorySize, smem);
    attn_kernel<<<dim3((SEQ / 64) * NS, NB), 128, smem>>>();

    combine_kernel<<<dim3(SEQ / 8, NB), 128>>>(out);
}

// round 8
// speedup vs baseline: 1.9972x; 1.1274x over previous
#include <cuda_runtime.h>
#include <cuda_fp16.h>
#include <math.h>

#define NB   4
#define SEQ  4096
#define EDIM 1024
#define ADIM 64
#define NS   8      // KV splits per q-tile

// Projected Q,K,V stored as split fp16 planes (hi + lo), [B*S, A] each.
__device__ __half g_Qh[NB * SEQ * ADIM];
__device__ __half g_Ql[NB * SEQ * ADIM];
__device__ __half g_Kh[NB * SEQ * ADIM];
__device__ __half g_Kl[NB * SEQ * ADIM];
__device__ __half g_Vh[NB * SEQ * ADIM];
__device__ __half g_Vl[NB * SEQ * ADIM];

// Split-KV partial results: O (unnormalized), row max m, row sum l.
__device__ float g_Om[NB * NS * SEQ * ADIM];   // 33.6 MB
__device__ float g_m [NB * NS * SEQ];
__device__ float g_l [NB * NS * SEQ];

// m16n8k16 f16 MMA, f32 accumulate, in-place C.
__device__ __forceinline__ void mma16816(float d[4], const unsigned a[4], const unsigned* b)
{
    asm volatile(
        "mma.sync.aligned.m16n8k16.row.col.f32.f16.f16.f32 "
        "{%0,%1,%2,%3}, {%4,%5,%6,%7}, {%8,%9}, {%0,%1,%2,%3};\n"
        : "+f"(d[0]), "+f"(d[1]), "+f"(d[2]), "+f"(d[3])
        : "r"(a[0]), "r"(a[1]), "r"(a[2]), "r"(a[3]), "r"(b[0]), "r"(b[1]));
}

// ldmatrix x4: 4 8x8 b16 matrices -> 4 regs/thread.
__device__ __forceinline__ void ldmx4(unsigned r[4], unsigned saddr)
{
    asm volatile(
        "ldmatrix.sync.aligned.m8n8.x4.shared.b16 {%0,%1,%2,%3}, [%4];\n"
        : "=r"(r[0]), "=r"(r[1]), "=r"(r[2]), "=r"(r[3]) : "r"(saddr));
}

__device__ __forceinline__ void split1(float v, __half& h, __half& l)
{
    h = __float2half_rn(v);
    l = __float2half_rn(v - __half2float(h));
}

__device__ __forceinline__ void split2(float a, float b, unsigned& hi, unsigned& lo)
{
    __half2 h = __floats2half2_rn(a, b);
    float2 hf = __half22float2(h);
    __half2 l = __floats2half2_rn(a - hf.x, b - hf.y);
    hi = *(unsigned*)&h;
    lo = *(unsigned*)&l;
}

// 16-byte async copy global -> shared (cp.async.cg).
__device__ __forceinline__ void cp16(void* smem_dst, const void* gsrc)
{
    unsigned sa = (unsigned)__cvta_generic_to_shared(smem_dst);
    asm volatile("cp.async.cg.shared.global [%0], [%1], 16;\n" :: "r"(sa), "l"(gsrc));
}

struct alignas(16) H8 { __half h[8]; };

// ---------------------------------------------------------------------------
// QKV projection, cp.async pipelined, ldmatrix fragment loads.
// ---------------------------------------------------------------------------
#define QP_SMEM 106496

__global__ __launch_bounds__(256, 2)
void qkv_proj(const float* __restrict__ x,
              const float* __restrict__ wk,
              const float* __restrict__ wq,
              const float* __restrict__ wv)
{
    extern __shared__ __align__(16) char qsm[];
    float*  Xraw = (float*)qsm;                    // [2][2048]
    float*  Wraw = (float*)(qsm + 16384);          // [2][6144]
    __half* Xh   = (__half*)(qsm + 65536);         // [64][40]
    __half* Xl   = (__half*)(qsm + 70656);
    __half* Wh   = (__half*)(qsm + 75776);         // [192][40]
    __half* Wl   = (__half*)(qsm + 91136);

    const int tid  = threadIdx.x;
    const int warp = tid >> 5;
    const int lane = tid & 31;
    const int g    = lane >> 2;
    const int cq   = lane & 3;
    const int li   = lane & 7;    // ldmatrix row within 8x8
    const int lm   = lane >> 3;   // ldmatrix matrix index 0..3
    const int rg   = warp >> 1;
    const int cg   = warp & 1;
    const int rows0 = blockIdx.x * 64;

    const int xr  = tid >> 3;
    const int xc  = (tid & 7) * 4;
    const int wr0 = tid >> 3;

    // ldmatrix base addresses (kc=0, t=0)
    // A (X): row = 16*rg + 8*(lm&1) + li, col halves = 8*(lm>>1); stride 40 halves
    const unsigned aXh = (unsigned)__cvta_generic_to_shared(Xh)
                       + ((16 * rg + 8 * (lm & 1) + li) * 40 + 8 * (lm >> 1)) * 2;
    const unsigned aXl = aXh + 5120;   // Xl = Xh + 64*40 halves = 5120 B
    // B (W): row = cg*96 + 8*(lm>>1) + li, col halves = 8*(lm&1); stride 40 halves
    const unsigned aWh = (unsigned)__cvta_generic_to_shared(Wh)
                       + ((cg * 96 + 8 * (lm >> 1) + li) * 40 + 8 * (lm & 1)) * 2;
    const unsigned aWl = aWh + 15360;  // Wl = Wh + 192*40 halves

    float acc[12][4];
    #pragma unroll
    for (int j = 0; j < 12; j++)
        #pragma unroll
        for (int i = 0; i < 4; i++) acc[j][i] = 0.f;

    // ---- issue chunk 0
    {
        cp16(Xraw + xr * 32 + xc,        x + (size_t)(rows0 + xr) * EDIM + xc);
        cp16(Xraw + (xr + 32) * 32 + xc, x + (size_t)(rows0 + xr + 32) * EDIM + xc);
        #pragma unroll
        for (int k = 0; k < 6; k++) {
            int r = wr0 + 32 * k;
            const float* src = (r < 64)  ? wk + (size_t)r * EDIM
                             : (r < 128) ? wq + (size_t)(r - 64) * EDIM
                                         : wv + (size_t)(r - 128) * EDIM;
            cp16(Wraw + r * 32 + xc, src + xc);
        }
        asm volatile("cp.async.commit_group;\n" ::: "memory");
    }

    for (int it = 0; it < 32; it++) {
        const int buf = it & 1;
        float* Xb = Xraw + buf * 2048;
        float* Wb = Wraw + buf * 6144;

        if (it + 1 < 32) {
            const int nbuf = (it + 1) & 1;
            const int e0   = (it + 1) * 32;
            float* Xn = Xraw + nbuf * 2048;
            float* Wn = Wraw + nbuf * 6144;
            cp16(Xn + xr * 32 + xc,        x + (size_t)(rows0 + xr) * EDIM + e0 + xc);
            cp16(Xn + (xr + 32) * 32 + xc, x + (size_t)(rows0 + xr + 32) * EDIM + e0 + xc);
            #pragma unroll
            for (int k = 0; k < 6; k++) {
                int r = wr0 + 32 * k;
                const float* src = (r < 64)  ? wk + (size_t)r * EDIM
                                 : (r < 128) ? wq + (size_t)(r - 64) * EDIM
                                             : wv + (size_t)(r - 128) * EDIM;
                cp16(Wn + r * 32 + xc, src + e0 + xc);
            }
            asm volatile("cp.async.commit_group;\n" ::: "memory");
            asm volatile("cp.async.wait_group 1;\n" ::: "memory");
        } else {
            asm volatile("cp.async.wait_group 0;\n" ::: "memory");
        }
        __syncthreads();

        // ---- split raw fp32 -> fp16 hi/lo planes
        #pragma unroll
        for (int k = 0; k < 2; k++) {
            int r = xr + 32 * k;
            float4 v = *(const float4*)(Xb + r * 32 + xc);
            __half h[4], l[4];
            split1(v.x, h[0], l[0]); split1(v.y, h[1], l[1]);
            split1(v.z, h[2], l[2]); split1(v.w, h[3], l[3]);
            *(uint2*)(Xh + r * 40 + xc) = *(uint2*)h;
            *(uint2*)(Xl + r * 40 + xc) = *(uint2*)l;
        }
        #pragma unroll
        for (int k = 0; k < 6; k++) {
            int r = wr0 + 32 * k;
            float4 v = *(const float4*)(Wb + r * 32 + xc);
            __half h[4], l[4];
            split1(v.x, h[0], l[0]); split1(v.y, h[1], l[1]);
            split1(v.z, h[2], l[2]); split1(v.w, h[3], l[3]);
            *(uint2*)(Wh + r * 40 + xc) = *(uint2*)h;
            *(uint2*)(Wl + r * 40 + xc) = *(uint2*)l;
        }
        __syncthreads();

        // ---- MMAs, ldmatrix fragment loads
        #pragma unroll
        for (int kc = 0; kc < 2; kc++) {
            unsigned ah[4], al[4];
            ldmx4(ah, aXh + kc * 32);
            ldmx4(al, aXl + kc * 32);
            #pragma unroll
            for (int t = 0; t < 6; t++) {   // j pairs (2t, 2t+1)
                unsigned bh[4], bl[4];
                ldmx4(bh, aWh + t * 1280 + kc * 32);   // 16 rows * 80 B
                ldmx4(bl, aWl + t * 1280 + kc * 32);
                mma16816(acc[2 * t],     ah, bh);
                mma16816(acc[2 * t],     ah, bl);
                mma16816(acc[2 * t],     al, bh);
                mma16816(acc[2 * t + 1], ah, bh + 2);
                mma16816(acc[2 * t + 1], ah, bl + 2);
                mma16816(acc[2 * t + 1], al, bh + 2);
            }
        }
    }

    const int row_lo = rows0 + 16 * rg + g;
    const int row_hi = row_lo + 8;
    #pragma unroll
    for (int j = 0; j < 12; j++) {
        int colg = cg * 96 + 8 * j + 2 * cq;
        __half *dh, *dl;
        float sc = 1.f;
        int cl;
        if (colg < 64)       { dh = g_Kh; dl = g_Kl; cl = colg; }
        else if (colg < 128) { dh = g_Qh; dl = g_Ql; cl = colg - 64; sc = 0.125f; }
        else                 { dh = g_Vh; dl = g_Vl; cl = colg - 128; }

        unsigned h2, l2;
        split2(acc[j][0] * sc, acc[j][1] * sc, h2, l2);
        *(unsigned*)(dh + (size_t)row_lo * ADIM + cl) = h2;
        *(unsigned*)(dl + (size_t)row_lo * ADIM + cl) = l2;
        split2(acc[j][2] * sc, acc[j][3] * sc, h2, l2);
        *(unsigned*)(dh + (size_t)row_hi * ADIM + cl) = h2;
        *(unsigned*)(dl + (size_t)row_hi * ADIM + cl) = l2;
    }
}

// ---------------------------------------------------------------------------
// Causal flash attention, split-KV (NS=8), ldmatrix K/V fragment loads.
// ---------------------------------------------------------------------------
#define ST 72
#define OFF_KH 0
#define OFF_KL 4608
#define OFF_VH 9216
#define OFF_VL 13824
#define SMEM_HALVES 18432

__global__ __launch_bounds__(128, 3)
void attn_kernel()
{
    extern __shared__ __align__(16) __half sh[];

    const int tid  = threadIdx.x;
    const int w    = tid >> 5;
    const int lane = tid & 31;
    const int g    = lane >> 2;
    const int cq   = lane & 3;
    const int li   = lane & 7;
    const int lm   = lane >> 3;
    const int bx   = blockIdx.x;
    const int s    = bx & (NS - 1);
    const int qi   = (SEQ / 64 - 1) - (bx >> 3);   // heavy q-tiles first
    const int b    = blockIdx.y;
    const int q0   = qi * 64;

    if (qi < s) return;

    // ldmatrix base addresses: row = 8*(lm>>1)+li, col halves = 8*(lm&1); stride 72
    const unsigned shu  = (unsigned)__cvta_generic_to_shared(sh);
    const unsigned lrow = ((8 * (lm >> 1) + li) * ST + 8 * (lm & 1)) * 2;
    const unsigned aKh = shu + OFF_KH * 2 + lrow;
    const unsigned aKl = shu + OFF_KL * 2 + lrow;
    const unsigned aVh = shu + OFF_VH * 2 + lrow;
    const unsigned aVl = shu + OFF_VL * 2 + lrow;

    // Resident Q fragments (pre-scaled at projection)
    unsigned qh[4][4], ql[4][4];
    {
        size_t rl = (size_t)(b * SEQ + q0 + 16 * w + g) * ADIM;
        size_t rh = rl + 8 * ADIM;
        #pragma unroll
        for (int kc = 0; kc < 4; kc++) {
            int off = 16 * kc + 2 * cq;
            qh[kc][0] = *(const unsigned*)(g_Qh + rl + off);
            qh[kc][1] = *(const unsigned*)(g_Qh + rh + off);
            qh[kc][2] = *(const unsigned*)(g_Qh + rl + off + 8);
            qh[kc][3] = *(const unsigned*)(g_Qh + rh + off + 8);
            ql[kc][0] = *(const unsigned*)(g_Ql + rl + off);
            ql[kc][1] = *(const unsigned*)(g_Ql + rh + off);
            ql[kc][2] = *(const unsigned*)(g_Ql + rl + off + 8);
            ql[kc][3] = *(const unsigned*)(g_Ql + rh + off + 8);
        }
    }

    float o[8][4];
    #pragma unroll
    for (int j = 0; j < 8; j++)
        #pragma unroll
        for (int i = 0; i < 4; i++) o[j][i] = 0.f;
    float m_lo = -1e30f, m_hi = -1e30f, l_lo = 0.f, l_hi = 0.f;

    for (int kb = s; kb <= qi; kb += NS) {
        __syncthreads();
        {
            const __half* sKh = g_Kh + (size_t)(b * SEQ + kb * 64) * ADIM;
            const __half* sKl = g_Kl + (size_t)(b * SEQ + kb * 64) * ADIM;
            #pragma unroll
            for (int k = 0; k < 4; k++) {
                int f = tid + 128 * k;
                int r = f >> 3, c = f & 7;
                *(uint4*)(sh + OFF_KH + r * ST + 8 * c) = *(const uint4*)(sKh + r * ADIM + 8 * c);
                *(uint4*)(sh + OFF_KL + r * ST + 8 * c) = *(const uint4*)(sKl + r * ADIM + 8 * c);
            }
        }
        {
            int kp = tid & 31;
            int a0 = (tid >> 5) * 16;
            const __half* r0h = g_Vh + (size_t)(b * SEQ + kb * 64 + 2 * kp) * ADIM + a0;
            const __half* r0l = g_Vl + (size_t)(b * SEQ + kb * 64 + 2 * kp) * ADIM + a0;
            H8 xh0 = *(const H8*)(r0h),      xh1 = *(const H8*)(r0h + 8);
            H8 yh0 = *(const H8*)(r0h + 64), yh1 = *(const H8*)(r0h + 72);
            H8 xl0 = *(const H8*)(r0l),      xl1 = *(const H8*)(r0l + 8);
            H8 yl0 = *(const H8*)(r0l + 64), yl1 = *(const H8*)(r0l + 72);
            #pragma unroll
            for (int i = 0; i < 8; i++) {
                *(__half2*)(sh + OFF_VH + (a0 + i) * ST + 2 * kp)     = __halves2half2(xh0.h[i], yh0.h[i]);
                *(__half2*)(sh + OFF_VH + (a0 + 8 + i) * ST + 2 * kp) = __halves2half2(xh1.h[i], yh1.h[i]);
                *(__half2*)(sh + OFF_VL + (a0 + i) * ST + 2 * kp)     = __halves2half2(xl0.h[i], yl0.h[i]);
                *(__half2*)(sh + OFF_VL + (a0 + 8 + i) * ST + 2 * kp) = __halves2half2(xl1.h[i], yl1.h[i]);
            }
        }
        __syncthreads();

        // ---- S = Q K^T  (ldmatrix B loads: j pair per x4)
        float sreg[8][4];
        #pragma unroll
        for (int j = 0; j < 8; j++)
            #pragma unroll
            for (int i = 0; i < 4; i++) sreg[j][i] = 0.f;

        #pragma unroll
        for (int kc = 0; kc < 4; kc++) {
            #pragma unroll
            for (int t = 0; t < 4; t++) {   // j pairs (2t, 2t+1)
                unsigned bh[4], bl[4];
                ldmx4(bh, aKh + t * 2304 + kc * 32);   // 16 rows * 144 B
                ldmx4(bl, aKl + t * 2304 + kc * 32);
                mma16816(sreg[2 * t],     qh[kc], bh);
                mma16816(sreg[2 * t],     qh[kc], bl);
                mma16816(sreg[2 * t],     ql[kc], bh);
                mma16816(sreg[2 * t + 1], qh[kc], bh + 2);
                mma16816(sreg[2 * t + 1], qh[kc], bl + 2);
                mma16816(sreg[2 * t + 1], ql[kc], bh + 2);
            }
        }

        if (kb == qi) {
            int r_lo = 16 * w + g, r_hi = r_lo + 8;
            #pragma unroll
            for (int j = 0; j < 8; j++) {
                int c0 = 8 * j + 2 * cq;
                if (c0     > r_lo) sreg[j][0] = -1e30f;
                if (c0 + 1 > r_lo) sreg[j][1] = -1e30f;
                if (c0     > r_hi) sreg[j][2] = -1e30f;
                if (c0 + 1 > r_hi) sreg[j][3] = -1e30f;
            }
        }

        // ---- online softmax
        float mx0 = -1e30f, mx1 = -1e30f;
        #pragma unroll
        for (int j = 0; j < 8; j++) {
            mx0 = fmaxf(mx0, fmaxf(sreg[j][0], sreg[j][1]));
            mx1 = fmaxf(mx1, fmaxf(sreg[j][2], sreg[j][3]));
        }
        mx0 = fmaxf(mx0, __shfl_xor_sync(0xffffffffu, mx0, 1));
        mx0 = fmaxf(mx0, __shfl_xor_sync(0xffffffffu, mx0, 2));
        mx1 = fmaxf(mx1, __shfl_xor_sync(0xffffffffu, mx1, 1));
        mx1 = fmaxf(mx1, __shfl_xor_sync(0xffffffffu, mx1, 2));
        float mn0 = fmaxf(m_lo, mx0), mn1 = fmaxf(m_hi, mx1);
        float sc0 = __expf(m_lo - mn0), sc1 = __expf(m_hi - mn1);
        m_lo = mn0; m_hi = mn1;
        float su0 = 0.f, su1 = 0.f;
        #pragma unroll
        for (int j = 0; j < 8; j++) {
            sreg[j][0] = __expf(sreg[j][0] - mn0);
            sreg[j][1] = __expf(sreg[j][1] - mn0);
            sreg[j][2] = __expf(sreg[j][2] - mn1);
            sreg[j][3] = __expf(sreg[j][3] - mn1);
            su0 += sreg[j][0] + sreg[j][1];
            su1 += sreg[j][2] + sreg[j][3];
        }
        su0 += __shfl_xor_sync(0xffffffffu, su0, 1);
        su0 += __shfl_xor_sync(0xffffffffu, su0, 2);
        su1 += __shfl_xor_sync(0xffffffffu, su1, 1);
        su1 += __shfl_xor_sync(0xffffffffu, su1, 2);
        l_lo = l_lo * sc0 + su0;
        l_hi = l_hi * sc1 + su1;
        #pragma unroll
        for (int j = 0; j < 8; j++) {
            o[j][0] *= sc0; o[j][1] *= sc0;
            o[j][2] *= sc1; o[j][3] *= sc1;
        }

        // ---- O += P V, packing P per k-chunk; V frags via ldmatrix
        #pragma unroll
        for (int kc = 0; kc < 4; kc++) {
            unsigned ph[4], pl[4];
            split2(sreg[2 * kc][0],     sreg[2 * kc][1],     ph[0], pl[0]);
            split2(sreg[2 * kc][2],     sreg[2 * kc][3],     ph[1], pl[1]);
            split2(sreg[2 * kc + 1][0], sreg[2 * kc + 1][1], ph[2], pl[2]);
            split2(sreg[2 * kc + 1][2], sreg[2 * kc + 1][3], ph[3], pl[3]);
            #pragma unroll
            for (int t = 0; t < 4; t++) {   // adim pairs (2t, 2t+1)
                unsigned bh[4], bl[4];
                ldmx4(bh, aVh + t * 2304 + kc * 32);
                ldmx4(bl, aVl + t * 2304 + kc * 32);
                mma16816(o[2 * t],     ph, bh);
                mma16816(o[2 * t],     ph, bl);
                mma16816(o[2 * t],     pl, bh);
                mma16816(o[2 * t + 1], ph, bh + 2);
                mma16816(o[2 * t + 1], ph, bl + 2);
                mma16816(o[2 * t + 1], pl, bh + 2);
            }
        }
    }

    // ---- epilogue: write unnormalized partial O + (m, l)
    const int row_lo = q0 + 16 * w + g;
    const int row_hi = row_lo + 8;
    const size_t sb  = (size_t)(b * NS + s) * SEQ;
    #pragma unroll
    for (int j = 0; j < 8; j++) {
        int col = 8 * j + 2 * cq;
        *(float2*)(g_Om + (sb + row_lo) * ADIM + col) = make_float2(o[j][0], o[j][1]);
        *(float2*)(g_Om + (sb + row_hi) * ADIM + col) = make_float2(o[j][2], o[j][3]);
    }
    if (cq == 0) {
        g_m[sb + row_lo] = m_lo;  g_l[sb + row_lo] = l_lo;
        g_m[sb + row_hi] = m_hi;  g_l[sb + row_hi] = l_hi;
    }
}

// ---------------------------------------------------------------------------
// Combine split-KV partials.
// ---------------------------------------------------------------------------
__global__ __launch_bounds__(128)
void combine_kernel(float* __restrict__ out)
{
    const int tid = threadIdx.x;
    const int row = blockIdx.x * 8 + (tid >> 4);
    const int b   = blockIdx.y;
    const int c0  = (tid & 15) * 4;
    const int qi  = row >> 6;
    const int ns  = (qi + 1 < NS) ? (qi + 1) : NS;

    float m = -1e30f;
    #pragma unroll
    for (int s = 0; s < NS; s++)
        if (s < ns) m = fmaxf(m, g_m[(size_t)(b * NS + s) * SEQ + row]);

    float l = 0.f;
    float4 acc = make_float4(0.f, 0.f, 0.f, 0.f);
    #pragma unroll
    for (int s = 0; s < NS; s++) {
        if (s >= ns) break;
        size_t sb = (size_t)(b * NS + s) * SEQ + row;
        float wgt = __expf(g_m[sb] - m);
        l += g_l[sb] * wgt;
        float4 v = *(const float4*)(g_Om + sb * ADIM + c0);
        acc.x += v.x * wgt; acc.y += v.y * wgt;
        acc.z += v.z * wgt; acc.w += v.w * wgt;
    }
    float inv = 1.f / l;
    float4 r;
    r.x = rintf(acc.x * inv * 1e4f) * 1e-4f;
    r.y = rintf(acc.y * inv * 1e4f) * 1e-4f;
    r.z = rintf(acc.z * inv * 1e4f) * 1e-4f;
    r.w = rintf(acc.w * inv * 1e4f) * 1e-4f;
    *(float4*)(out + ((size_t)b * SEQ + row) * ADIM + c0) = r;
}

extern "C" void kernel_launch(void* const* d_in, const int* in_sizes, int n_in,
                              void* d_out, int out_size)
{
    const float* x  = (const float*)d_in[0];
    const float* wk = (const float*)d_in[1];
    const float* wq = (const float*)d_in[2];
    const float* wv = (const float*)d_in[3];
    float* out = (float*)d_out;

    cudaFuncSetAttribute(qkv_proj, cudaFuncAttributeMaxDynamicSharedMemorySize, QP_SMEM);
    qkv_proj<<<(NB * SEQ) / 64, 256, QP_SMEM>>>(x, wk, wq, wv);

    int smem = SMEM_HALVES * (int)sizeof(__half);  // 36864 B
    cudaFuncSetAttribute(attn_kernel, cudaFuncAttributeMaxDynamicSharedMemorySize, smem);
    attn_kernel<<<dim3((SEQ / 64) * NS, NB), 128, smem>>>();

    combine_kernel<<<dim3(SEQ / 8, NB), 128>>>(out);
}

// round 9
// speedup vs baseline: 2.0806x; 1.0418x over previous
#include <cuda_runtime.h>
#include <cuda_fp16.h>
#include <math.h>

#define NB   4
#define SEQ  4096
#define EDIM 1024
#define ADIM 64
#define NS   8      // KV splits per q-tile

// Projected Q,K,V stored as split fp16 planes (hi + lo), [B*S, A] each.
__device__ __half g_Qh[NB * SEQ * ADIM];
__device__ __half g_Ql[NB * SEQ * ADIM];
__device__ __half g_Kh[NB * SEQ * ADIM];
__device__ __half g_Kl[NB * SEQ * ADIM];
__device__ __half g_Vh[NB * SEQ * ADIM];
__device__ __half g_Vl[NB * SEQ * ADIM];

// Split-KV partial results: O (unnormalized), row max m, row sum l.
__device__ float g_Om[NB * NS * SEQ * ADIM];   // 33.6 MB
__device__ float g_m [NB * NS * SEQ];
__device__ float g_l [NB * NS * SEQ];

// m16n8k16 f16 MMA, f32 accumulate, in-place C.
__device__ __forceinline__ void mma16816(float d[4], const unsigned a[4], const unsigned* b)
{
    asm volatile(
        "mma.sync.aligned.m16n8k16.row.col.f32.f16.f16.f32 "
        "{%0,%1,%2,%3}, {%4,%5,%6,%7}, {%8,%9}, {%0,%1,%2,%3};\n"
        : "+f"(d[0]), "+f"(d[1]), "+f"(d[2]), "+f"(d[3])
        : "r"(a[0]), "r"(a[1]), "r"(a[2]), "r"(a[3]), "r"(b[0]), "r"(b[1]));
}

// ldmatrix x4: 4 8x8 b16 matrices -> 4 regs/thread.
__device__ __forceinline__ void ldmx4(unsigned r[4], unsigned saddr)
{
    asm volatile(
        "ldmatrix.sync.aligned.m8n8.x4.shared.b16 {%0,%1,%2,%3}, [%4];\n"
        : "=r"(r[0]), "=r"(r[1]), "=r"(r[2]), "=r"(r[3]) : "r"(saddr));
}

// ldmatrix x4 transposed (for V^T fragments from row-major V).
__device__ __forceinline__ void ldmx4t(unsigned r[4], unsigned saddr)
{
    asm volatile(
        "ldmatrix.sync.aligned.m8n8.x4.trans.shared.b16 {%0,%1,%2,%3}, [%4];\n"
        : "=r"(r[0]), "=r"(r[1]), "=r"(r[2]), "=r"(r[3]) : "r"(saddr));
}

__device__ __forceinline__ void split1(float v, __half& h, __half& l)
{
    h = __float2half_rn(v);
    l = __float2half_rn(v - __half2float(h));
}

__device__ __forceinline__ void split2(float a, float b, unsigned& hi, unsigned& lo)
{
    __half2 h = __floats2half2_rn(a, b);
    float2 hf = __half22float2(h);
    __half2 l = __floats2half2_rn(a - hf.x, b - hf.y);
    hi = *(unsigned*)&h;
    lo = *(unsigned*)&l;
}

// 16-byte async copy global -> shared (cp.async.cg).
__device__ __forceinline__ void cp16(void* smem_dst, const void* gsrc)
{
    unsigned sa = (unsigned)__cvta_generic_to_shared(smem_dst);
    asm volatile("cp.async.cg.shared.global [%0], [%1], 16;\n" :: "r"(sa), "l"(gsrc));
}

// ---------------------------------------------------------------------------
// QKV projection, N-split: block = (64 X-rows, 96 of 192 output cols).
// Grid (256, 2). cp.async pipelined, ldmatrix fragment loads.
// Smem layout (bytes):
//   Xraw[2][64*32] f32 : 0     .. 16384
//   Wraw[2][96*32] f32 : 16384 .. 40960
//   Xh [64][40] h16    : 40960 .. 46080
//   Xl                 : 46080 .. 51200
//   Wh [96][40] h16    : 51200 .. 58880
//   Wl                 : 58880 .. 66560
// ---------------------------------------------------------------------------
#define QP_SMEM 66560

__global__ __launch_bounds__(256, 2)
void qkv_proj(const float* __restrict__ x,
              const float* __restrict__ wk,
              const float* __restrict__ wq,
              const float* __restrict__ wv)
{
    extern __shared__ __align__(16) char qsm[];
    float*  Xraw = (float*)qsm;                    // [2][2048]
    float*  Wraw = (float*)(qsm + 16384);          // [2][3072]
    __half* Xh   = (__half*)(qsm + 40960);         // [64][40]
    __half* Xl   = (__half*)(qsm + 46080);
    __half* Wh   = (__half*)(qsm + 51200);         // [96][40]
    __half* Wl   = (__half*)(qsm + 58880);

    const int tid  = threadIdx.x;
    const int warp = tid >> 5;
    const int lane = tid & 31;
    const int g    = lane >> 2;
    const int cq   = lane & 3;
    const int li   = lane & 7;
    const int lm   = lane >> 3;
    const int rg   = warp >> 1;          // row group 0..3
    const int cg   = warp & 1;           // col group 0..1 (48 cols each)
    const int cy   = blockIdx.y;         // which 96-col half of the 192
    const int rows0 = blockIdx.x * 64;

    // ldmatrix base addresses
    const unsigned aXh = (unsigned)__cvta_generic_to_shared(Xh)
                       + ((16 * rg + 8 * (lm & 1) + li) * 40 + 8 * (lm >> 1)) * 2;
    const unsigned aXl = aXh + 5120;               // 64*40 halves
    const unsigned aWh = (unsigned)__cvta_generic_to_shared(Wh)
                       + ((cg * 48 + 8 * (lm >> 1) + li) * 40 + 8 * (lm & 1)) * 2;
    const unsigned aWl = aWh + 7680;               // 96*40 halves

    float acc[6][4];
    #pragma unroll
    for (int j = 0; j < 6; j++)
        #pragma unroll
        for (int i = 0; i < 4; i++) acc[j][i] = 0.f;

    // ---- issue chunk 0
    #pragma unroll
    for (int k = 0; k < 2; k++) {
        int f = tid + k * 256;
        int r = f >> 3, c4 = (f & 7) * 4;
        cp16(Xraw + r * 32 + c4, x + (size_t)(rows0 + r) * EDIM + c4);
    }
    #pragma unroll
    for (int k = 0; k < 3; k++) {
        int f = tid + k * 256;
        int r = f >> 3, c4 = (f & 7) * 4;
        int rglob = cy * 96 + r;
        const float* src = (rglob < 64)  ? wk + (size_t)rglob * EDIM
                         : (rglob < 128) ? wq + (size_t)(rglob - 64) * EDIM
                                         : wv + (size_t)(rglob - 128) * EDIM;
        cp16(Wraw + r * 32 + c4, src + c4);
    }
    asm volatile("cp.async.commit_group;\n" ::: "memory");

    for (int it = 0; it < 32; it++) {
        const int buf = it & 1;
        float* Xb = Xraw + buf * 2048;
        float* Wb = Wraw + buf * 3072;

        if (it + 1 < 32) {
            const int nbuf = (it + 1) & 1;
            const int e0   = (it + 1) * 32;
            float* Xn = Xraw + nbuf * 2048;
            float* Wn = Wraw + nbuf * 3072;
            #pragma unroll
            for (int k = 0; k < 2; k++) {
                int f = tid + k * 256;
                int r = f >> 3, c4 = (f & 7) * 4;
                cp16(Xn + r * 32 + c4, x + (size_t)(rows0 + r) * EDIM + e0 + c4);
            }
            #pragma unroll
            for (int k = 0; k < 3; k++) {
                int f = tid + k * 256;
                int r = f >> 3, c4 = (f & 7) * 4;
                int rglob = cy * 96 + r;
                const float* src = (rglob < 64)  ? wk + (size_t)rglob * EDIM
                                 : (rglob < 128) ? wq + (size_t)(rglob - 64) * EDIM
                                                 : wv + (size_t)(rglob - 128) * EDIM;
                cp16(Wn + r * 32 + c4, src + e0 + c4);
            }
            asm volatile("cp.async.commit_group;\n" ::: "memory");
            asm volatile("cp.async.wait_group 1;\n" ::: "memory");
        } else {
            asm volatile("cp.async.wait_group 0;\n" ::: "memory");
        }
        __syncthreads();

        // ---- split raw fp32 -> fp16 hi/lo planes
        #pragma unroll
        for (int k = 0; k < 2; k++) {
            int f = tid + k * 256;
            int r = f >> 3, c4 = (f & 7) * 4;
            float4 v = *(const float4*)(Xb + r * 32 + c4);
            __half h[4], l[4];
            split1(v.x, h[0], l[0]); split1(v.y, h[1], l[1]);
            split1(v.z, h[2], l[2]); split1(v.w, h[3], l[3]);
            *(uint2*)(Xh + r * 40 + c4) = *(uint2*)h;
            *(uint2*)(Xl + r * 40 + c4) = *(uint2*)l;
        }
        #pragma unroll
        for (int k = 0; k < 3; k++) {
            int f = tid + k * 256;
            int r = f >> 3, c4 = (f & 7) * 4;
            float4 v = *(const float4*)(Wb + r * 32 + c4);
            __half h[4], l[4];
            split1(v.x, h[0], l[0]); split1(v.y, h[1], l[1]);
            split1(v.z, h[2], l[2]); split1(v.w, h[3], l[3]);
            *(uint2*)(Wh + r * 40 + c4) = *(uint2*)h;
            *(uint2*)(Wl + r * 40 + c4) = *(uint2*)l;
        }
        __syncthreads();

        // ---- MMAs, ldmatrix fragment loads
        #pragma unroll
        for (int kc = 0; kc < 2; kc++) {
            unsigned ah[4], al[4];
            ldmx4(ah, aXh + kc * 32);
            ldmx4(al, aXl + kc * 32);
            #pragma unroll
            for (int t = 0; t < 3; t++) {   // j pairs (2t, 2t+1)
                unsigned bh[4], bl[4];
                ldmx4(bh, aWh + t * 1280 + kc * 32);   // 16 rows * 80 B
                ldmx4(bl, aWl + t * 1280 + kc * 32);
                mma16816(acc[2 * t],     ah, bh);
                mma16816(acc[2 * t],     ah, bl);
                mma16816(acc[2 * t],     al, bh);
                mma16816(acc[2 * t + 1], ah, bh + 2);
                mma16816(acc[2 * t + 1], ah, bl + 2);
                mma16816(acc[2 * t + 1], al, bh + 2);
            }
        }
    }

    const int row_lo = rows0 + 16 * rg + g;
    const int row_hi = row_lo + 8;
    #pragma unroll
    for (int j = 0; j < 6; j++) {
        int colg = cy * 96 + cg * 48 + 8 * j + 2 * cq;
        __half *dh, *dl;
        float sc = 1.f;
        int cl;
        if (colg < 64)       { dh = g_Kh; dl = g_Kl; cl = colg; }
        else if (colg < 128) { dh = g_Qh; dl = g_Ql; cl = colg - 64; sc = 0.125f; }
        else                 { dh = g_Vh; dl = g_Vl; cl = colg - 128; }

        unsigned h2, l2;
        split2(acc[j][0] * sc, acc[j][1] * sc, h2, l2);
        *(unsigned*)(dh + (size_t)row_lo * ADIM + cl) = h2;
        *(unsigned*)(dl + (size_t)row_lo * ADIM + cl) = l2;
        split2(acc[j][2] * sc, acc[j][3] * sc, h2, l2);
        *(unsigned*)(dh + (size_t)row_hi * ADIM + cl) = h2;
        *(unsigned*)(dl + (size_t)row_hi * ADIM + cl) = l2;
    }
}

// ---------------------------------------------------------------------------
// Causal flash attention, split-KV (NS=8). K and V both stored row-major
// [key][adim]; K fragments via ldmatrix, V fragments via ldmatrix.trans.
// ---------------------------------------------------------------------------
#define ST 72
#define OFF_KH 0
#define OFF_KL 4608
#define OFF_VH 9216
#define OFF_VL 13824
#define SMEM_HALVES 18432

__global__ __launch_bounds__(128, 3)
void attn_kernel()
{
    extern __shared__ __align__(16) __half sh[];

    const int tid  = threadIdx.x;
    const int w    = tid >> 5;
    const int lane = tid & 31;
    const int g    = lane >> 2;
    const int cq   = lane & 3;
    const int li   = lane & 7;
    const int lm   = lane >> 3;
    const int bx   = blockIdx.x;
    const int s    = bx & (NS - 1);
    const int qi   = (SEQ / 64 - 1) - (bx >> 3);   // heavy q-tiles first
    const int b    = blockIdx.y;
    const int q0   = qi * 64;

    if (qi < s) return;

    const unsigned shu = (unsigned)__cvta_generic_to_shared(sh);
    // K (non-trans): row = n-block, col = k-half
    const unsigned lrowK = ((8 * (lm >> 1) + li) * ST + 8 * (lm & 1)) * 2;
    const unsigned aKh = shu + OFF_KH * 2 + lrowK;
    const unsigned aKl = shu + OFF_KL * 2 + lrowK;
    // V (trans): stored row = key (k-half from lm&1), col = adim (n-block from lm>>1)
    const unsigned lrowV = ((8 * (lm & 1) + li) * ST + 8 * (lm >> 1)) * 2;
    const unsigned aVh = shu + OFF_VH * 2 + lrowV;
    const unsigned aVl = shu + OFF_VL * 2 + lrowV;

    // Resident Q fragments (pre-scaled at projection)
    unsigned qh[4][4], ql[4][4];
    {
        size_t rl = (size_t)(b * SEQ + q0 + 16 * w + g) * ADIM;
        size_t rh = rl + 8 * ADIM;
        #pragma unroll
        for (int kc = 0; kc < 4; kc++) {
            int off = 16 * kc + 2 * cq;
            qh[kc][0] = *(const unsigned*)(g_Qh + rl + off);
            qh[kc][1] = *(const unsigned*)(g_Qh + rh + off);
            qh[kc][2] = *(const unsigned*)(g_Qh + rl + off + 8);
            qh[kc][3] = *(const unsigned*)(g_Qh + rh + off + 8);
            ql[kc][0] = *(const unsigned*)(g_Ql + rl + off);
            ql[kc][1] = *(const unsigned*)(g_Ql + rh + off);
            ql[kc][2] = *(const unsigned*)(g_Ql + rl + off + 8);
            ql[kc][3] = *(const unsigned*)(g_Ql + rh + off + 8);
        }
    }

    float o[8][4];
    #pragma unroll
    for (int j = 0; j < 8; j++)
        #pragma unroll
        for (int i = 0; i < 4; i++) o[j][i] = 0.f;
    float m_lo = -1e30f, m_hi = -1e30f, l_lo = 0.f, l_hi = 0.f;

    for (int kb = s; kb <= qi; kb += NS) {
        __syncthreads();
        {
            const __half* sKh = g_Kh + (size_t)(b * SEQ + kb * 64) * ADIM;
            const __half* sKl = g_Kl + (size_t)(b * SEQ + kb * 64) * ADIM;
            const __half* sVh = g_Vh + (size_t)(b * SEQ + kb * 64) * ADIM;
            const __half* sVl = g_Vl + (size_t)(b * SEQ + kb * 64) * ADIM;
            #pragma unroll
            for (int k = 0; k < 4; k++) {
                int f = tid + 128 * k;
                int r = f >> 3, c = f & 7;
                *(uint4*)(sh + OFF_KH + r * ST + 8 * c) = *(const uint4*)(sKh + r * ADIM + 8 * c);
                *(uint4*)(sh + OFF_KL + r * ST + 8 * c) = *(const uint4*)(sKl + r * ADIM + 8 * c);
                *(uint4*)(sh + OFF_VH + r * ST + 8 * c) = *(const uint4*)(sVh + r * ADIM + 8 * c);
                *(uint4*)(sh + OFF_VL + r * ST + 8 * c) = *(const uint4*)(sVl + r * ADIM + 8 * c);
            }
        }
        __syncthreads();

        // ---- S = Q K^T
        float sreg[8][4];
        #pragma unroll
        for (int j = 0; j < 8; j++)
            #pragma unroll
            for (int i = 0; i < 4; i++) sreg[j][i] = 0.f;

        #pragma unroll
        for (int kc = 0; kc < 4; kc++) {
            #pragma unroll
            for (int t = 0; t < 4; t++) {   // j pairs (2t, 2t+1)
                unsigned bh[4], bl[4];
                ldmx4(bh, aKh + t * 2304 + kc * 32);   // 16 rows * 144 B
                ldmx4(bl, aKl + t * 2304 + kc * 32);
                mma16816(sreg[2 * t],     qh[kc], bh);
                mma16816(sreg[2 * t],     qh[kc], bl);
                mma16816(sreg[2 * t],     ql[kc], bh);
                mma16816(sreg[2 * t + 1], qh[kc], bh + 2);
                mma16816(sreg[2 * t + 1], qh[kc], bl + 2);
                mma16816(sreg[2 * t + 1], ql[kc], bh + 2);
            }
        }

        if (kb == qi) {
            int r_lo = 16 * w + g, r_hi = r_lo + 8;
            #pragma unroll
            for (int j = 0; j < 8; j++) {
                int c0 = 8 * j + 2 * cq;
                if (c0     > r_lo) sreg[j][0] = -1e30f;
                if (c0 + 1 > r_lo) sreg[j][1] = -1e30f;
                if (c0     > r_hi) sreg[j][2] = -1e30f;
                if (c0 + 1 > r_hi) sreg[j][3] = -1e30f;
            }
        }

        // ---- online softmax
        float mx0 = -1e30f, mx1 = -1e30f;
        #pragma unroll
        for (int j = 0; j < 8; j++) {
            mx0 = fmaxf(mx0, fmaxf(sreg[j][0], sreg[j][1]));
            mx1 = fmaxf(mx1, fmaxf(sreg[j][2], sreg[j][3]));
        }
        mx0 = fmaxf(mx0, __shfl_xor_sync(0xffffffffu, mx0, 1));
        mx0 = fmaxf(mx0, __shfl_xor_sync(0xffffffffu, mx0, 2));
        mx1 = fmaxf(mx1, __shfl_xor_sync(0xffffffffu, mx1, 1));
        mx1 = fmaxf(mx1, __shfl_xor_sync(0xffffffffu, mx1, 2));
        float mn0 = fmaxf(m_lo, mx0), mn1 = fmaxf(m_hi, mx1);
        float sc0 = __expf(m_lo - mn0), sc1 = __expf(m_hi - mn1);
        m_lo = mn0; m_hi = mn1;
        float su0 = 0.f, su1 = 0.f;
        #pragma unroll
        for (int j = 0; j < 8; j++) {
            sreg[j][0] = __expf(sreg[j][0] - mn0);
            sreg[j][1] = __expf(sreg[j][1] - mn0);
            sreg[j][2] = __expf(sreg[j][2] - mn1);
            sreg[j][3] = __expf(sreg[j][3] - mn1);
            su0 += sreg[j][0] + sreg[j][1];
            su1 += sreg[j][2] + sreg[j][3];
        }
        su0 += __shfl_xor_sync(0xffffffffu, su0, 1);
        su0 += __shfl_xor_sync(0xffffffffu, su0, 2);
        su1 += __shfl_xor_sync(0xffffffffu, su1, 1);
        su1 += __shfl_xor_sync(0xffffffffu, su1, 2);
        l_lo = l_lo * sc0 + su0;
        l_hi = l_hi * sc1 + su1;
        #pragma unroll
        for (int j = 0; j < 8; j++) {
            o[j][0] *= sc0; o[j][1] *= sc0;
            o[j][2] *= sc1; o[j][3] *= sc1;
        }

        // ---- O += P V; V fragments via ldmatrix.trans from row-major V
        #pragma unroll
        for (int kc = 0; kc < 4; kc++) {
            unsigned ph[4], pl[4];
            split2(sreg[2 * kc][0],     sreg[2 * kc][1],     ph[0], pl[0]);
            split2(sreg[2 * kc][2],     sreg[2 * kc][3],     ph[1], pl[1]);
            split2(sreg[2 * kc + 1][0], sreg[2 * kc + 1][1], ph[2], pl[2]);
            split2(sreg[2 * kc + 1][2], sreg[2 * kc + 1][3], ph[3], pl[3]);
            #pragma unroll
            for (int t = 0; t < 4; t++) {   // adim pairs (2t, 2t+1)
                unsigned bh[4], bl[4];
                ldmx4t(bh, aVh + kc * 2304 + t * 32);  // rows = key chunk, cols = adim pair
                ldmx4t(bl, aVl + kc * 2304 + t * 32);
                mma16816(o[2 * t],     ph, bh);
                mma16816(o[2 * t],     ph, bl);
                mma16816(o[2 * t],     pl, bh);
                mma16816(o[2 * t + 1], ph, bh + 2);
                mma16816(o[2 * t + 1], ph, bl + 2);
                mma16816(o[2 * t + 1], pl, bh + 2);
            }
        }
    }

    // ---- epilogue: write unnormalized partial O + (m, l)
    const int row_lo = q0 + 16 * w + g;
    const int row_hi = row_lo + 8;
    const size_t sb  = (size_t)(b * NS + s) * SEQ;
    #pragma unroll
    for (int j = 0; j < 8; j++) {
        int col = 8 * j + 2 * cq;
        *(float2*)(g_Om + (sb + row_lo) * ADIM + col) = make_float2(o[j][0], o[j][1]);
        *(float2*)(g_Om + (sb + row_hi) * ADIM + col) = make_float2(o[j][2], o[j][3]);
    }
    if (cq == 0) {
        g_m[sb + row_lo] = m_lo;  g_l[sb + row_lo] = l_lo;
        g_m[sb + row_hi] = m_hi;  g_l[sb + row_hi] = l_hi;
    }
}

// ---------------------------------------------------------------------------
// Combine split-KV partials.
// ---------------------------------------------------------------------------
__global__ __launch_bounds__(128)
void combine_kernel(float* __restrict__ out)
{
    const int tid = threadIdx.x;
    const int row = blockIdx.x * 8 + (tid >> 4);
    const int b   = blockIdx.y;
    const int c0  = (tid & 15) * 4;
    const int qi  = row >> 6;
    const int ns  = (qi + 1 < NS) ? (qi + 1) : NS;

    float m = -1e30f;
    #pragma unroll
    for (int s = 0; s < NS; s++)
        if (s < ns) m = fmaxf(m, g_m[(size_t)(b * NS + s) * SEQ + row]);

    float l = 0.f;
    float4 acc = make_float4(0.f, 0.f, 0.f, 0.f);
    #pragma unroll
    for (int s = 0; s < NS; s++) {
        if (s >= ns) break;
        size_t sb = (size_t)(b * NS + s) * SEQ + row;
        float wgt = __expf(g_m[sb] - m);
        l += g_l[sb] * wgt;
        float4 v = *(const float4*)(g_Om + sb * ADIM + c0);
        acc.x += v.x * wgt; acc.y += v.y * wgt;
        acc.z += v.z * wgt; acc.w += v.w * wgt;
    }
    float inv = 1.f / l;
    float4 r;
    r.x = rintf(acc.x * inv * 1e4f) * 1e-4f;
    r.y = rintf(acc.y * inv * 1e4f) * 1e-4f;
    r.z = rintf(acc.z * inv * 1e4f) * 1e-4f;
    r.w = rintf(acc.w * inv * 1e4f) * 1e-4f;
    *(float4*)(out + ((size_t)b * SEQ + row) * ADIM + c0) = r;
}

extern "C" void kernel_launch(void* const* d_in, const int* in_sizes, int n_in,
                              void* d_out, int out_size)
{
    const float* x  = (const float*)d_in[0];
    const float* wk = (const float*)d_in[1];
    const float* wq = (const float*)d_in[2];
    const float* wv = (const float*)d_in[3];
    float* out = (float*)d_out;

    cudaFuncSetAttribute(qkv_proj, cudaFuncAttributeMaxDynamicSharedMemorySize, QP_SMEM);
    qkv_proj<<<dim3(256, 2), 256, QP_SMEM>>>(x, wk, wq, wv);

    int smem = SMEM_HALVES * (int)sizeof(__half);  // 36864 B
    cudaFuncSetAttribute(attn_kernel, cudaFuncAttributeMaxDynamicSharedMemorySize, smem);
    attn_kernel<<<dim3((SEQ / 64) * NS, NB), 128, smem>>>();

    combine_kernel<<<dim3(SEQ / 8, NB), 128>>>(out);
}

// round 10
// speedup vs baseline: 2.2435x; 1.0783x over previous
#include <cuda_runtime.h>
#include <cuda_fp16.h>
#include <math.h>

#define NB   4
#define SEQ  4096
#define EDIM 1024
#define ADIM 64
#define NS   8      // KV splits per q-tile

// Projected Q,K,V stored as split fp16 planes (hi + lo), [B*S, A] each.
__device__ __half g_Qh[NB * SEQ * ADIM];
__device__ __half g_Ql[NB * SEQ * ADIM];
__device__ __half g_Kh[NB * SEQ * ADIM];
__device__ __half g_Kl[NB * SEQ * ADIM];
__device__ __half g_Vh[NB * SEQ * ADIM];
__device__ __half g_Vl[NB * SEQ * ADIM];

// Split-KV partial results: O (unnormalized), row max m, row sum l.
__device__ float g_Om[NB * NS * SEQ * ADIM];   // 33.6 MB
__device__ float g_m [NB * NS * SEQ];
__device__ float g_l [NB * NS * SEQ];

// m16n8k16 f16 MMA, f32 accumulate, in-place C.
__device__ __forceinline__ void mma16816(float d[4], const unsigned a[4], const unsigned* b)
{
    asm volatile(
        "mma.sync.aligned.m16n8k16.row.col.f32.f16.f16.f32 "
        "{%0,%1,%2,%3}, {%4,%5,%6,%7}, {%8,%9}, {%0,%1,%2,%3};\n"
        : "+f"(d[0]), "+f"(d[1]), "+f"(d[2]), "+f"(d[3])
        : "r"(a[0]), "r"(a[1]), "r"(a[2]), "r"(a[3]), "r"(b[0]), "r"(b[1]));
}

// ldmatrix x4: 4 8x8 b16 matrices -> 4 regs/thread.
__device__ __forceinline__ void ldmx4(unsigned r[4], unsigned saddr)
{
    asm volatile(
        "ldmatrix.sync.aligned.m8n8.x4.shared.b16 {%0,%1,%2,%3}, [%4];\n"
        : "=r"(r[0]), "=r"(r[1]), "=r"(r[2]), "=r"(r[3]) : "r"(saddr));
}

// ldmatrix x4 transposed (for V^T fragments from row-major V).
__device__ __forceinline__ void ldmx4t(unsigned r[4], unsigned saddr)
{
    asm volatile(
        "ldmatrix.sync.aligned.m8n8.x4.trans.shared.b16 {%0,%1,%2,%3}, [%4];\n"
        : "=r"(r[0]), "=r"(r[1]), "=r"(r[2]), "=r"(r[3]) : "r"(saddr));
}

__device__ __forceinline__ void split1(float v, __half& h, __half& l)
{
    h = __float2half_rn(v);
    l = __float2half_rn(v - __half2float(h));
}

__device__ __forceinline__ void split2(float a, float b, unsigned& hi, unsigned& lo)
{
    __half2 h = __floats2half2_rn(a, b);
    float2 hf = __half22float2(h);
    __half2 l = __floats2half2_rn(a - hf.x, b - hf.y);
    hi = *(unsigned*)&h;
    lo = *(unsigned*)&l;
}

// 16-byte async copy global -> shared (cp.async.cg).
__device__ __forceinline__ void cp16(void* smem_dst, const void* gsrc)
{
    unsigned sa = (unsigned)__cvta_generic_to_shared(smem_dst);
    asm volatile("cp.async.cg.shared.global [%0], [%1], 16;\n" :: "r"(sa), "l"(gsrc));
}

// ---------------------------------------------------------------------------
// QKV projection — exact R7 version (72.3us): grid 256, block = 64 rows x
// all 192 cols, cp.async pipelined, ldmatrix fragment loads.
// ---------------------------------------------------------------------------
#define QP_SMEM 106496

__global__ __launch_bounds__(256, 2)
void qkv_proj(const float* __restrict__ x,
              const float* __restrict__ wk,
              const float* __restrict__ wq,
              const float* __restrict__ wv)
{
    extern __shared__ __align__(16) char qsm[];
    float*  Xraw = (float*)qsm;                    // [2][2048]
    float*  Wraw = (float*)(qsm + 16384);          // [2][6144]
    __half* Xh   = (__half*)(qsm + 65536);         // [64][40]
    __half* Xl   = (__half*)(qsm + 70656);
    __half* Wh   = (__half*)(qsm + 75776);         // [192][40]
    __half* Wl   = (__half*)(qsm + 91136);

    const int tid  = threadIdx.x;
    const int warp = tid >> 5;
    const int lane = tid & 31;
    const int g    = lane >> 2;
    const int cq   = lane & 3;
    const int li   = lane & 7;
    const int lm   = lane >> 3;
    const int rg   = warp >> 1;
    const int cg   = warp & 1;
    const int rows0 = blockIdx.x * 64;

    const int xr  = tid >> 3;
    const int xc  = (tid & 7) * 4;
    const int wr0 = tid >> 3;

    const unsigned aXh = (unsigned)__cvta_generic_to_shared(Xh)
                       + ((16 * rg + 8 * (lm & 1) + li) * 40 + 8 * (lm >> 1)) * 2;
    const unsigned aXl = aXh + 5120;
    const unsigned aWh = (unsigned)__cvta_generic_to_shared(Wh)
                       + ((cg * 96 + 8 * (lm >> 1) + li) * 40 + 8 * (lm & 1)) * 2;
    const unsigned aWl = aWh + 15360;

    float acc[12][4];
    #pragma unroll
    for (int j = 0; j < 12; j++)
        #pragma unroll
        for (int i = 0; i < 4; i++) acc[j][i] = 0.f;

    {
        cp16(Xraw + xr * 32 + xc,        x + (size_t)(rows0 + xr) * EDIM + xc);
        cp16(Xraw + (xr + 32) * 32 + xc, x + (size_t)(rows0 + xr + 32) * EDIM + xc);
        #pragma unroll
        for (int k = 0; k < 6; k++) {
            int r = wr0 + 32 * k;
            const float* src = (r < 64)  ? wk + (size_t)r * EDIM
                             : (r < 128) ? wq + (size_t)(r - 64) * EDIM
                                         : wv + (size_t)(r - 128) * EDIM;
            cp16(Wraw + r * 32 + xc, src + xc);
        }
        asm volatile("cp.async.commit_group;\n" ::: "memory");
    }

    for (int it = 0; it < 32; it++) {
        const int buf = it & 1;
        float* Xb = Xraw + buf * 2048;
        float* Wb = Wraw + buf * 6144;

        if (it + 1 < 32) {
            const int nbuf = (it + 1) & 1;
            const int e0   = (it + 1) * 32;
            float* Xn = Xraw + nbuf * 2048;
            float* Wn = Wraw + nbuf * 6144;
            cp16(Xn + xr * 32 + xc,        x + (size_t)(rows0 + xr) * EDIM + e0 + xc);
            cp16(Xn + (xr + 32) * 32 + xc, x + (size_t)(rows0 + xr + 32) * EDIM + e0 + xc);
            #pragma unroll
            for (int k = 0; k < 6; k++) {
                int r = wr0 + 32 * k;
                const float* src = (r < 64)  ? wk + (size_t)r * EDIM
                                 : (r < 128) ? wq + (size_t)(r - 64) * EDIM
                                             : wv + (size_t)(r - 128) * EDIM;
                cp16(Wn + r * 32 + xc, src + e0 + xc);
            }
            asm volatile("cp.async.commit_group;\n" ::: "memory");
            asm volatile("cp.async.wait_group 1;\n" ::: "memory");
        } else {
            asm volatile("cp.async.wait_group 0;\n" ::: "memory");
        }
        __syncthreads();

        #pragma unroll
        for (int k = 0; k < 2; k++) {
            int r = xr + 32 * k;
            float4 v = *(const float4*)(Xb + r * 32 + xc);
            __half h[4], l[4];
            split1(v.x, h[0], l[0]); split1(v.y, h[1], l[1]);
            split1(v.z, h[2], l[2]); split1(v.w, h[3], l[3]);
            *(uint2*)(Xh + r * 40 + xc) = *(uint2*)h;
            *(uint2*)(Xl + r * 40 + xc) = *(uint2*)l;
        }
        #pragma unroll
        for (int k = 0; k < 6; k++) {
            int r = wr0 + 32 * k;
            float4 v = *(const float4*)(Wb + r * 32 + xc);
            __half h[4], l[4];
            split1(v.x, h[0], l[0]); split1(v.y, h[1], l[1]);
            split1(v.z, h[2], l[2]); split1(v.w, h[3], l[3]);
            *(uint2*)(Wh + r * 40 + xc) = *(uint2*)h;
            *(uint2*)(Wl + r * 40 + xc) = *(uint2*)l;
        }
        __syncthreads();

        #pragma unroll
        for (int kc = 0; kc < 2; kc++) {
            unsigned ah[4], al[4];
            ldmx4(ah, aXh + kc * 32);
            ldmx4(al, aXl + kc * 32);
            #pragma unroll
            for (int t = 0; t < 6; t++) {
                unsigned bh[4], bl[4];
                ldmx4(bh, aWh + t * 1280 + kc * 32);
                ldmx4(bl, aWl + t * 1280 + kc * 32);
                mma16816(acc[2 * t],     ah, bh);
                mma16816(acc[2 * t],     ah, bl);
                mma16816(acc[2 * t],     al, bh);
                mma16816(acc[2 * t + 1], ah, bh + 2);
                mma16816(acc[2 * t + 1], ah, bl + 2);
                mma16816(acc[2 * t + 1], al, bh + 2);
            }
        }
    }

    const int row_lo = rows0 + 16 * rg + g;
    const int row_hi = row_lo + 8;
    #pragma unroll
    for (int j = 0; j < 12; j++) {
        int colg = cg * 96 + 8 * j + 2 * cq;
        __half *dh, *dl;
        float sc = 1.f;
        int cl;
        if (colg < 64)       { dh = g_Kh; dl = g_Kl; cl = colg; }
        else if (colg < 128) { dh = g_Qh; dl = g_Ql; cl = colg - 64; sc = 0.125f; }
        else                 { dh = g_Vh; dl = g_Vl; cl = colg - 128; }

        unsigned h2, l2;
        split2(acc[j][0] * sc, acc[j][1] * sc, h2, l2);
        *(unsigned*)(dh + (size_t)row_lo * ADIM + cl) = h2;
        *(unsigned*)(dl + (size_t)row_lo * ADIM + cl) = l2;
        split2(acc[j][2] * sc, acc[j][3] * sc, h2, l2);
        *(unsigned*)(dh + (size_t)row_hi * ADIM + cl) = h2;
        *(unsigned*)(dl + (size_t)row_hi * ADIM + cl) = l2;
    }
}

// ---------------------------------------------------------------------------
// Causal flash attention, split-KV (NS=8). K/V row-major; K via ldmatrix,
// V via ldmatrix.trans. Residency raised to 4 CTA/SM.
// ---------------------------------------------------------------------------
#define ST 72
#define OFF_KH 0
#define OFF_KL 4608
#define OFF_VH 9216
#define OFF_VL 13824
#define SMEM_HALVES 18432

__global__ __launch_bounds__(128, 4)
void attn_kernel()
{
    extern __shared__ __align__(16) __half sh[];

    const int tid  = threadIdx.x;
    const int w    = tid >> 5;
    const int lane = tid & 31;
    const int g    = lane >> 2;
    const int cq   = lane & 3;
    const int li   = lane & 7;
    const int lm   = lane >> 3;
    const int bx   = blockIdx.x;
    const int s    = bx & (NS - 1);
    const int qi   = (SEQ / 64 - 1) - (bx >> 3);   // heavy q-tiles first
    const int b    = blockIdx.y;
    const int q0   = qi * 64;

    if (qi < s) return;

    const unsigned shu = (unsigned)__cvta_generic_to_shared(sh);
    const unsigned lrowK = ((8 * (lm >> 1) + li) * ST + 8 * (lm & 1)) * 2;
    const unsigned aKh = shu + OFF_KH * 2 + lrowK;
    const unsigned aKl = shu + OFF_KL * 2 + lrowK;
    const unsigned lrowV = ((8 * (lm & 1) + li) * ST + 8 * (lm >> 1)) * 2;
    const unsigned aVh = shu + OFF_VH * 2 + lrowV;
    const unsigned aVl = shu + OFF_VL * 2 + lrowV;

    unsigned qh[4][4], ql[4][4];
    {
        size_t rl = (size_t)(b * SEQ + q0 + 16 * w + g) * ADIM;
        size_t rh = rl + 8 * ADIM;
        #pragma unroll
        for (int kc = 0; kc < 4; kc++) {
            int off = 16 * kc + 2 * cq;
            qh[kc][0] = *(const unsigned*)(g_Qh + rl + off);
            qh[kc][1] = *(const unsigned*)(g_Qh + rh + off);
            qh[kc][2] = *(const unsigned*)(g_Qh + rl + off + 8);
            qh[kc][3] = *(const unsigned*)(g_Qh + rh + off + 8);
            ql[kc][0] = *(const unsigned*)(g_Ql + rl + off);
            ql[kc][1] = *(const unsigned*)(g_Ql + rh + off);
            ql[kc][2] = *(const unsigned*)(g_Ql + rl + off + 8);
            ql[kc][3] = *(const unsigned*)(g_Ql + rh + off + 8);
        }
    }

    float o[8][4];
    #pragma unroll
    for (int j = 0; j < 8; j++)
        #pragma unroll
        for (int i = 0; i < 4; i++) o[j][i] = 0.f;
    float m_lo = -1e30f, m_hi = -1e30f, l_lo = 0.f, l_hi = 0.f;

    for (int kb = s; kb <= qi; kb += NS) {
        __syncthreads();
        {
            const __half* sKh = g_Kh + (size_t)(b * SEQ + kb * 64) * ADIM;
            const __half* sKl = g_Kl + (size_t)(b * SEQ + kb * 64) * ADIM;
            const __half* sVh = g_Vh + (size_t)(b * SEQ + kb * 64) * ADIM;
            const __half* sVl = g_Vl + (size_t)(b * SEQ + kb * 64) * ADIM;
            #pragma unroll
            for (int k = 0; k < 4; k++) {
                int f = tid + 128 * k;
                int r = f >> 3, c = f & 7;
                *(uint4*)(sh + OFF_KH + r * ST + 8 * c) = *(const uint4*)(sKh + r * ADIM + 8 * c);
                *(uint4*)(sh + OFF_KL + r * ST + 8 * c) = *(const uint4*)(sKl + r * ADIM + 8 * c);
                *(uint4*)(sh + OFF_VH + r * ST + 8 * c) = *(const uint4*)(sVh + r * ADIM + 8 * c);
                *(uint4*)(sh + OFF_VL + r * ST + 8 * c) = *(const uint4*)(sVl + r * ADIM + 8 * c);
            }
        }
        __syncthreads();

        // ---- S = Q K^T
        float sreg[8][4];
        #pragma unroll
        for (int j = 0; j < 8; j++)
            #pragma unroll
            for (int i = 0; i < 4; i++) sreg[j][i] = 0.f;

        #pragma unroll
        for (int kc = 0; kc < 4; kc++) {
            #pragma unroll
            for (int t = 0; t < 4; t++) {
                unsigned bh[4], bl[4];
                ldmx4(bh, aKh + t * 2304 + kc * 32);
                ldmx4(bl, aKl + t * 2304 + kc * 32);
                mma16816(sreg[2 * t],     qh[kc], bh);
                mma16816(sreg[2 * t],     qh[kc], bl);
                mma16816(sreg[2 * t],     ql[kc], bh);
                mma16816(sreg[2 * t + 1], qh[kc], bh + 2);
                mma16816(sreg[2 * t + 1], qh[kc], bl + 2);
                mma16816(sreg[2 * t + 1], ql[kc], bh + 2);
            }
        }

        if (kb == qi) {
            int r_lo = 16 * w + g, r_hi = r_lo + 8;
            #pragma unroll
            for (int j = 0; j < 8; j++) {
                int c0 = 8 * j + 2 * cq;
                if (c0     > r_lo) sreg[j][0] = -1e30f;
                if (c0 + 1 > r_lo) sreg[j][1] = -1e30f;
                if (c0     > r_hi) sreg[j][2] = -1e30f;
                if (c0 + 1 > r_hi) sreg[j][3] = -1e30f;
            }
        }

        // ---- online softmax
        float mx0 = -1e30f, mx1 = -1e30f;
        #pragma unroll
        for (int j = 0; j < 8; j++) {
            mx0 = fmaxf(mx0, fmaxf(sreg[j][0], sreg[j][1]));
            mx1 = fmaxf(mx1, fmaxf(sreg[j][2], sreg[j][3]));
        }
        mx0 = fmaxf(mx0, __shfl_xor_sync(0xffffffffu, mx0, 1));
        mx0 = fmaxf(mx0, __shfl_xor_sync(0xffffffffu, mx0, 2));
        mx1 = fmaxf(mx1, __shfl_xor_sync(0xffffffffu, mx1, 1));
        mx1 = fmaxf(mx1, __shfl_xor_sync(0xffffffffu, mx1, 2));
        float mn0 = fmaxf(m_lo, mx0), mn1 = fmaxf(m_hi, mx1);
        float sc0 = __expf(m_lo - mn0), sc1 = __expf(m_hi - mn1);
        m_lo = mn0; m_hi = mn1;
        float su0 = 0.f, su1 = 0.f;
        #pragma unroll
        for (int j = 0; j < 8; j++) {
            sreg[j][0] = __expf(sreg[j][0] - mn0);
            sreg[j][1] = __expf(sreg[j][1] - mn0);
            sreg[j][2] = __expf(sreg[j][2] - mn1);
            sreg[j][3] = __expf(sreg[j][3] - mn1);
            su0 += sreg[j][0] + sreg[j][1];
            su1 += sreg[j][2] + sreg[j][3];
        }
        su0 += __shfl_xor_sync(0xffffffffu, su0, 1);
        su0 += __shfl_xor_sync(0xffffffffu, su0, 2);
        su1 += __shfl_xor_sync(0xffffffffu, su1, 1);
        su1 += __shfl_xor_sync(0xffffffffu, su1, 2);
        l_lo = l_lo * sc0 + su0;
        l_hi = l_hi * sc1 + su1;
        #pragma unroll
        for (int j = 0; j < 8; j++) {
            o[j][0] *= sc0; o[j][1] *= sc0;
            o[j][2] *= sc1; o[j][3] *= sc1;
        }

        // ---- O += P V; V fragments via ldmatrix.trans
        #pragma unroll
        for (int kc = 0; kc < 4; kc++) {
            unsigned ph[4], pl[4];
            split2(sreg[2 * kc][0],     sreg[2 * kc][1],     ph[0], pl[0]);
            split2(sreg[2 * kc][2],     sreg[2 * kc][3],     ph[1], pl[1]);
            split2(sreg[2 * kc + 1][0], sreg[2 * kc + 1][1], ph[2], pl[2]);
            split2(sreg[2 * kc + 1][2], sreg[2 * kc + 1][3], ph[3], pl[3]);
            #pragma unroll
            for (int t = 0; t < 4; t++) {
                unsigned bh[4], bl[4];
                ldmx4t(bh, aVh + kc * 2304 + t * 32);
                ldmx4t(bl, aVl + kc * 2304 + t * 32);
                mma16816(o[2 * t],     ph, bh);
                mma16816(o[2 * t],     ph, bl);
                mma16816(o[2 * t],     pl, bh);
                mma16816(o[2 * t + 1], ph, bh + 2);
                mma16816(o[2 * t + 1], ph, bl + 2);
                mma16816(o[2 * t + 1], pl, bh + 2);
            }
        }
    }

    const int row_lo = q0 + 16 * w + g;
    const int row_hi = row_lo + 8;
    const size_t sb  = (size_t)(b * NS + s) * SEQ;
    #pragma unroll
    for (int j = 0; j < 8; j++) {
        int col = 8 * j + 2 * cq;
        *(float2*)(g_Om + (sb + row_lo) * ADIM + col) = make_float2(o[j][0], o[j][1]);
        *(float2*)(g_Om + (sb + row_hi) * ADIM + col) = make_float2(o[j][2], o[j][3]);
    }
    if (cq == 0) {
        g_m[sb + row_lo] = m_lo;  g_l[sb + row_lo] = l_lo;
        g_m[sb + row_hi] = m_hi;  g_l[sb + row_hi] = l_hi;
    }
}

// ---------------------------------------------------------------------------
// Combine split-KV partials.
// ---------------------------------------------------------------------------
__global__ __launch_bounds__(128)
void combine_kernel(float* __restrict__ out)
{
    const int tid = threadIdx.x;
    const int row = blockIdx.x * 8 + (tid >> 4);
    const int b   = blockIdx.y;
    const int c0  = (tid & 15) * 4;
    const int qi  = row >> 6;
    const int ns  = (qi + 1 < NS) ? (qi + 1) : NS;

    float m = -1e30f;
    #pragma unroll
    for (int s = 0; s < NS; s++)
        if (s < ns) m = fmaxf(m, g_m[(size_t)(b * NS + s) * SEQ + row]);

    float l = 0.f;
    float4 acc = make_float4(0.f, 0.f, 0.f, 0.f);
    #pragma unroll
    for (int s = 0; s < NS; s++) {
        if (s >= ns) break;
        size_t sb = (size_t)(b * NS + s) * SEQ + row;
        float wgt = __expf(g_m[sb] - m);
        l += g_l[sb] * wgt;
        float4 v = *(const float4*)(g_Om + sb * ADIM + c0);
        acc.x += v.x * wgt; acc.y += v.y * wgt;
        acc.z += v.z * wgt; acc.w += v.w * wgt;
    }
    float inv = 1.f / l;
    float4 r;
    r.x = rintf(acc.x * inv * 1e4f) * 1e-4f;
    r.y = rintf(acc.y * inv * 1e4f) * 1e-4f;
    r.z = rintf(acc.z * inv * 1e4f) * 1e-4f;
    r.w = rintf(acc.w * inv * 1e4f) * 1e-4f;
    *(float4*)(out + ((size_t)b * SEQ + row) * ADIM + c0) = r;
}

extern "C" void kernel_launch(void* const* d_in, const int* in_sizes, int n_in,
                              void* d_out, int out_size)
{
    const float* x  = (const float*)d_in[0];
    const float* wk = (const float*)d_in[1];
    const float* wq = (const float*)d_in[2];
    const float* wv = (const float*)d_in[3];
    float* out = (float*)d_out;

    cudaFuncSetAttribute(qkv_proj, cudaFuncAttributeMaxDynamicSharedMemorySize, QP_SMEM);
    qkv_proj<<<256, 256, QP_SMEM>>>(x, wk, wq, wv);

    int smem = SMEM_HALVES * (int)sizeof(__half);  // 36864 B
    cudaFuncSetAttribute(attn_kernel, cudaFuncAttributeMaxDynamicSharedMemorySize, smem);
    attn_kernel<<<dim3((SEQ / 64) * NS, NB), 128, smem>>>();

    combine_kernel<<<dim3(SEQ / 8, NB), 128>>>(out);
}

// round 11
// speedup vs baseline: 2.3645x; 1.0539x over previous
#include <cuda_runtime.h>
#include <cuda_fp16.h>
#include <math.h>

#define NB   4
#define SEQ  4096
#define EDIM 1024
#define ADIM 64
#define NS   8      // KV splits per q-tile

// Projected Q,K,V stored as split fp16 planes (hi + lo), [B*S, A] each.
__device__ __half g_Qh[NB * SEQ * ADIM];
__device__ __half g_Ql[NB * SEQ * ADIM];
__device__ __half g_Kh[NB * SEQ * ADIM];
__device__ __half g_Kl[NB * SEQ * ADIM];
__device__ __half g_Vh[NB * SEQ * ADIM];
__device__ __half g_Vl[NB * SEQ * ADIM];

// Split-KV partial results: O (unnormalized), row max m, row sum l.
__device__ float g_Om[NB * NS * SEQ * ADIM];   // 33.6 MB
__device__ float g_m [NB * NS * SEQ];
__device__ float g_l [NB * NS * SEQ];

// m16n8k16 f16 MMA, f32 accumulate, in-place C.
__device__ __forceinline__ void mma16816(float d[4], const unsigned a[4], const unsigned* b)
{
    asm volatile(
        "mma.sync.aligned.m16n8k16.row.col.f32.f16.f16.f32 "
        "{%0,%1,%2,%3}, {%4,%5,%6,%7}, {%8,%9}, {%0,%1,%2,%3};\n"
        : "+f"(d[0]), "+f"(d[1]), "+f"(d[2]), "+f"(d[3])
        : "r"(a[0]), "r"(a[1]), "r"(a[2]), "r"(a[3]), "r"(b[0]), "r"(b[1]));
}

// ldmatrix x4: 4 8x8 b16 matrices -> 4 regs/thread.
__device__ __forceinline__ void ldmx4(unsigned r[4], unsigned saddr)
{
    asm volatile(
        "ldmatrix.sync.aligned.m8n8.x4.shared.b16 {%0,%1,%2,%3}, [%4];\n"
        : "=r"(r[0]), "=r"(r[1]), "=r"(r[2]), "=r"(r[3]) : "r"(saddr));
}

// ldmatrix x4 transposed (for V^T fragments from row-major V).
__device__ __forceinline__ void ldmx4t(unsigned r[4], unsigned saddr)
{
    asm volatile(
        "ldmatrix.sync.aligned.m8n8.x4.trans.shared.b16 {%0,%1,%2,%3}, [%4];\n"
        : "=r"(r[0]), "=r"(r[1]), "=r"(r[2]), "=r"(r[3]) : "r"(saddr));
}

__device__ __forceinline__ void split1(float v, __half& h, __half& l)
{
    h = __float2half_rn(v);
    l = __float2half_rn(v - __half2float(h));
}

__device__ __forceinline__ void split2(float a, float b, unsigned& hi, unsigned& lo)
{
    __half2 h = __floats2half2_rn(a, b);
    float2 hf = __half22float2(h);
    __half2 l = __floats2half2_rn(a - hf.x, b - hf.y);
    hi = *(unsigned*)&h;
    lo = *(unsigned*)&l;
}

// 16-byte async copy global -> shared (cp.async.cg).
__device__ __forceinline__ void cp16(void* smem_dst, const void* gsrc)
{
    unsigned sa = (unsigned)__cvta_generic_to_shared(smem_dst);
    asm volatile("cp.async.cg.shared.global [%0], [%1], 16;\n" :: "r"(sa), "l"(gsrc));
}

// ---------------------------------------------------------------------------
// QKV projection. X via cp.async double-buffer (DRAM path); W via direct
// LDG (L2-resident) + inline split — no raw W staging. Warp grid 2 rg x 4 cg
// (32 rows x 48 cols per warp): B-fragment ldmatrix duplication 4x -> 2x.
// Smem (bytes): Xraw[2][2048]f32 @0, Xh[64][40] @16384, Xl @21504,
//               Wh[192][40] @26624, Wl @41984; total 57344.
// ---------------------------------------------------------------------------
#define QP_SMEM 57344

__global__ __launch_bounds__(256, 2)
void qkv_proj(const float* __restrict__ x,
              const float* __restrict__ wk,
              const float* __restrict__ wq,
              const float* __restrict__ wv)
{
    extern __shared__ __align__(16) char qsm[];
    float*  Xraw = (float*)qsm;                    // [2][2048]
    __half* Xh   = (__half*)(qsm + 16384);         // [64][40]
    __half* Xl   = (__half*)(qsm + 21504);
    __half* Wh   = (__half*)(qsm + 26624);         // [192][40]
    __half* Wl   = (__half*)(qsm + 41984);

    const int tid  = threadIdx.x;
    const int warp = tid >> 5;
    const int lane = tid & 31;
    const int g    = lane >> 2;
    const int cq   = lane & 3;
    const int li   = lane & 7;
    const int lm   = lane >> 3;
    const int rg   = warp >> 2;          // row group 0..1 (32 rows)
    const int cg   = warp & 3;           // col group 0..3 (48 cols)
    const int rows0 = blockIdx.x * 64;

    const int xr  = tid >> 3;            // 0..31
    const int xc  = (tid & 7) * 4;
    const int wr0 = tid >> 3;            // W rows wr0 + 32k

    const unsigned aXh = (unsigned)__cvta_generic_to_shared(Xh)
                       + ((32 * rg + 8 * (lm & 1) + li) * 40 + 8 * (lm >> 1)) * 2;
    const unsigned aXl = aXh + 5120;
    const unsigned aWh = (unsigned)__cvta_generic_to_shared(Wh)
                       + ((cg * 48 + 8 * (lm >> 1) + li) * 40 + 8 * (lm & 1)) * 2;
    const unsigned aWl = aWh + 15360;

    // Per-thread W row sources (constant across iterations)
    const float* wsrc[6];
    #pragma unroll
    for (int k = 0; k < 6; k++) {
        int r = wr0 + 32 * k;
        wsrc[k] = (r < 64)  ? wk + (size_t)r * EDIM
                : (r < 128) ? wq + (size_t)(r - 64) * EDIM
                            : wv + (size_t)(r - 128) * EDIM;
    }

    float acc[2][6][4];
    #pragma unroll
    for (int m = 0; m < 2; m++)
        #pragma unroll
        for (int j = 0; j < 6; j++)
            #pragma unroll
            for (int i = 0; i < 4; i++) acc[m][j][i] = 0.f;

    cp16(Xraw + xr * 32 + xc,        x + (size_t)(rows0 + xr) * EDIM + xc);
    cp16(Xraw + (xr + 32) * 32 + xc, x + (size_t)(rows0 + xr + 32) * EDIM + xc);
    asm volatile("cp.async.commit_group;\n" ::: "memory");

    for (int it = 0; it < 32; it++) {
        const int buf = it & 1;
        const int e0  = it * 32;
        float* Xb = Xraw + buf * 2048;

        // W prefetch into registers (L2-hot)
        float4 wvreg[6];
        #pragma unroll
        for (int k = 0; k < 6; k++)
            wvreg[k] = *(const float4*)(wsrc[k] + e0 + xc);

        if (it + 1 < 32) {
            const int nbuf = (it + 1) & 1;
            const int e1   = (it + 1) * 32;
            float* Xn = Xraw + nbuf * 2048;
            cp16(Xn + xr * 32 + xc,        x + (size_t)(rows0 + xr) * EDIM + e1 + xc);
            cp16(Xn + (xr + 32) * 32 + xc, x + (size_t)(rows0 + xr + 32) * EDIM + e1 + xc);
            asm volatile("cp.async.commit_group;\n" ::: "memory");
            asm volatile("cp.async.wait_group 1;\n" ::: "memory");
        } else {
            asm volatile("cp.async.wait_group 0;\n" ::: "memory");
        }
        __syncthreads();   // prev MMA done with planes; X chunk `it` resident

        // split W registers -> planes
        #pragma unroll
        for (int k = 0; k < 6; k++) {
            int r = wr0 + 32 * k;
            __half h[4], l[4];
            split1(wvreg[k].x, h[0], l[0]); split1(wvreg[k].y, h[1], l[1]);
            split1(wvreg[k].z, h[2], l[2]); split1(wvreg[k].w, h[3], l[3]);
            *(uint2*)(Wh + r * 40 + xc) = *(uint2*)h;
            *(uint2*)(Wl + r * 40 + xc) = *(uint2*)l;
        }
        // split X raw -> planes
        #pragma unroll
        for (int k = 0; k < 2; k++) {
            int r = xr + 32 * k;
            float4 v = *(const float4*)(Xb + r * 32 + xc);
            __half h[4], l[4];
            split1(v.x, h[0], l[0]); split1(v.y, h[1], l[1]);
            split1(v.z, h[2], l[2]); split1(v.w, h[3], l[3]);
            *(uint2*)(Xh + r * 40 + xc) = *(uint2*)h;
            *(uint2*)(Xl + r * 40 + xc) = *(uint2*)l;
        }
        __syncthreads();

        // MMAs
        #pragma unroll
        for (int kc = 0; kc < 2; kc++) {
            unsigned ah[2][4], al[2][4];
            #pragma unroll
            for (int m = 0; m < 2; m++) {
                ldmx4(ah[m], aXh + m * 1280 + kc * 32);
                ldmx4(al[m], aXl + m * 1280 + kc * 32);
            }
            #pragma unroll
            for (int t = 0; t < 3; t++) {
                unsigned bh[4], bl[4];
                ldmx4(bh, aWh + t * 1280 + kc * 32);
                ldmx4(bl, aWl + t * 1280 + kc * 32);
                #pragma unroll
                for (int m = 0; m < 2; m++) {
                    mma16816(acc[m][2 * t],     ah[m], bh);
                    mma16816(acc[m][2 * t],     ah[m], bl);
                    mma16816(acc[m][2 * t],     al[m], bh);
                    mma16816(acc[m][2 * t + 1], ah[m], bh + 2);
                    mma16816(acc[m][2 * t + 1], ah[m], bl + 2);
                    mma16816(acc[m][2 * t + 1], al[m], bh + 2);
                }
            }
        }
    }

    #pragma unroll
    for (int m = 0; m < 2; m++) {
        const int row_lo = rows0 + 32 * rg + 16 * m + g;
        const int row_hi = row_lo + 8;
        #pragma unroll
        for (int j = 0; j < 6; j++) {
            int colg = cg * 48 + 8 * j + 2 * cq;
            __half *dh, *dl;
            float sc = 1.f;
            int cl;
            if (colg < 64)       { dh = g_Kh; dl = g_Kl; cl = colg; }
            else if (colg < 128) { dh = g_Qh; dl = g_Ql; cl = colg - 64; sc = 0.125f; }
            else                 { dh = g_Vh; dl = g_Vl; cl = colg - 128; }

            unsigned h2, l2;
            split2(acc[m][j][0] * sc, acc[m][j][1] * sc, h2, l2);
            *(unsigned*)(dh + (size_t)row_lo * ADIM + cl) = h2;
            *(unsigned*)(dl + (size_t)row_lo * ADIM + cl) = l2;
            split2(acc[m][j][2] * sc, acc[m][j][3] * sc, h2, l2);
            *(unsigned*)(dh + (size_t)row_hi * ADIM + cl) = h2;
            *(unsigned*)(dl + (size_t)row_hi * ADIM + cl) = l2;
        }
    }
}

// ---------------------------------------------------------------------------
// Causal flash attention, split-KV (NS=8). Unchanged from R9.
// ---------------------------------------------------------------------------
#define ST 72
#define OFF_KH 0
#define OFF_KL 4608
#define OFF_VH 9216
#define OFF_VL 13824
#define SMEM_HALVES 18432

__global__ __launch_bounds__(128, 4)
void attn_kernel()
{
    extern __shared__ __align__(16) __half sh[];

    const int tid  = threadIdx.x;
    const int w    = tid >> 5;
    const int lane = tid & 31;
    const int g    = lane >> 2;
    const int cq   = lane & 3;
    const int li   = lane & 7;
    const int lm   = lane >> 3;
    const int bx   = blockIdx.x;
    const int s    = bx & (NS - 1);
    const int qi   = (SEQ / 64 - 1) - (bx >> 3);
    const int b    = blockIdx.y;
    const int q0   = qi * 64;

    if (qi < s) return;

    const unsigned shu = (unsigned)__cvta_generic_to_shared(sh);
    const unsigned lrowK = ((8 * (lm >> 1) + li) * ST + 8 * (lm & 1)) * 2;
    const unsigned aKh = shu + OFF_KH * 2 + lrowK;
    const unsigned aKl = shu + OFF_KL * 2 + lrowK;
    const unsigned lrowV = ((8 * (lm & 1) + li) * ST + 8 * (lm >> 1)) * 2;
    const unsigned aVh = shu + OFF_VH * 2 + lrowV;
    const unsigned aVl = shu + OFF_VL * 2 + lrowV;

    unsigned qh[4][4], ql[4][4];
    {
        size_t rl = (size_t)(b * SEQ + q0 + 16 * w + g) * ADIM;
        size_t rh = rl + 8 * ADIM;
        #pragma unroll
        for (int kc = 0; kc < 4; kc++) {
            int off = 16 * kc + 2 * cq;
            qh[kc][0] = *(const unsigned*)(g_Qh + rl + off);
            qh[kc][1] = *(const unsigned*)(g_Qh + rh + off);
            qh[kc][2] = *(const unsigned*)(g_Qh + rl + off + 8);
            qh[kc][3] = *(const unsigned*)(g_Qh + rh + off + 8);
            ql[kc][0] = *(const unsigned*)(g_Ql + rl + off);
            ql[kc][1] = *(const unsigned*)(g_Ql + rh + off);
            ql[kc][2] = *(const unsigned*)(g_Ql + rl + off + 8);
            ql[kc][3] = *(const unsigned*)(g_Ql + rh + off + 8);
        }
    }

    float o[8][4];
    #pragma unroll
    for (int j = 0; j < 8; j++)
        #pragma unroll
        for (int i = 0; i < 4; i++) o[j][i] = 0.f;
    float m_lo = -1e30f, m_hi = -1e30f, l_lo = 0.f, l_hi = 0.f;

    for (int kb = s; kb <= qi; kb += NS) {
        __syncthreads();
        {
            const __half* sKh = g_Kh + (size_t)(b * SEQ + kb * 64) * ADIM;
            const __half* sKl = g_Kl + (size_t)(b * SEQ + kb * 64) * ADIM;
            const __half* sVh = g_Vh + (size_t)(b * SEQ + kb * 64) * ADIM;
            const __half* sVl = g_Vl + (size_t)(b * SEQ + kb * 64) * ADIM;
            #pragma unroll
            for (int k = 0; k < 4; k++) {
                int f = tid + 128 * k;
                int r = f >> 3, c = f & 7;
                *(uint4*)(sh + OFF_KH + r * ST + 8 * c) = *(const uint4*)(sKh + r * ADIM + 8 * c);
                *(uint4*)(sh + OFF_KL + r * ST + 8 * c) = *(const uint4*)(sKl + r * ADIM + 8 * c);
                *(uint4*)(sh + OFF_VH + r * ST + 8 * c) = *(const uint4*)(sVh + r * ADIM + 8 * c);
                *(uint4*)(sh + OFF_VL + r * ST + 8 * c) = *(const uint4*)(sVl + r * ADIM + 8 * c);
            }
        }
        __syncthreads();

        float sreg[8][4];
        #pragma unroll
        for (int j = 0; j < 8; j++)
            #pragma unroll
            for (int i = 0; i < 4; i++) sreg[j][i] = 0.f;

        #pragma unroll
        for (int kc = 0; kc < 4; kc++) {
            #pragma unroll
            for (int t = 0; t < 4; t++) {
                unsigned bh[4], bl[4];
                ldmx4(bh, aKh + t * 2304 + kc * 32);
                ldmx4(bl, aKl + t * 2304 + kc * 32);
                mma16816(sreg[2 * t],     qh[kc], bh);
                mma16816(sreg[2 * t],     qh[kc], bl);
                mma16816(sreg[2 * t],     ql[kc], bh);
                mma16816(sreg[2 * t + 1], qh[kc], bh + 2);
                mma16816(sreg[2 * t + 1], qh[kc], bl + 2);
                mma16816(sreg[2 * t + 1], ql[kc], bh + 2);
            }
        }

        if (kb == qi) {
            int r_lo = 16 * w + g, r_hi = r_lo + 8;
            #pragma unroll
            for (int j = 0; j < 8; j++) {
                int c0 = 8 * j + 2 * cq;
                if (c0     > r_lo) sreg[j][0] = -1e30f;
                if (c0 + 1 > r_lo) sreg[j][1] = -1e30f;
                if (c0     > r_hi) sreg[j][2] = -1e30f;
                if (c0 + 1 > r_hi) sreg[j][3] = -1e30f;
            }
        }

        float mx0 = -1e30f, mx1 = -1e30f;
        #pragma unroll
        for (int j = 0; j < 8; j++) {
            mx0 = fmaxf(mx0, fmaxf(sreg[j][0], sreg[j][1]));
            mx1 = fmaxf(mx1, fmaxf(sreg[j][2], sreg[j][3]));
        }
        mx0 = fmaxf(mx0, __shfl_xor_sync(0xffffffffu, mx0, 1));
        mx0 = fmaxf(mx0, __shfl_xor_sync(0xffffffffu, mx0, 2));
        mx1 = fmaxf(mx1, __shfl_xor_sync(0xffffffffu, mx1, 1));
        mx1 = fmaxf(mx1, __shfl_xor_sync(0xffffffffu, mx1, 2));
        float mn0 = fmaxf(m_lo, mx0), mn1 = fmaxf(m_hi, mx1);
        float sc0 = __expf(m_lo - mn0), sc1 = __expf(m_hi - mn1);
        m_lo = mn0; m_hi = mn1;
        float su0 = 0.f, su1 = 0.f;
        #pragma unroll
        for (int j = 0; j < 8; j++) {
            sreg[j][0] = __expf(sreg[j][0] - mn0);
            sreg[j][1] = __expf(sreg[j][1] - mn0);
            sreg[j][2] = __expf(sreg[j][2] - mn1);
            sreg[j][3] = __expf(sreg[j][3] - mn1);
            su0 += sreg[j][0] + sreg[j][1];
            su1 += sreg[j][2] + sreg[j][3];
        }
        su0 += __shfl_xor_sync(0xffffffffu, su0, 1);
        su0 += __shfl_xor_sync(0xffffffffu, su0, 2);
        su1 += __shfl_xor_sync(0xffffffffu, su1, 1);
        su1 += __shfl_xor_sync(0xffffffffu, su1, 2);
        l_lo = l_lo * sc0 + su0;
        l_hi = l_hi * sc1 + su1;
        #pragma unroll
        for (int j = 0; j < 8; j++) {
            o[j][0] *= sc0; o[j][1] *= sc0;
            o[j][2] *= sc1; o[j][3] *= sc1;
        }

        #pragma unroll
        for (int kc = 0; kc < 4; kc++) {
            unsigned ph[4], pl[4];
            split2(sreg[2 * kc][0],     sreg[2 * kc][1],     ph[0], pl[0]);
            split2(sreg[2 * kc][2],     sreg[2 * kc][3],     ph[1], pl[1]);
            split2(sreg[2 * kc + 1][0], sreg[2 * kc + 1][1], ph[2], pl[2]);
            split2(sreg[2 * kc + 1][2], sreg[2 * kc + 1][3], ph[3], pl[3]);
            #pragma unroll
            for (int t = 0; t < 4; t++) {
                unsigned bh[4], bl[4];
                ldmx4t(bh, aVh + kc * 2304 + t * 32);
                ldmx4t(bl, aVl + kc * 2304 + t * 32);
                mma16816(o[2 * t],     ph, bh);
                mma16816(o[2 * t],     ph, bl);
                mma16816(o[2 * t],     pl, bh);
                mma16816(o[2 * t + 1], ph, bh + 2);
                mma16816(o[2 * t + 1], ph, bl + 2);
                mma16816(o[2 * t + 1], pl, bh + 2);
            }
        }
    }

    const int row_lo = q0 + 16 * w + g;
    const int row_hi = row_lo + 8;
    const size_t sb  = (size_t)(b * NS + s) * SEQ;
    #pragma unroll
    for (int j = 0; j < 8; j++) {
        int col = 8 * j + 2 * cq;
        *(float2*)(g_Om + (sb + row_lo) * ADIM + col) = make_float2(o[j][0], o[j][1]);
        *(float2*)(g_Om + (sb + row_hi) * ADIM + col) = make_float2(o[j][2], o[j][3]);
    }
    if (cq == 0) {
        g_m[sb + row_lo] = m_lo;  g_l[sb + row_lo] = l_lo;
        g_m[sb + row_hi] = m_hi;  g_l[sb + row_hi] = l_hi;
    }
}

// ---------------------------------------------------------------------------
// Combine split-KV partials.
// ---------------------------------------------------------------------------
__global__ __launch_bounds__(128)
void combine_kernel(float* __restrict__ out)
{
    const int tid = threadIdx.x;
    const int row = blockIdx.x * 8 + (tid >> 4);
    const int b   = blockIdx.y;
    const int c0  = (tid & 15) * 4;
    const int qi  = row >> 6;
    const int ns  = (qi + 1 < NS) ? (qi + 1) : NS;

    float m = -1e30f;
    #pragma unroll
    for (int s = 0; s < NS; s++)
        if (s < ns) m = fmaxf(m, g_m[(size_t)(b * NS + s) * SEQ + row]);

    float l = 0.f;
    float4 acc = make_float4(0.f, 0.f, 0.f, 0.f);
    #pragma unroll
    for (int s = 0; s < NS; s++) {
        if (s >= ns) break;
        size_t sb = (size_t)(b * NS + s) * SEQ + row;
        float wgt = __expf(g_m[sb] - m);
        l += g_l[sb] * wgt;
        float4 v = *(const float4*)(g_Om + sb * ADIM + c0);
        acc.x += v.x * wgt; acc.y += v.y * wgt;
        acc.z += v.z * wgt; acc.w += v.w * wgt;
    }
    float inv = 1.f / l;
    float4 r;
    r.x = rintf(acc.x * inv * 1e4f) * 1e-4f;
    r.y = rintf(acc.y * inv * 1e4f) * 1e-4f;
    r.z = rintf(acc.z * inv * 1e4f) * 1e-4f;
    r.w = rintf(acc.w * inv * 1e4f) * 1e-4f;
    *(float4*)(out + ((size_t)b * SEQ + row) * ADIM + c0) = r;
}

extern "C" void kernel_launch(void* const* d_in, const int* in_sizes, int n_in,
                              void* d_out, int out_size)
{
    const float* x  = (const float*)d_in[0];
    const float* wk = (const float*)d_in[1];
    const float* wq = (const float*)d_in[2];
    const float* wv = (const float*)d_in[3];
    float* out = (float*)d_out;

    cudaFuncSetAttribute(qkv_proj, cudaFuncAttributeMaxDynamicSharedMemorySize, QP_SMEM);
    qkv_proj<<<256, 256, QP_SMEM>>>(x, wk, wq, wv);

    int smem = SMEM_HALVES * (int)sizeof(__half);  // 36864 B
    cudaFuncSetAttribute(attn_kernel, cudaFuncAttributeMaxDynamicSharedMemorySize, smem);
    attn_kernel<<<dim3((SEQ / 64) * NS, NB), 128, smem>>>();

    combine_kernel<<<dim3(SEQ / 8, NB), 128>>>(out);
}

// round 12
// speedup vs baseline: 2.5132x; 1.0629x over previous
#include <cuda_runtime.h>
#include <cuda_fp16.h>
#include <math.h>

#define NB   4
#define SEQ  4096
#define EDIM 1024
#define ADIM 64
#define NS   8      // KV splits per q-tile

// Projected Q,K,V stored as split fp16 planes (hi + lo), [B*S, A] each.
// (V lo plane still produced by projection; attention uses only Vh.)
__device__ __half g_Qh[NB * SEQ * ADIM];
__device__ __half g_Ql[NB * SEQ * ADIM];
__device__ __half g_Kh[NB * SEQ * ADIM];
__device__ __half g_Kl[NB * SEQ * ADIM];
__device__ __half g_Vh[NB * SEQ * ADIM];
__device__ __half g_Vl[NB * SEQ * ADIM];

// Split-KV partial results: O (unnormalized), row max m, row sum l.
__device__ float g_Om[NB * NS * SEQ * ADIM];   // 33.6 MB
__device__ float g_m [NB * NS * SEQ];
__device__ float g_l [NB * NS * SEQ];

// m16n8k16 f16 MMA, f32 accumulate, in-place C.
__device__ __forceinline__ void mma16816(float d[4], const unsigned a[4], const unsigned* b)
{
    asm volatile(
        "mma.sync.aligned.m16n8k16.row.col.f32.f16.f16.f32 "
        "{%0,%1,%2,%3}, {%4,%5,%6,%7}, {%8,%9}, {%0,%1,%2,%3};\n"
        : "+f"(d[0]), "+f"(d[1]), "+f"(d[2]), "+f"(d[3])
        : "r"(a[0]), "r"(a[1]), "r"(a[2]), "r"(a[3]), "r"(b[0]), "r"(b[1]));
}

// ldmatrix x4: 4 8x8 b16 matrices -> 4 regs/thread.
__device__ __forceinline__ void ldmx4(unsigned r[4], unsigned saddr)
{
    asm volatile(
        "ldmatrix.sync.aligned.m8n8.x4.shared.b16 {%0,%1,%2,%3}, [%4];\n"
        : "=r"(r[0]), "=r"(r[1]), "=r"(r[2]), "=r"(r[3]) : "r"(saddr));
}

// ldmatrix x4 transposed (for V^T fragments from row-major V).
__device__ __forceinline__ void ldmx4t(unsigned r[4], unsigned saddr)
{
    asm volatile(
        "ldmatrix.sync.aligned.m8n8.x4.trans.shared.b16 {%0,%1,%2,%3}, [%4];\n"
        : "=r"(r[0]), "=r"(r[1]), "=r"(r[2]), "=r"(r[3]) : "r"(saddr));
}

__device__ __forceinline__ void split1(float v, __half& h, __half& l)
{
    h = __float2half_rn(v);
    l = __float2half_rn(v - __half2float(h));
}

__device__ __forceinline__ void split2(float a, float b, unsigned& hi, unsigned& lo)
{
    __half2 h = __floats2half2_rn(a, b);
    float2 hf = __half22float2(h);
    __half2 l = __floats2half2_rn(a - hf.x, b - hf.y);
    hi = *(unsigned*)&h;
    lo = *(unsigned*)&l;
}

// ---------------------------------------------------------------------------
// QKV projection. X and W both direct LDG with register double-buffer
// (no raw smem staging at all); split planes only in smem.
// Warp grid 2 rg x 4 cg (32 rows x 48 cols per warp).
// Smem (bytes): Xh[64][40] @0, Xl @5120, Wh[192][40] @10240, Wl @25600;
// total 40960.
// ---------------------------------------------------------------------------
#define QP_SMEM 40960

__global__ __launch_bounds__(256, 2)
void qkv_proj(const float* __restrict__ x,
              const float* __restrict__ wk,
              const float* __restrict__ wq,
              const float* __restrict__ wv)
{
    extern __shared__ __align__(16) char qsm[];
    __half* Xh = (__half*)qsm;                     // [64][40]
    __half* Xl = (__half*)(qsm + 5120);
    __half* Wh = (__half*)(qsm + 10240);           // [192][40]
    __half* Wl = (__half*)(qsm + 25600);

    const int tid  = threadIdx.x;
    const int warp = tid >> 5;
    const int lane = tid & 31;
    const int g    = lane >> 2;
    const int cq   = lane & 3;
    const int li   = lane & 7;
    const int lm   = lane >> 3;
    const int rg   = warp >> 2;          // row group 0..1 (32 rows)
    const int cg   = warp & 3;           // col group 0..3 (48 cols)
    const int rows0 = blockIdx.x * 64;

    const int xr  = tid >> 3;            // 0..31 (rows xr, xr+32)
    const int xc  = (tid & 7) * 4;
    const int wr0 = tid >> 3;            // W rows wr0 + 32k

    const unsigned aXh = (unsigned)__cvta_generic_to_shared(Xh)
                       + ((32 * rg + 8 * (lm & 1) + li) * 40 + 8 * (lm >> 1)) * 2;
    const unsigned aXl = aXh + 5120;
    const unsigned aWh = (unsigned)__cvta_generic_to_shared(Wh)
                       + ((cg * 48 + 8 * (lm >> 1) + li) * 40 + 8 * (lm & 1)) * 2;
    const unsigned aWl = aWh + 15360;

    // Per-thread global row pointers (constant across iterations)
    const float* xsrc0 = x + (size_t)(rows0 + xr) * EDIM + xc;
    const float* xsrc1 = x + (size_t)(rows0 + xr + 32) * EDIM + xc;
    const float* wsrc[6];
    #pragma unroll
    for (int k = 0; k < 6; k++) {
        int r = wr0 + 32 * k;
        wsrc[k] = ((r < 64)  ? wk + (size_t)r * EDIM
                 : (r < 128) ? wq + (size_t)(r - 64) * EDIM
                             : wv + (size_t)(r - 128) * EDIM) + xc;
    }

    float acc[2][6][4];
    #pragma unroll
    for (int m = 0; m < 2; m++)
        #pragma unroll
        for (int j = 0; j < 6; j++)
            #pragma unroll
            for (int i = 0; i < 4; i++) acc[m][j][i] = 0.f;

    // Prologue: chunk 0 into registers
    float4 xa = *(const float4*)(xsrc0);
    float4 xb = *(const float4*)(xsrc1);
    float4 wvreg[6];
    #pragma unroll
    for (int k = 0; k < 6; k++) wvreg[k] = *(const float4*)(wsrc[k]);

    for (int it = 0; it < 32; it++) {
        __syncthreads();   // previous MMA done reading the planes

        // split current registers -> planes
        {
            __half h[4], l[4];
            split1(xa.x, h[0], l[0]); split1(xa.y, h[1], l[1]);
            split1(xa.z, h[2], l[2]); split1(xa.w, h[3], l[3]);
            *(uint2*)(Xh + xr * 40 + xc) = *(uint2*)h;
            *(uint2*)(Xl + xr * 40 + xc) = *(uint2*)l;
            split1(xb.x, h[0], l[0]); split1(xb.y, h[1], l[1]);
            split1(xb.z, h[2], l[2]); split1(xb.w, h[3], l[3]);
            *(uint2*)(Xh + (xr + 32) * 40 + xc) = *(uint2*)h;
            *(uint2*)(Xl + (xr + 32) * 40 + xc) = *(uint2*)l;
        }
        #pragma unroll
        for (int k = 0; k < 6; k++) {
            int r = wr0 + 32 * k;
            __half h[4], l[4];
            split1(wvreg[k].x, h[0], l[0]); split1(wvreg[k].y, h[1], l[1]);
            split1(wvreg[k].z, h[2], l[2]); split1(wvreg[k].w, h[3], l[3]);
            *(uint2*)(Wh + r * 40 + xc) = *(uint2*)h;
            *(uint2*)(Wl + r * 40 + xc) = *(uint2*)l;
        }

        // prefetch next chunk into the (now dead) registers;
        // LDG latency overlaps the MMA phase below.
        if (it + 1 < 32) {
            const int e1 = (it + 1) * 32;
            xa = *(const float4*)(xsrc0 + e1);
            xb = *(const float4*)(xsrc1 + e1);
            #pragma unroll
            for (int k = 0; k < 6; k++)
                wvreg[k] = *(const float4*)(wsrc[k] + e1);
        }
        __syncthreads();   // planes visible to all warps

        // MMAs
        #pragma unroll
        for (int kc = 0; kc < 2; kc++) {
            unsigned ah[2][4], al[2][4];
            #pragma unroll
            for (int m = 0; m < 2; m++) {
                ldmx4(ah[m], aXh + m * 1280 + kc * 32);
                ldmx4(al[m], aXl + m * 1280 + kc * 32);
            }
            #pragma unroll
            for (int t = 0; t < 3; t++) {
                unsigned bh[4], bl[4];
                ldmx4(bh, aWh + t * 1280 + kc * 32);
                ldmx4(bl, aWl + t * 1280 + kc * 32);
                #pragma unroll
                for (int m = 0; m < 2; m++) {
                    mma16816(acc[m][2 * t],     ah[m], bh);
                    mma16816(acc[m][2 * t],     ah[m], bl);
                    mma16816(acc[m][2 * t],     al[m], bh);
                    mma16816(acc[m][2 * t + 1], ah[m], bh + 2);
                    mma16816(acc[m][2 * t + 1], ah[m], bl + 2);
                    mma16816(acc[m][2 * t + 1], al[m], bh + 2);
                }
            }
        }
    }

    #pragma unroll
    for (int m = 0; m < 2; m++) {
        const int row_lo = rows0 + 32 * rg + 16 * m + g;
        const int row_hi = row_lo + 8;
        #pragma unroll
        for (int j = 0; j < 6; j++) {
            int colg = cg * 48 + 8 * j + 2 * cq;
            __half *dh, *dl;
            float sc = 1.f;
            int cl;
            if (colg < 64)       { dh = g_Kh; dl = g_Kl; cl = colg; }
            else if (colg < 128) { dh = g_Qh; dl = g_Ql; cl = colg - 64; sc = 0.125f; }
            else                 { dh = g_Vh; dl = g_Vl; cl = colg - 128; }

            unsigned h2, l2;
            split2(acc[m][j][0] * sc, acc[m][j][1] * sc, h2, l2);
            *(unsigned*)(dh + (size_t)row_lo * ADIM + cl) = h2;
            *(unsigned*)(dl + (size_t)row_lo * ADIM + cl) = l2;
            split2(acc[m][j][2] * sc, acc[m][j][3] * sc, h2, l2);
            *(unsigned*)(dh + (size_t)row_hi * ADIM + cl) = h2;
            *(unsigned*)(dl + (size_t)row_hi * ADIM + cl) = l2;
        }
    }
}

// ---------------------------------------------------------------------------
// Causal flash attention, split-KV (NS=8). K hi/lo split; V single fp16
// plane (PV = Ph*Vh + Pl*Vh; the Ph*Vl term ~2^-11 is dropped).
// ---------------------------------------------------------------------------
#define ST 72
#define OFF_KH 0
#define OFF_KL 4608
#define OFF_VH 9216
#define SMEM_HALVES 13824

__global__ __launch_bounds__(128, 4)
void attn_kernel()
{
    extern __shared__ __align__(16) __half sh[];

    const int tid  = threadIdx.x;
    const int w    = tid >> 5;
    const int lane = tid & 31;
    const int g    = lane >> 2;
    const int cq   = lane & 3;
    const int li   = lane & 7;
    const int lm   = lane >> 3;
    const int bx   = blockIdx.x;
    const int s    = bx & (NS - 1);
    const int qi   = (SEQ / 64 - 1) - (bx >> 3);
    const int b    = blockIdx.y;
    const int q0   = qi * 64;

    if (qi < s) return;

    const unsigned shu = (unsigned)__cvta_generic_to_shared(sh);
    const unsigned lrowK = ((8 * (lm >> 1) + li) * ST + 8 * (lm & 1)) * 2;
    const unsigned aKh = shu + OFF_KH * 2 + lrowK;
    const unsigned aKl = shu + OFF_KL * 2 + lrowK;
    const unsigned lrowV = ((8 * (lm & 1) + li) * ST + 8 * (lm >> 1)) * 2;
    const unsigned aVh = shu + OFF_VH * 2 + lrowV;

    unsigned qh[4][4], ql[4][4];
    {
        size_t rl = (size_t)(b * SEQ + q0 + 16 * w + g) * ADIM;
        size_t rh = rl + 8 * ADIM;
        #pragma unroll
        for (int kc = 0; kc < 4; kc++) {
            int off = 16 * kc + 2 * cq;
            qh[kc][0] = *(const unsigned*)(g_Qh + rl + off);
            qh[kc][1] = *(const unsigned*)(g_Qh + rh + off);
            qh[kc][2] = *(const unsigned*)(g_Qh + rl + off + 8);
            qh[kc][3] = *(const unsigned*)(g_Qh + rh + off + 8);
            ql[kc][0] = *(const unsigned*)(g_Ql + rl + off);
            ql[kc][1] = *(const unsigned*)(g_Ql + rh + off);
            ql[kc][2] = *(const unsigned*)(g_Ql + rl + off + 8);
            ql[kc][3] = *(const unsigned*)(g_Ql + rh + off + 8);
        }
    }

    float o[8][4];
    #pragma unroll
    for (int j = 0; j < 8; j++)
        #pragma unroll
        for (int i = 0; i < 4; i++) o[j][i] = 0.f;
    float m_lo = -1e30f, m_hi = -1e30f, l_lo = 0.f, l_hi = 0.f;

    for (int kb = s; kb <= qi; kb += NS) {
        __syncthreads();
        {
            const __half* sKh = g_Kh + (size_t)(b * SEQ + kb * 64) * ADIM;
            const __half* sKl = g_Kl + (size_t)(b * SEQ + kb * 64) * ADIM;
            const __half* sVh = g_Vh + (size_t)(b * SEQ + kb * 64) * ADIM;
            #pragma unroll
            for (int k = 0; k < 4; k++) {
                int f = tid + 128 * k;
                int r = f >> 3, c = f & 7;
                *(uint4*)(sh + OFF_KH + r * ST + 8 * c) = *(const uint4*)(sKh + r * ADIM + 8 * c);
                *(uint4*)(sh + OFF_KL + r * ST + 8 * c) = *(const uint4*)(sKl + r * ADIM + 8 * c);
                *(uint4*)(sh + OFF_VH + r * ST + 8 * c) = *(const uint4*)(sVh + r * ADIM + 8 * c);
            }
        }
        __syncthreads();

        // ---- S = Q K^T
        float sreg[8][4];
        #pragma unroll
        for (int j = 0; j < 8; j++)
            #pragma unroll
            for (int i = 0; i < 4; i++) sreg[j][i] = 0.f;

        #pragma unroll
        for (int kc = 0; kc < 4; kc++) {
            #pragma unroll
            for (int t = 0; t < 4; t++) {
                unsigned bh[4], bl[4];
                ldmx4(bh, aKh + t * 2304 + kc * 32);
                ldmx4(bl, aKl + t * 2304 + kc * 32);
                mma16816(sreg[2 * t],     qh[kc], bh);
                mma16816(sreg[2 * t],     qh[kc], bl);
                mma16816(sreg[2 * t],     ql[kc], bh);
                mma16816(sreg[2 * t + 1], qh[kc], bh + 2);
                mma16816(sreg[2 * t + 1], qh[kc], bl + 2);
                mma16816(sreg[2 * t + 1], ql[kc], bh + 2);
            }
        }

        if (kb == qi) {
            int r_lo = 16 * w + g, r_hi = r_lo + 8;
            #pragma unroll
            for (int j = 0; j < 8; j++) {
                int c0 = 8 * j + 2 * cq;
                if (c0     > r_lo) sreg[j][0] = -1e30f;
                if (c0 + 1 > r_lo) sreg[j][1] = -1e30f;
                if (c0     > r_hi) sreg[j][2] = -1e30f;
                if (c0 + 1 > r_hi) sreg[j][3] = -1e30f;
            }
        }

        // ---- online softmax
        float mx0 = -1e30f, mx1 = -1e30f;
        #pragma unroll
        for (int j = 0; j < 8; j++) {
            mx0 = fmaxf(mx0, fmaxf(sreg[j][0], sreg[j][1]));
            mx1 = fmaxf(mx1, fmaxf(sreg[j][2], sreg[j][3]));
        }
        mx0 = fmaxf(mx0, __shfl_xor_sync(0xffffffffu, mx0, 1));
        mx0 = fmaxf(mx0, __shfl_xor_sync(0xffffffffu, mx0, 2));
        mx1 = fmaxf(mx1, __shfl_xor_sync(0xffffffffu, mx1, 1));
        mx1 = fmaxf(mx1, __shfl_xor_sync(0xffffffffu, mx1, 2));
        float mn0 = fmaxf(m_lo, mx0), mn1 = fmaxf(m_hi, mx1);
        float sc0 = __expf(m_lo - mn0), sc1 = __expf(m_hi - mn1);
        m_lo = mn0; m_hi = mn1;
        float su0 = 0.f, su1 = 0.f;
        #pragma unroll
        for (int j = 0; j < 8; j++) {
            sreg[j][0] = __expf(sreg[j][0] - mn0);
            sreg[j][1] = __expf(sreg[j][1] - mn0);
            sreg[j][2] = __expf(sreg[j][2] - mn1);
            sreg[j][3] = __expf(sreg[j][3] - mn1);
            su0 += sreg[j][0] + sreg[j][1];
            su1 += sreg[j][2] + sreg[j][3];
        }
        su0 += __shfl_xor_sync(0xffffffffu, su0, 1);
        su0 += __shfl_xor_sync(0xffffffffu, su0, 2);
        su1 += __shfl_xor_sync(0xffffffffu, su1, 1);
        su1 += __shfl_xor_sync(0xffffffffu, su1, 2);
        l_lo = l_lo * sc0 + su0;
        l_hi = l_hi * sc1 + su1;
        #pragma unroll
        for (int j = 0; j < 8; j++) {
            o[j][0] *= sc0; o[j][1] *= sc0;
            o[j][2] *= sc1; o[j][3] *= sc1;
        }

        // ---- O += P V (P split, V single plane)
        #pragma unroll
        for (int kc = 0; kc < 4; kc++) {
            unsigned ph[4], pl[4];
            split2(sreg[2 * kc][0],     sreg[2 * kc][1],     ph[0], pl[0]);
            split2(sreg[2 * kc][2],     sreg[2 * kc][3],     ph[1], pl[1]);
            split2(sreg[2 * kc + 1][0], sreg[2 * kc + 1][1], ph[2], pl[2]);
            split2(sreg[2 * kc + 1][2], sreg[2 * kc + 1][3], ph[3], pl[3]);
            #pragma unroll
            for (int t = 0; t < 4; t++) {
                unsigned bh[4];
                ldmx4t(bh, aVh + kc * 2304 + t * 32);
                mma16816(o[2 * t],     ph, bh);
                mma16816(o[2 * t],     pl, bh);
                mma16816(o[2 * t + 1], ph, bh + 2);
                mma16816(o[2 * t + 1], pl, bh + 2);
            }
        }
    }

    const int row_lo = q0 + 16 * w + g;
    const int row_hi = row_lo + 8;
    const size_t sb  = (size_t)(b * NS + s) * SEQ;
    #pragma unroll
    for (int j = 0; j < 8; j++) {
        int col = 8 * j + 2 * cq;
        *(float2*)(g_Om + (sb + row_lo) * ADIM + col) = make_float2(o[j][0], o[j][1]);
        *(float2*)(g_Om + (sb + row_hi) * ADIM + col) = make_float2(o[j][2], o[j][3]);
    }
    if (cq == 0) {
        g_m[sb + row_lo] = m_lo;  g_l[sb + row_lo] = l_lo;
        g_m[sb + row_hi] = m_hi;  g_l[sb + row_hi] = l_hi;
    }
}

// ---------------------------------------------------------------------------
// Combine split-KV partials.
// ---------------------------------------------------------------------------
__global__ __launch_bounds__(128)
void combine_kernel(float* __restrict__ out)
{
    const int tid = threadIdx.x;
    const int row = blockIdx.x * 8 + (tid >> 4);
    const int b   = blockIdx.y;
    const int c0  = (tid & 15) * 4;
    const int qi  = row >> 6;
    const int ns  = (qi + 1 < NS) ? (qi + 1) : NS;

    float m = -1e30f;
    #pragma unroll
    for (int s = 0; s < NS; s++)
        if (s < ns) m = fmaxf(m, g_m[(size_t)(b * NS + s) * SEQ + row]);

    float l = 0.f;
    float4 acc = make_float4(0.f, 0.f, 0.f, 0.f);
    #pragma unroll
    for (int s = 0; s < NS; s++) {
        if (s >= ns) break;
        size_t sb = (size_t)(b * NS + s) * SEQ + row;
        float wgt = __expf(g_m[sb] - m);
        l += g_l[sb] * wgt;
        float4 v = *(const float4*)(g_Om + sb * ADIM + c0);
        acc.x += v.x * wgt; acc.y += v.y * wgt;
        acc.z += v.z * wgt; acc.w += v.w * wgt;
    }
    float inv = 1.f / l;
    float4 r;
    r.x = rintf(acc.x * inv * 1e4f) * 1e-4f;
    r.y = rintf(acc.y * inv * 1e4f) * 1e-4f;
    r.z = rintf(acc.z * inv * 1e4f) * 1e-4f;
    r.w = rintf(acc.w * inv * 1e4f) * 1e-4f;
    *(float4*)(out + ((size_t)b * SEQ + row) * ADIM + c0) = r;
}

extern "C" void kernel_launch(void* const* d_in, const int* in_sizes, int n_in,
                              void* d_out, int out_size)
{
    const float* x  = (const float*)d_in[0];
    const float* wk = (const float*)d_in[1];
    const float* wq = (const float*)d_in[2];
    const float* wv = (const float*)d_in[3];
    float* out = (float*)d_out;

    cudaFuncSetAttribute(qkv_proj, cudaFuncAttributeMaxDynamicSharedMemorySize, QP_SMEM);
    qkv_proj<<<256, 256, QP_SMEM>>>(x, wk, wq, wv);

    int smem = SMEM_HALVES * (int)sizeof(__half);  // 27648 B
    cudaFuncSetAttribute(attn_kernel, cudaFuncAttributeMaxDynamicSharedMemorySize, smem);
    attn_kernel<<<dim3((SEQ / 64) * NS, NB), 128, smem>>>();

    combine_kernel<<<dim3(SEQ / 8, NB), 128>>>(out);
}

// round 13
// speedup vs baseline: 2.5995x; 1.0343x over previous
#include <cuda_runtime.h>
#include <cuda_fp16.h>
#include <math.h>

#define NB   4
#define SEQ  4096
#define EDIM 1024
#define ADIM 64
#define NS   8      // KV splits per q-tile

// Projected Q,K,V stored as split fp16 planes (hi + lo), [B*S, A] each.
// (V lo plane still produced by projection; attention uses only Vh.)
__device__ __half g_Qh[NB * SEQ * ADIM];
__device__ __half g_Ql[NB * SEQ * ADIM];
__device__ __half g_Kh[NB * SEQ * ADIM];
__device__ __half g_Kl[NB * SEQ * ADIM];
__device__ __half g_Vh[NB * SEQ * ADIM];
__device__ __half g_Vl[NB * SEQ * ADIM];

// Split-KV partial results: O (unnormalized), row max m, row sum l.
__device__ float g_Om[NB * NS * SEQ * ADIM];   // 33.6 MB
__device__ float g_m [NB * NS * SEQ];
__device__ float g_l [NB * NS * SEQ];

// m16n8k16 f16 MMA, f32 accumulate, in-place C.
__device__ __forceinline__ void mma16816(float d[4], const unsigned a[4], const unsigned* b)
{
    asm volatile(
        "mma.sync.aligned.m16n8k16.row.col.f32.f16.f16.f32 "
        "{%0,%1,%2,%3}, {%4,%5,%6,%7}, {%8,%9}, {%0,%1,%2,%3};\n"
        : "+f"(d[0]), "+f"(d[1]), "+f"(d[2]), "+f"(d[3])
        : "r"(a[0]), "r"(a[1]), "r"(a[2]), "r"(a[3]), "r"(b[0]), "r"(b[1]));
}

// ldmatrix x4: 4 8x8 b16 matrices -> 4 regs/thread.
__device__ __forceinline__ void ldmx4(unsigned r[4], unsigned saddr)
{
    asm volatile(
        "ldmatrix.sync.aligned.m8n8.x4.shared.b16 {%0,%1,%2,%3}, [%4];\n"
        : "=r"(r[0]), "=r"(r[1]), "=r"(r[2]), "=r"(r[3]) : "r"(saddr));
}

// ldmatrix x4 transposed (for V^T fragments from row-major V).
__device__ __forceinline__ void ldmx4t(unsigned r[4], unsigned saddr)
{
    asm volatile(
        "ldmatrix.sync.aligned.m8n8.x4.trans.shared.b16 {%0,%1,%2,%3}, [%4];\n"
        : "=r"(r[0]), "=r"(r[1]), "=r"(r[2]), "=r"(r[3]) : "r"(saddr));
}

__device__ __forceinline__ void split1(float v, __half& h, __half& l)
{
    h = __float2half_rn(v);
    l = __float2half_rn(v - __half2float(h));
}

__device__ __forceinline__ void split2(float a, float b, unsigned& hi, unsigned& lo)
{
    __half2 h = __floats2half2_rn(a, b);
    float2 hf = __half22float2(h);
    __half2 l = __floats2half2_rn(a - hf.x, b - hf.y);
    hi = *(unsigned*)&h;
    lo = *(unsigned*)&l;
}

// 16-byte async copy global -> shared (cp.async.cg).
__device__ __forceinline__ void cp16(void* smem_dst, const void* gsrc)
{
    unsigned sa = (unsigned)__cvta_generic_to_shared(smem_dst);
    asm volatile("cp.async.cg.shared.global [%0], [%1], 16;\n" :: "r"(sa), "l"(gsrc));
}

// ---------------------------------------------------------------------------
// QKV projection — R10 version (measured 66.7us). X via cp.async double-
// buffer (DRAM path); W via direct LDG (L2-resident) + inline split.
// Warp grid 2 rg x 4 cg (32 rows x 48 cols per warp).
// Smem (bytes): Xraw[2][2048]f32 @0, Xh[64][40] @16384, Xl @21504,
//               Wh[192][40] @26624, Wl @41984; total 57344.
// ---------------------------------------------------------------------------
#define QP_SMEM 57344

__global__ __launch_bounds__(256, 2)
void qkv_proj(const float* __restrict__ x,
              const float* __restrict__ wk,
              const float* __restrict__ wq,
              const float* __restrict__ wv)
{
    extern __shared__ __align__(16) char qsm[];
    float*  Xraw = (float*)qsm;                    // [2][2048]
    __half* Xh   = (__half*)(qsm + 16384);         // [64][40]
    __half* Xl   = (__half*)(qsm + 21504);
    __half* Wh   = (__half*)(qsm + 26624);         // [192][40]
    __half* Wl   = (__half*)(qsm + 41984);

    const int tid  = threadIdx.x;
    const int warp = tid >> 5;
    const int lane = tid & 31;
    const int g    = lane >> 2;
    const int cq   = lane & 3;
    const int li   = lane & 7;
    const int lm   = lane >> 3;
    const int rg   = warp >> 2;          // row group 0..1 (32 rows)
    const int cg   = warp & 3;           // col group 0..3 (48 cols)
    const int rows0 = blockIdx.x * 64;

    const int xr  = tid >> 3;            // 0..31
    const int xc  = (tid & 7) * 4;
    const int wr0 = tid >> 3;            // W rows wr0 + 32k

    const unsigned aXh = (unsigned)__cvta_generic_to_shared(Xh)
                       + ((32 * rg + 8 * (lm & 1) + li) * 40 + 8 * (lm >> 1)) * 2;
    const unsigned aXl = aXh + 5120;
    const unsigned aWh = (unsigned)__cvta_generic_to_shared(Wh)
                       + ((cg * 48 + 8 * (lm >> 1) + li) * 40 + 8 * (lm & 1)) * 2;
    const unsigned aWl = aWh + 15360;

    // Per-thread W row sources (constant across iterations)
    const float* wsrc[6];
    #pragma unroll
    for (int k = 0; k < 6; k++) {
        int r = wr0 + 32 * k;
        wsrc[k] = (r < 64)  ? wk + (size_t)r * EDIM
                : (r < 128) ? wq + (size_t)(r - 64) * EDIM
                            : wv + (size_t)(r - 128) * EDIM;
    }

    float acc[2][6][4];
    #pragma unroll
    for (int m = 0; m < 2; m++)
        #pragma unroll
        for (int j = 0; j < 6; j++)
            #pragma unroll
            for (int i = 0; i < 4; i++) acc[m][j][i] = 0.f;

    cp16(Xraw + xr * 32 + xc,        x + (size_t)(rows0 + xr) * EDIM + xc);
    cp16(Xraw + (xr + 32) * 32 + xc, x + (size_t)(rows0 + xr + 32) * EDIM + xc);
    asm volatile("cp.async.commit_group;\n" ::: "memory");

    for (int it = 0; it < 32; it++) {
        const int buf = it & 1;
        const int e0  = it * 32;
        float* Xb = Xraw + buf * 2048;

        // W prefetch into registers (L2-hot)
        float4 wvreg[6];
        #pragma unroll
        for (int k = 0; k < 6; k++)
            wvreg[k] = *(const float4*)(wsrc[k] + e0 + xc);

        if (it + 1 < 32) {
            const int nbuf = (it + 1) & 1;
            const int e1   = (it + 1) * 32;
            float* Xn = Xraw + nbuf * 2048;
            cp16(Xn + xr * 32 + xc,        x + (size_t)(rows0 + xr) * EDIM + e1 + xc);
            cp16(Xn + (xr + 32) * 32 + xc, x + (size_t)(rows0 + xr + 32) * EDIM + e1 + xc);
            asm volatile("cp.async.commit_group;\n" ::: "memory");
            asm volatile("cp.async.wait_group 1;\n" ::: "memory");
        } else {
            asm volatile("cp.async.wait_group 0;\n" ::: "memory");
        }
        __syncthreads();   // prev MMA done with planes; X chunk `it` resident

        // split W registers -> planes
        #pragma unroll
        for (int k = 0; k < 6; k++) {
            int r = wr0 + 32 * k;
            __half h[4], l[4];
            split1(wvreg[k].x, h[0], l[0]); split1(wvreg[k].y, h[1], l[1]);
            split1(wvreg[k].z, h[2], l[2]); split1(wvreg[k].w, h[3], l[3]);
            *(uint2*)(Wh + r * 40 + xc) = *(uint2*)h;
            *(uint2*)(Wl + r * 40 + xc) = *(uint2*)l;
        }
        // split X raw -> planes
        #pragma unroll
        for (int k = 0; k < 2; k++) {
            int r = xr + 32 * k;
            float4 v = *(const float4*)(Xb + r * 32 + xc);
            __half h[4], l[4];
            split1(v.x, h[0], l[0]); split1(v.y, h[1], l[1]);
            split1(v.z, h[2], l[2]); split1(v.w, h[3], l[3]);
            *(uint2*)(Xh + r * 40 + xc) = *(uint2*)h;
            *(uint2*)(Xl + r * 40 + xc) = *(uint2*)l;
        }
        __syncthreads();

        // MMAs
        #pragma unroll
        for (int kc = 0; kc < 2; kc++) {
            unsigned ah[2][4], al[2][4];
            #pragma unroll
            for (int m = 0; m < 2; m++) {
                ldmx4(ah[m], aXh + m * 1280 + kc * 32);
                ldmx4(al[m], aXl + m * 1280 + kc * 32);
            }
            #pragma unroll
            for (int t = 0; t < 3; t++) {
                unsigned bh[4], bl[4];
                ldmx4(bh, aWh + t * 1280 + kc * 32);
                ldmx4(bl, aWl + t * 1280 + kc * 32);
                #pragma unroll
                for (int m = 0; m < 2; m++) {
                    mma16816(acc[m][2 * t],     ah[m], bh);
                    mma16816(acc[m][2 * t],     ah[m], bl);
                    mma16816(acc[m][2 * t],     al[m], bh);
                    mma16816(acc[m][2 * t + 1], ah[m], bh + 2);
                    mma16816(acc[m][2 * t + 1], ah[m], bl + 2);
                    mma16816(acc[m][2 * t + 1], al[m], bh + 2);
                }
            }
        }
    }

    #pragma unroll
    for (int m = 0; m < 2; m++) {
        const int row_lo = rows0 + 32 * rg + 16 * m + g;
        const int row_hi = row_lo + 8;
        #pragma unroll
        for (int j = 0; j < 6; j++) {
            int colg = cg * 48 + 8 * j + 2 * cq;
            __half *dh, *dl;
            float sc = 1.f;
            int cl;
            if (colg < 64)       { dh = g_Kh; dl = g_Kl; cl = colg; }
            else if (colg < 128) { dh = g_Qh; dl = g_Ql; cl = colg - 64; sc = 0.125f; }
            else                 { dh = g_Vh; dl = g_Vl; cl = colg - 128; }

            unsigned h2, l2;
            split2(acc[m][j][0] * sc, acc[m][j][1] * sc, h2, l2);
            *(unsigned*)(dh + (size_t)row_lo * ADIM + cl) = h2;
            *(unsigned*)(dl + (size_t)row_lo * ADIM + cl) = l2;
            split2(acc[m][j][2] * sc, acc[m][j][3] * sc, h2, l2);
            *(unsigned*)(dh + (size_t)row_hi * ADIM + cl) = h2;
            *(unsigned*)(dl + (size_t)row_hi * ADIM + cl) = l2;
        }
    }
}

// ---------------------------------------------------------------------------
// Causal flash attention, split-KV (NS=8). K hi/lo split; V single fp16
// plane (PV = Ph*Vh + Pl*Vh). Unchanged from R11 (the winner).
// ---------------------------------------------------------------------------
#define ST 72
#define OFF_KH 0
#define OFF_KL 4608
#define OFF_VH 9216
#define SMEM_HALVES 13824

__global__ __launch_bounds__(128, 4)
void attn_kernel()
{
    extern __shared__ __align__(16) __half sh[];

    const int tid  = threadIdx.x;
    const int w    = tid >> 5;
    const int lane = tid & 31;
    const int g    = lane >> 2;
    const int cq   = lane & 3;
    const int li   = lane & 7;
    const int lm   = lane >> 3;
    const int bx   = blockIdx.x;
    const int s    = bx & (NS - 1);
    const int qi   = (SEQ / 64 - 1) - (bx >> 3);
    const int b    = blockIdx.y;
    const int q0   = qi * 64;

    if (qi < s) return;

    const unsigned shu = (unsigned)__cvta_generic_to_shared(sh);
    const unsigned lrowK = ((8 * (lm >> 1) + li) * ST + 8 * (lm & 1)) * 2;
    const unsigned aKh = shu + OFF_KH * 2 + lrowK;
    const unsigned aKl = shu + OFF_KL * 2 + lrowK;
    const unsigned lrowV = ((8 * (lm & 1) + li) * ST + 8 * (lm >> 1)) * 2;
    const unsigned aVh = shu + OFF_VH * 2 + lrowV;

    unsigned qh[4][4], ql[4][4];
    {
        size_t rl = (size_t)(b * SEQ + q0 + 16 * w + g) * ADIM;
        size_t rh = rl + 8 * ADIM;
        #pragma unroll
        for (int kc = 0; kc < 4; kc++) {
            int off = 16 * kc + 2 * cq;
            qh[kc][0] = *(const unsigned*)(g_Qh + rl + off);
            qh[kc][1] = *(const unsigned*)(g_Qh + rh + off);
            qh[kc][2] = *(const unsigned*)(g_Qh + rl + off + 8);
            qh[kc][3] = *(const unsigned*)(g_Qh + rh + off + 8);
            ql[kc][0] = *(const unsigned*)(g_Ql + rl + off);
            ql[kc][1] = *(const unsigned*)(g_Ql + rh + off);
            ql[kc][2] = *(const unsigned*)(g_Ql + rl + off + 8);
            ql[kc][3] = *(const unsigned*)(g_Ql + rh + off + 8);
        }
    }

    float o[8][4];
    #pragma unroll
    for (int j = 0; j < 8; j++)
        #pragma unroll
        for (int i = 0; i < 4; i++) o[j][i] = 0.f;
    float m_lo = -1e30f, m_hi = -1e30f, l_lo = 0.f, l_hi = 0.f;

    for (int kb = s; kb <= qi; kb += NS) {
        __syncthreads();
        {
            const __half* sKh = g_Kh + (size_t)(b * SEQ + kb * 64) * ADIM;
            const __half* sKl = g_Kl + (size_t)(b * SEQ + kb * 64) * ADIM;
            const __half* sVh = g_Vh + (size_t)(b * SEQ + kb * 64) * ADIM;
            #pragma unroll
            for (int k = 0; k < 4; k++) {
                int f = tid + 128 * k;
                int r = f >> 3, c = f & 7;
                *(uint4*)(sh + OFF_KH + r * ST + 8 * c) = *(const uint4*)(sKh + r * ADIM + 8 * c);
                *(uint4*)(sh + OFF_KL + r * ST + 8 * c) = *(const uint4*)(sKl + r * ADIM + 8 * c);
                *(uint4*)(sh + OFF_VH + r * ST + 8 * c) = *(const uint4*)(sVh + r * ADIM + 8 * c);
            }
        }
        __syncthreads();

        // ---- S = Q K^T
        float sreg[8][4];
        #pragma unroll
        for (int j = 0; j < 8; j++)
            #pragma unroll
            for (int i = 0; i < 4; i++) sreg[j][i] = 0.f;

        #pragma unroll
        for (int kc = 0; kc < 4; kc++) {
            #pragma unroll
            for (int t = 0; t < 4; t++) {
                unsigned bh[4], bl[4];
                ldmx4(bh, aKh + t * 2304 + kc * 32);
                ldmx4(bl, aKl + t * 2304 + kc * 32);
                mma16816(sreg[2 * t],     qh[kc], bh);
                mma16816(sreg[2 * t],     qh[kc], bl);
                mma16816(sreg[2 * t],     ql[kc], bh);
                mma16816(sreg[2 * t + 1], qh[kc], bh + 2);
                mma16816(sreg[2 * t + 1], qh[kc], bl + 2);
                mma16816(sreg[2 * t + 1], ql[kc], bh + 2);
            }
        }

        if (kb == qi) {
            int r_lo = 16 * w + g, r_hi = r_lo + 8;
            #pragma unroll
            for (int j = 0; j < 8; j++) {
                int c0 = 8 * j + 2 * cq;
                if (c0     > r_lo) sreg[j][0] = -1e30f;
                if (c0 + 1 > r_lo) sreg[j][1] = -1e30f;
                if (c0     > r_hi) sreg[j][2] = -1e30f;
                if (c0 + 1 > r_hi) sreg[j][3] = -1e30f;
            }
        }

        // ---- online softmax
        float mx0 = -1e30f, mx1 = -1e30f;
        #pragma unroll
        for (int j = 0; j < 8; j++) {
            mx0 = fmaxf(mx0, fmaxf(sreg[j][0], sreg[j][1]));
            mx1 = fmaxf(mx1, fmaxf(sreg[j][2], sreg[j][3]));
        }
        mx0 = fmaxf(mx0, __shfl_xor_sync(0xffffffffu, mx0, 1));
        mx0 = fmaxf(mx0, __shfl_xor_sync(0xffffffffu, mx0, 2));
        mx1 = fmaxf(mx1, __shfl_xor_sync(0xffffffffu, mx1, 1));
        mx1 = fmaxf(mx1, __shfl_xor_sync(0xffffffffu, mx1, 2));
        float mn0 = fmaxf(m_lo, mx0), mn1 = fmaxf(m_hi, mx1);
        float sc0 = __expf(m_lo - mn0), sc1 = __expf(m_hi - mn1);
        m_lo = mn0; m_hi = mn1;
        float su0 = 0.f, su1 = 0.f;
        #pragma unroll
        for (int j = 0; j < 8; j++) {
            sreg[j][0] = __expf(sreg[j][0] - mn0);
            sreg[j][1] = __expf(sreg[j][1] - mn0);
            sreg[j][2] = __expf(sreg[j][2] - mn1);
            sreg[j][3] = __expf(sreg[j][3] - mn1);
            su0 += sreg[j][0] + sreg[j][1];
            su1 += sreg[j][2] + sreg[j][3];
        }
        su0 += __shfl_xor_sync(0xffffffffu, su0, 1);
        su0 += __shfl_xor_sync(0xffffffffu, su0, 2);
        su1 += __shfl_xor_sync(0xffffffffu, su1, 1);
        su1 += __shfl_xor_sync(0xffffffffu, su1, 2);
        l_lo = l_lo * sc0 + su0;
        l_hi = l_hi * sc1 + su1;
        #pragma unroll
        for (int j = 0; j < 8; j++) {
            o[j][0] *= sc0; o[j][1] *= sc0;
            o[j][2] *= sc1; o[j][3] *= sc1;
        }

        // ---- O += P V (P split, V single plane)
        #pragma unroll
        for (int kc = 0; kc < 4; kc++) {
            unsigned ph[4], pl[4];
            split2(sreg[2 * kc][0],     sreg[2 * kc][1],     ph[0], pl[0]);
            split2(sreg[2 * kc][2],     sreg[2 * kc][3],     ph[1], pl[1]);
            split2(sreg[2 * kc + 1][0], sreg[2 * kc + 1][1], ph[2], pl[2]);
            split2(sreg[2 * kc + 1][2], sreg[2 * kc + 1][3], ph[3], pl[3]);
            #pragma unroll
            for (int t = 0; t < 4; t++) {
                unsigned bh[4];
                ldmx4t(bh, aVh + kc * 2304 + t * 32);
                mma16816(o[2 * t],     ph, bh);
                mma16816(o[2 * t],     pl, bh);
                mma16816(o[2 * t + 1], ph, bh + 2);
                mma16816(o[2 * t + 1], pl, bh + 2);
            }
        }
    }

    const int row_lo = q0 + 16 * w + g;
    const int row_hi = row_lo + 8;
    const size_t sb  = (size_t)(b * NS + s) * SEQ;
    #pragma unroll
    for (int j = 0; j < 8; j++) {
        int col = 8 * j + 2 * cq;
        *(float2*)(g_Om + (sb + row_lo) * ADIM + col) = make_float2(o[j][0], o[j][1]);
        *(float2*)(g_Om + (sb + row_hi) * ADIM + col) = make_float2(o[j][2], o[j][3]);
    }
    if (cq == 0) {
        g_m[sb + row_lo] = m_lo;  g_l[sb + row_lo] = l_lo;
        g_m[sb + row_hi] = m_hi;  g_l[sb + row_hi] = l_hi;
    }
}

// ---------------------------------------------------------------------------
// Combine split-KV partials.
// ---------------------------------------------------------------------------
__global__ __launch_bounds__(128)
void combine_kernel(float* __restrict__ out)
{
    const int tid = threadIdx.x;
    const int row = blockIdx.x * 8 + (tid >> 4);
    const int b   = blockIdx.y;
    const int c0  = (tid & 15) * 4;
    const int qi  = row >> 6;
    const int ns  = (qi + 1 < NS) ? (qi + 1) : NS;

    float m = -1e30f;
    #pragma unroll
    for (int s = 0; s < NS; s++)
        if (s < ns) m = fmaxf(m, g_m[(size_t)(b * NS + s) * SEQ + row]);

    float l = 0.f;
    float4 acc = make_float4(0.f, 0.f, 0.f, 0.f);
    #pragma unroll
    for (int s = 0; s < NS; s++) {
        if (s >= ns) break;
        size_t sb = (size_t)(b * NS + s) * SEQ + row;
        float wgt = __expf(g_m[sb] - m);
        l += g_l[sb] * wgt;
        float4 v = *(const float4*)(g_Om + sb * ADIM + c0);
        acc.x += v.x * wgt; acc.y += v.y * wgt;
        acc.z += v.z * wgt; acc.w += v.w * wgt;
    }
    float inv = 1.f / l;
    float4 r;
    r.x = rintf(acc.x * inv * 1e4f) * 1e-4f;
    r.y = rintf(acc.y * inv * 1e4f) * 1e-4f;
    r.z = rintf(acc.z * inv * 1e4f) * 1e-4f;
    r.w = rintf(acc.w * inv * 1e4f) * 1e-4f;
    *(float4*)(out + ((size_t)b * SEQ + row) * ADIM + c0) = r;
}

extern "C" void kernel_launch(void* const* d_in, const int* in_sizes, int n_in,
                              void* d_out, int out_size)
{
    const float* x  = (const float*)d_in[0];
    const float* wk = (const float*)d_in[1];
    const float* wq = (const float*)d_in[2];
    const float* wv = (const float*)d_in[3];
    float* out = (float*)d_out;

    cudaFuncSetAttribute(qkv_proj, cudaFuncAttributeMaxDynamicSharedMemorySize, QP_SMEM);
    qkv_proj<<<256, 256, QP_SMEM>>>(x, wk, wq, wv);

    int smem = SMEM_HALVES * (int)sizeof(__half);  // 27648 B
    cudaFuncSetAttribute(attn_kernel, cudaFuncAttributeMaxDynamicSharedMemorySize, smem);
    attn_kernel<<<dim3((SEQ / 64) * NS, NB), 128, smem>>>();

    combine_kernel<<<dim3(SEQ / 8, NB), 128>>>(out);
}